// round 5
// baseline (speedup 1.0000x reference)
#include <cuda_runtime.h>
#include <math.h>

#define T_ 2048
#define H_ 2048
#define NH_ 16
#define NKV_ 4
#define HD_ 128
#define I_ 1024
#define E_ 16
#define TOPK_ 2
#define P_ (T_*TOPK_)
#define QKVW_ 3072

// ---------------- scratch (device globals; no allocations allowed) ----------------
__device__ float g_xn[T_*H_];
__device__ float g_qkv[T_*QKVW_];
__device__ float g_attn[T_*H_];
__device__ float g_aproj[T_*H_];
__device__ float g_resat[T_*H_];
__device__ float g_h2n[T_*H_];
__device__ float g_gu[T_*2*H_];
__device__ float g_hmid[T_*H_];
__device__ float g_mlp[T_*H_];
__device__ float g_h3n[T_*H_];
__device__ float g_gum[P_*2*I_];
__device__ float g_hmm[P_*I_];
__device__ float g_ym[P_*H_];
__device__ int   g_topi[P_];
__device__ float g_topw[P_];
__device__ int   g_cnt[E_];
__device__ int   g_off[E_];
__device__ int   g_cur[E_];
__device__ int   g_ptok[P_];
__device__ int   g_pslot[P_];

__device__ __forceinline__ float neg_inff() { return __int_as_float(0xff800000); }

// ---------------- RMSNorm: one block per token ----------------
__global__ void __launch_bounds__(256) rmsnorm_kernel(const float* __restrict__ x,
                                                      const float* __restrict__ w,
                                                      float* __restrict__ out) {
  const int t = blockIdx.x;
  const float4* xr = (const float4*)(x + (size_t)t*H_);
  const float4* wr = (const float4*)w;
  float4* orow = (float4*)(out + (size_t)t*H_);
  const int i0 = threadIdx.x, i1 = threadIdx.x + 256;
  float4 v0 = xr[i0], v1 = xr[i1];
  float s = v0.x*v0.x+v0.y*v0.y+v0.z*v0.z+v0.w*v0.w
          + v1.x*v1.x+v1.y*v1.y+v1.z*v1.z+v1.w*v1.w;
  #pragma unroll
  for (int off=16; off; off>>=1) s += __shfl_xor_sync(0xffffffffu, s, off);
  __shared__ float red[8];
  __shared__ float sinv;
  if ((threadIdx.x & 31)==0) red[threadIdx.x>>5] = s;
  __syncthreads();
  if (threadIdx.x==0) {
    float tt = 0.f;
    #pragma unroll
    for (int k=0;k<8;k++) tt += red[k];
    sinv = rsqrtf(tt * (1.f/H_) + 1e-5f);
  }
  __syncthreads();
  float r = sinv;
  float4 w0 = wr[i0], w1 = wr[i1];
  float4 o0, o1;
  o0.x=v0.x*r*w0.x; o0.y=v0.y*r*w0.y; o0.z=v0.z*r*w0.z; o0.w=v0.w*r*w0.w;
  o1.x=v1.x*r*w1.x; o1.y=v1.y*r*w1.y; o1.z=v1.z*r*w1.z; o1.w=v1.w*r*w1.w;
  orow[i0]=o0; orow[i1]=o1;
}

// ---------------- GEMM microkernel fragment ----------------
__device__ __forceinline__ void mm_frag(const float (&As)[8][128], const float (&Bs)[8][128],
                                        float (&acc)[8][8], int ty, int tx) {
  #pragma unroll
  for (int kk=0; kk<8; kk++) {
    float4 a0 = *(const float4*)&As[kk][ty*8];
    float4 a1 = *(const float4*)&As[kk][ty*8+4];
    float4 b0 = *(const float4*)&Bs[kk][tx*8];
    float4 b1 = *(const float4*)&Bs[kk][tx*8+4];
    float av[8]={a0.x,a0.y,a0.z,a0.w,a1.x,a1.y,a1.z,a1.w};
    float bv[8]={b0.x,b0.y,b0.z,b0.w,b1.x,b1.y,b1.z,b1.w};
    #pragma unroll
    for (int i=0;i<8;i++)
      #pragma unroll
      for (int j=0;j<8;j++)
        acc[i][j] += av[i]*bv[j];
  }
}

// C[M,N] = A[M,K] @ B[K,N], B row-major (K,N). M = gridDim.y*128, tiles exact.
__global__ void __launch_bounds__(256) gemm_nn(const float* __restrict__ A,
                                               const float* __restrict__ B,
                                               float* __restrict__ C, int N, int K) {
  __shared__ float As[8][128];
  __shared__ float Bs[8][128];
  const int m0 = blockIdx.y<<7, n0 = blockIdx.x<<7;
  const int tid = threadIdx.x, ty = tid>>4, tx = tid&15;
  const int am = tid>>1, ak = (tid&1)<<2;
  const int bk = tid>>5, bn = (tid&31)<<2;
  const float* Ap = A + (size_t)(m0+am)*K + ak;
  const float* Bp = B + (size_t)bk*N + n0 + bn;
  float acc[8][8] = {};
  float4 a = *(const float4*)Ap;
  float4 b = *(const float4*)Bp;
  for (int k0 = 0;;) {
    As[ak+0][am]=a.x; As[ak+1][am]=a.y; As[ak+2][am]=a.z; As[ak+3][am]=a.w;
    *(float4*)&Bs[bk][bn] = b;
    __syncthreads();
    int k1 = k0 + 8;
    float4 a2, b2;
    if (k1 < K) {
      a2 = *(const float4*)(Ap + k1);
      b2 = *(const float4*)(Bp + (size_t)k1*N);
    }
    mm_frag(As, Bs, acc, ty, tx);
    __syncthreads();
    if (k1 >= K) break;
    a = a2; b = b2; k0 = k1;
  }
  #pragma unroll
  for (int i=0;i<8;i++) {
    float* cp = C + (size_t)(m0+ty*8+i)*N + n0 + tx*8;
    float4 c0 = {acc[i][0],acc[i][1],acc[i][2],acc[i][3]};
    float4 c1 = {acc[i][4],acc[i][5],acc[i][6],acc[i][7]};
    *(float4*)cp = c0; *(float4*)(cp+4) = c1;
  }
}

// Grouped, gathered GEMM with B transposed: C[slot, n] = sum_k A[row(slot),k] * B_e[n,k]
// B_e = Bbase + e*N*K, shape (N,K) row-major. Expert tiles with early exit.
__global__ void __launch_bounds__(256) gemm_bt_group(const float* __restrict__ Abase,
                                                     const float* __restrict__ Bbase,
                                                     float* __restrict__ C,
                                                     int N, int K, int lda, int useTok) {
  const int e = blockIdx.z;
  const int count = g_cnt[e];
  const int mt = blockIdx.y;
  if ((mt<<7) >= count) return;
  const int base = g_off[e];
  const int n0 = blockIdx.x<<7;
  const float* B = Bbase + (size_t)e * N * K;
  __shared__ float As[8][128];
  __shared__ float Bs[8][128];
  const int tid = threadIdx.x, ty = tid>>4, tx = tid&15;
  const int am = tid>>1, ak = (tid&1)<<2;
  const int mloc = (mt<<7) + am;
  const bool av = mloc < count;
  int arow = 0;
  if (av) { int slot = base + mloc; arow = useTok ? g_ptok[slot] : slot; }
  const float* Ap = Abase + (size_t)arow*lda + ak;
  const int bn = tid>>1, bkq = (tid&1)<<2;
  const float* Bp = B + (size_t)(n0+bn)*K + bkq;
  float acc[8][8] = {};
  float4 a = av ? *(const float4*)Ap : make_float4(0.f,0.f,0.f,0.f);
  float4 b = *(const float4*)Bp;
  for (int k0=0;;) {
    As[ak+0][am]=a.x; As[ak+1][am]=a.y; As[ak+2][am]=a.z; As[ak+3][am]=a.w;
    Bs[bkq+0][bn]=b.x; Bs[bkq+1][bn]=b.y; Bs[bkq+2][bn]=b.z; Bs[bkq+3][bn]=b.w;
    __syncthreads();
    int k1 = k0 + 8;
    float4 a2, b2;
    if (k1 < K) {
      a2 = av ? *(const float4*)(Ap + k1) : make_float4(0.f,0.f,0.f,0.f);
      b2 = *(const float4*)(Bp + k1);
    }
    mm_frag(As, Bs, acc, ty, tx);
    __syncthreads();
    if (k1 >= K) break;
    a = a2; b = b2; k0 = k1;
  }
  #pragma unroll
  for (int i=0;i<8;i++) {
    int r = (mt<<7) + ty*8 + i;
    if (r < count) {
      float* cp = C + (size_t)(base+r)*N + n0 + tx*8;
      float4 c0 = {acc[i][0],acc[i][1],acc[i][2],acc[i][3]};
      float4 c1 = {acc[i][4],acc[i][5],acc[i][6],acc[i][7]};
      *(float4*)cp = c0; *(float4*)(cp+4) = c1;
    }
  }
}

// ---------------- RoPE (neox) on q and k heads, in place ----------------
// positions are arange(T) by construction (the causal mask in the reference
// also reduces to index comparison) -> use t directly; no dependence on the
// int64 input's binary layout.
__global__ void rope_kernel(float* __restrict__ qkv) {
  const int t = blockIdx.x, hh = blockIdx.y, i = threadIdx.x;   // 64 threads
  float* bptr = qkv + (size_t)t*QKVW_ + (hh < NH_ ? hh*HD_ : NH_*HD_ + (hh-NH_)*HD_);
  float p = (float)t;
  float fr = powf(10000.f, -(float)(2*i) * (1.f/HD_));
  float ang = p * fr;
  float sn, cs; sincosf(ang, &sn, &cs);
  float x1 = bptr[i], x2 = bptr[i+64];
  bptr[i]    = x1*cs - x2*sn;
  bptr[i+64] = x2*cs + x1*sn;
}

// ---------------- Flash attention: block = (head, q-tile of 64) ----------------
#define ATTN_SMEM (20928*4)
__global__ void __launch_bounds__(256) attn_kernel(const float* __restrict__ qkv,
                                                   float* __restrict__ out) {
  extern __shared__ float sm[];
  float* Qs  = sm;              // [128][64] d-major
  float* KVs = sm + 8192;       // Ks [128][64] then Vs [64][128]
  float* Ss  = sm + 16384;      // [64][68]
  float* rm  = sm + 16384 + 64*68;
  float* rl  = rm + 64;
  float* ra  = rl + 64;

  const int h  = blockIdx.x;
  const int q0 = blockIdx.y * 64;
  const int kvh = h >> 2;               // NH/NKV = 4
  const int tid = threadIdx.x;
  const int ty = tid >> 4, tx = tid & 15;

  for (int i = tid; i < 2048; i += 256) {      // 64 rows x 32 float4
    int r = i >> 5, dq = (i & 31) << 2;
    float4 v = *(const float4*)(qkv + (size_t)(q0+r)*QKVW_ + h*HD_ + dq);
    Qs[(dq+0)*64 + r] = v.x; Qs[(dq+1)*64 + r] = v.y;
    Qs[(dq+2)*64 + r] = v.z; Qs[(dq+3)*64 + r] = v.w;
  }
  if (tid < 64) { rm[tid] = neg_inff(); rl[tid] = 0.f; }
  float o[4][8];
  #pragma unroll
  for (int i=0;i<4;i++)
    #pragma unroll
    for (int j=0;j<8;j++) o[i][j]=0.f;
  __syncthreads();

  const float scale = 0.08838834764831845f;   // 1/sqrt(128)
  const int ntiles = blockIdx.y + 1;
  for (int kt = 0; kt < ntiles; kt++) {
    const int k0 = kt * 64;
    for (int i = tid; i < 2048; i += 256) {
      int s = i >> 5, dq = (i & 31) << 2;
      float4 v = *(const float4*)(qkv + (size_t)(k0+s)*QKVW_ + NH_*HD_ + kvh*HD_ + dq);
      KVs[(dq+0)*64+s]=v.x; KVs[(dq+1)*64+s]=v.y;
      KVs[(dq+2)*64+s]=v.z; KVs[(dq+3)*64+s]=v.w;
    }
    __syncthreads();
    float acc[4][4] = {};
    #pragma unroll 4
    for (int d = 0; d < 128; d++) {
      float4 qa = *(const float4*)&Qs[d*64 + ty*4];
      float4 kb = *(const float4*)&KVs[d*64 + tx*4];
      float av[4]={qa.x,qa.y,qa.z,qa.w}, bv[4]={kb.x,kb.y,kb.z,kb.w};
      #pragma unroll
      for (int i=0;i<4;i++)
        #pragma unroll
        for (int j=0;j<4;j++) acc[i][j] += av[i]*bv[j];
    }
    __syncthreads();
    #pragma unroll
    for (int i=0;i<4;i++) {
      int qq = q0 + ty*4 + i;
      #pragma unroll
      for (int j=0;j<4;j++) {
        int kk = k0 + tx*4 + j;
        Ss[(ty*4+i)*68 + tx*4+j] = (kk <= qq) ? acc[i][j]*scale : neg_inff();
      }
    }
    __syncthreads();
    if (tid < 64) {
      float mold = rm[tid];
      float mmax = mold;
      float* srw = Ss + tid*68;
      for (int c=0;c<64;c++) mmax = fmaxf(mmax, srw[c]);
      float sum = 0.f;
      for (int c=0;c<64;c++){ float p = __expf(srw[c]-mmax); srw[c]=p; sum+=p; }
      float al = (mold == neg_inff()) ? 0.f : __expf(mold - mmax);
      rl[tid] = rl[tid]*al + sum;
      rm[tid] = mmax;
      ra[tid] = al;
    }
    __syncthreads();
    for (int i = tid; i < 2048; i += 256) {   // V tile, s-major [64][128]
      int s = i >> 5, dq = (i & 31) << 2;
      float4 v = *(const float4*)(qkv + (size_t)(k0+s)*QKVW_ + (NH_+NKV_)*HD_ + kvh*HD_ + dq);
      *(float4*)&KVs[s*128 + dq] = v;
    }
    __syncthreads();
    float alr[4];
    #pragma unroll
    for (int i=0;i<4;i++) alr[i] = ra[ty*4+i];
    #pragma unroll
    for (int i=0;i<4;i++)
      #pragma unroll
      for (int j=0;j<8;j++) o[i][j] *= alr[i];
    for (int s=0;s<64;s++) {
      float4 v0 = *(const float4*)&KVs[s*128 + tx*8];
      float4 v1 = *(const float4*)&KVs[s*128 + tx*8 + 4];
      float pv[4];
      #pragma unroll
      for (int i=0;i<4;i++) pv[i] = Ss[(ty*4+i)*68 + s];
      #pragma unroll
      for (int i=0;i<4;i++) {
        o[i][0]+=pv[i]*v0.x; o[i][1]+=pv[i]*v0.y; o[i][2]+=pv[i]*v0.z; o[i][3]+=pv[i]*v0.w;
        o[i][4]+=pv[i]*v1.x; o[i][5]+=pv[i]*v1.y; o[i][6]+=pv[i]*v1.z; o[i][7]+=pv[i]*v1.w;
      }
    }
    __syncthreads();
  }
  #pragma unroll
  for (int i=0;i<4;i++) {
    float inv = 1.f / rl[ty*4+i];
    int r = q0 + ty*4 + i;
    #pragma unroll
    for (int j=0;j<8;j++)
      out[(size_t)r*H_ + h*HD_ + tx*8 + j] = o[i][j]*inv;
  }
}

// ---------------- elementwise ----------------
__global__ void add_kernel(const float* __restrict__ a, const float* __restrict__ b,
                           float* __restrict__ c) {
  int i = blockIdx.x*256 + threadIdx.x;   // float4 index, exact cover
  float4 va = ((const float4*)a)[i], vb = ((const float4*)b)[i];
  ((float4*)c)[i] = make_float4(va.x+vb.x, va.y+vb.y, va.z+vb.z, va.w+vb.w);
}

__device__ __forceinline__ float siluf(float g){ return g / (1.f + expf(-g)); }

__global__ void silu_resmlp_kernel() {
  int idx = blockIdx.x*256 + threadIdx.x;       // over T_*H_/4
  int t = idx >> 9;                             // H_/4 = 512
  int jq = idx & 511;
  const float4* gp = (const float4*)(g_gu + (size_t)t*2*H_);
  float4 g4 = gp[jq], u4 = gp[jq + 512];
  float4 o = make_float4(siluf(g4.x)*u4.x, siluf(g4.y)*u4.y, siluf(g4.z)*u4.z, siluf(g4.w)*u4.w);
  ((float4*)(g_hmid + (size_t)t*H_))[jq] = o;
}

__global__ void silu_moe_kernel() {
  int idx = blockIdx.x*256 + threadIdx.x;       // over P_*I_/4
  int p = idx >> 8;                             // I_/4 = 256
  int jq = idx & 255;
  const float4* gp = (const float4*)(g_gum + (size_t)p*2*I_);
  float4 g4 = gp[jq], u4 = gp[jq + 256];
  float4 o = make_float4(siluf(g4.x)*u4.x, siluf(g4.y)*u4.y, siluf(g4.z)*u4.z, siluf(g4.w)*u4.w);
  ((float4*)(g_hmm + (size_t)p*I_))[jq] = o;
}

// ---------------- gating + routing ----------------
__global__ void __launch_bounds__(256) gate_kernel(const float* __restrict__ gw) {
  const int t = blockIdx.x;
  __shared__ float part[256];
  const int tid = threadIdx.x;
  const int e = tid & 15, c = tid >> 4;
  const float* xr = g_h3n + (size_t)t*H_;
  float s = 0.f;
  for (int h = c*128; h < c*128+128; h++)
    s += xr[h] * gw[h*E_ + e];
  part[tid] = s;
  __syncthreads();
  if (tid == 0) {
    float lg[16];
    for (int ee=0; ee<16; ee++){ float v=0.f; for (int cc=0; cc<16; cc++) v += part[cc*16+ee]; lg[ee]=v; }
    int i1 = 0;
    for (int ee=1; ee<16; ee++) if (lg[ee] > lg[i1]) i1 = ee;
    int i2 = (i1==0) ? 1 : 0;
    for (int ee=0; ee<16; ee++) if (ee!=i1 && lg[ee] > lg[i2]) i2 = ee;
    float mx = lg[i1];
    float p1 = expf(lg[i1]-mx), p2 = expf(lg[i2]-mx);
    float d = p1 + p2;
    g_topi[t*2]=i1; g_topi[t*2+1]=i2;
    g_topw[t*2]=p1/d; g_topw[t*2+1]=p2/d;
  }
}

__global__ void moe_zero_kernel(){ if (threadIdx.x < E_){ g_cnt[threadIdx.x]=0; g_cur[threadIdx.x]=0; } }
__global__ void moe_count_kernel(){ int i = blockIdx.x*256+threadIdx.x; if (i < P_) atomicAdd(&g_cnt[g_topi[i]], 1); }
__global__ void moe_scan_kernel(){ if (threadIdx.x==0){ int o=0; for (int e=0;e<E_;e++){ g_off[e]=o; o+=g_cnt[e]; } } }
__global__ void moe_scatter_kernel(){
  int i = blockIdx.x*256+threadIdx.x;
  if (i < P_) {
    int e = g_topi[i];
    int pos = g_off[e] + atomicAdd(&g_cur[e], 1);
    g_ptok[pos] = i >> 1;
    g_pslot[i]  = pos;
  }
}

// ---------------- final combine: out = resattn + mlp + w0*y0 + w1*y1 ----------------
__global__ void final_kernel(float* __restrict__ out) {
  const int t = blockIdx.x;
  const int p0 = g_pslot[t*2], p1 = g_pslot[t*2+1];
  const float w0 = g_topw[t*2], w1 = g_topw[t*2+1];
  const float4* ra = (const float4*)(g_resat + (size_t)t*H_);
  const float4* ml = (const float4*)(g_mlp   + (size_t)t*H_);
  const float4* y0 = (const float4*)(g_ym    + (size_t)p0*H_);
  const float4* y1 = (const float4*)(g_ym    + (size_t)p1*H_);
  float4* op = (float4*)(out + (size_t)t*H_);
  for (int i = threadIdx.x; i < 512; i += 256) {
    float4 A=ra[i], B=ml[i], C=y0[i], D=y1[i];
    op[i] = make_float4(A.x+B.x+w0*C.x+w1*D.x, A.y+B.y+w0*C.y+w1*D.y,
                        A.z+B.z+w0*C.z+w1*D.z, A.w+B.w+w0*C.w+w1*D.w);
  }
}

// ---------------- host ----------------
extern "C" void kernel_launch(void* const* d_in, const int* in_sizes, int n_in,
                              void* d_out, int out_size) {
  (void)in_sizes; (void)n_in; (void)out_size;
  const float* x      = (const float*)d_in[0];
  const float* ln_in  = (const float*)d_in[1];
  const float* ln_post= (const float*)d_in[2];
  const float* ln_res = (const float*)d_in[3];
  const float* wqkv   = (const float*)d_in[4];
  const float* wo     = (const float*)d_in[5];
  const float* w13    = (const float*)d_in[6];
  const float* w2     = (const float*)d_in[7];
  const float* gw     = (const float*)d_in[8];
  const float* ws     = (const float*)d_in[9];
  const float* w2s    = (const float*)d_in[10];
  float* out = (float*)d_out;

  float *xn,*qkv,*attn,*aproj,*resat,*h2n,*gu,*hmid,*mlp,*h3n,*gum,*hmm,*ym;
  cudaGetSymbolAddress((void**)&xn,   g_xn);
  cudaGetSymbolAddress((void**)&qkv,  g_qkv);
  cudaGetSymbolAddress((void**)&attn, g_attn);
  cudaGetSymbolAddress((void**)&aproj,g_aproj);
  cudaGetSymbolAddress((void**)&resat,g_resat);
  cudaGetSymbolAddress((void**)&h2n,  g_h2n);
  cudaGetSymbolAddress((void**)&gu,   g_gu);
  cudaGetSymbolAddress((void**)&hmid, g_hmid);
  cudaGetSymbolAddress((void**)&mlp,  g_mlp);
  cudaGetSymbolAddress((void**)&h3n,  g_h3n);
  cudaGetSymbolAddress((void**)&gum,  g_gum);
  cudaGetSymbolAddress((void**)&hmm,  g_hmm);
  cudaGetSymbolAddress((void**)&ym,   g_ym);

  cudaFuncSetAttribute(attn_kernel, cudaFuncAttributeMaxDynamicSharedMemorySize, ATTN_SMEM);

  // attention branch
  rmsnorm_kernel<<<T_, 256>>>(x, ln_in, xn);
  gemm_nn<<<dim3(QKVW_/128, T_/128), 256>>>(xn, wqkv, qkv, QKVW_, H_);
  rope_kernel<<<dim3(T_, NH_+NKV_), 64>>>(qkv);
  attn_kernel<<<dim3(NH_, T_/64), 256, ATTN_SMEM>>>(qkv, attn);
  gemm_nn<<<dim3(H_/128, T_/128), 256>>>(attn, wo, aproj, H_, H_);
  add_kernel<<<(T_*H_)/1024, 256>>>(x, aproj, resat);

  // residual MLP branch
  rmsnorm_kernel<<<T_, 256>>>(resat, ln_res, h2n);
  gemm_nn<<<dim3((2*H_)/128, T_/128), 256>>>(h2n, w13, gu, 2*H_, H_);
  silu_resmlp_kernel<<<(T_*H_)/1024, 256>>>();
  gemm_nn<<<dim3(H_/128, T_/128), 256>>>(hmid, w2, mlp, H_, H_);

  // MoE branch (on original residual input)
  rmsnorm_kernel<<<T_, 256>>>(x, ln_post, h3n);
  gate_kernel<<<T_, 256>>>(gw);
  moe_zero_kernel<<<1, 32>>>();
  moe_count_kernel<<<P_/256, 256>>>();
  moe_scan_kernel<<<1, 32>>>();
  moe_scatter_kernel<<<P_/256, 256>>>();
  // per-expert count <= T (each token picks 2 distinct experts) -> 16 m-tiles suffice
  gemm_bt_group<<<dim3((2*I_)/128, T_/128, E_), 256>>>(h3n, ws, gum, 2*I_, H_, H_, 1);
  silu_moe_kernel<<<(P_*I_)/1024, 256>>>();
  gemm_bt_group<<<dim3(H_/128, T_/128, E_), 256>>>(hmm, w2s, ym, H_, I_, I_, 0);

  // combine
  final_kernel<<<T_, 256>>>(out);
}

// round 7
// speedup vs baseline: 1.8501x; 1.8501x over previous
#include <cuda_runtime.h>
#include <cuda_bf16.h>
#include <math.h>

#define T_ 2048
#define H_ 2048
#define NH_ 16
#define NKV_ 4
#define HD_ 128
#define I_ 1024
#define E_ 16
#define TOPK_ 2
#define P_ (T_*TOPK_)
#define QKVW_ 3072

typedef __nv_bfloat16 bf16;

// ---------------- scratch (device globals; no allocations allowed) ----------------
__device__ float g_qkv[T_*QKVW_];
__device__ float g_aproj[T_*H_];
__device__ float g_resat[T_*H_];
__device__ float g_gu[T_*2*H_];
__device__ float g_mlp[T_*H_];
__device__ float g_gum[P_*2*I_];
__device__ float g_ym[P_*H_];

__device__ bf16 g_xn_h[T_*H_],   g_xn_l[T_*H_];
__device__ bf16 g_attn_h[T_*H_], g_attn_l[T_*H_];
__device__ bf16 g_h2n_h[T_*H_],  g_h2n_l[T_*H_];
__device__ bf16 g_hmid_h[T_*H_], g_hmid_l[T_*H_];
__device__ bf16 g_h3n_h[T_*H_],  g_h3n_l[T_*H_];
__device__ bf16 g_hmm_h[P_*I_],  g_hmm_l[P_*I_];

__device__ bf16 g_wqkvT_h[QKVW_*H_], g_wqkvT_l[QKVW_*H_];
__device__ bf16 g_woT_h[H_*H_],      g_woT_l[H_*H_];
__device__ bf16 g_w13T_h[2*H_*H_],   g_w13T_l[2*H_*H_];
__device__ bf16 g_w2T_h[H_*H_],      g_w2T_l[H_*H_];
__device__ bf16 g_ws_h[E_*2*I_*H_],  g_ws_l[E_*2*I_*H_];
__device__ bf16 g_w2s_h[E_*H_*I_],   g_w2s_l[E_*H_*I_];

__device__ int   g_topi[P_];
__device__ float g_topw[P_];
__device__ int   g_cnt[E_];
__device__ int   g_off[E_];
__device__ int   g_cur[E_];
__device__ int   g_ptok[P_];
__device__ int   g_pslot[P_];

__device__ __forceinline__ float neg_inff() { return __int_as_float(0xff800000); }

// ---------------- ptx helpers (base compute_103-safe: cp.async/ldmatrix/mma.sync only) ----------------
__device__ __forceinline__ unsigned smem_u32(const void* p) {
  unsigned a;
  asm("{ .reg .u64 t; cvta.to.shared.u64 t, %1; cvt.u32.u64 %0, t; }" : "=r"(a) : "l"(p));
  return a;
}
__device__ __forceinline__ void cp16(unsigned dst, const void* src, bool valid) {
  int sz = valid ? 16 : 0;
  asm volatile("cp.async.cg.shared.global [%0], [%1], 16, %2;"
               :: "r"(dst), "l"(src), "r"(sz) : "memory");
}
#define CP_COMMIT() asm volatile("cp.async.commit_group;" ::: "memory")
#define CP_WAIT(n)  asm volatile("cp.async.wait_group %0;" :: "n"(n) : "memory")

__device__ __forceinline__ void ldsm4(unsigned* r, unsigned addr) {
  asm volatile("ldmatrix.sync.aligned.m8n8.x4.shared.b16 {%0,%1,%2,%3}, [%4];"
               : "=r"(r[0]), "=r"(r[1]), "=r"(r[2]), "=r"(r[3]) : "r"(addr));
}
__device__ __forceinline__ void mma16816(float* d, const unsigned* a, unsigned b0, unsigned b1) {
  asm volatile("mma.sync.aligned.m16n8k16.row.col.f32.bf16.bf16.f32 "
               "{%0,%1,%2,%3}, {%4,%5,%6,%7}, {%8,%9}, {%0,%1,%2,%3};"
               : "+f"(d[0]), "+f"(d[1]), "+f"(d[2]), "+f"(d[3])
               : "r"(a[0]), "r"(a[1]), "r"(a[2]), "r"(a[3]), "r"(b0), "r"(b1));
}

// ---------------- bf16 split helpers ----------------
__device__ __forceinline__ void split_store4(float4 v, bf16* ph, bf16* pl) {
  float a[4] = {v.x, v.y, v.z, v.w};
  bf16 h[4], l[4];
  #pragma unroll
  for (int i = 0; i < 4; i++) {
    h[i] = __float2bfloat16_rn(a[i]);
    l[i] = __float2bfloat16_rn(a[i] - __bfloat162float(h[i]));
  }
  *(uint2*)ph = *(uint2*)h;
  *(uint2*)pl = *(uint2*)l;
}

// ---------------- weight prep ----------------
__global__ void __launch_bounds__(256) convert_split(const float* __restrict__ in,
                                                     bf16* __restrict__ oh, bf16* __restrict__ ol) {
  size_t i = (size_t)blockIdx.x * 256 + threadIdx.x;
  float4 v = ((const float4*)in)[i];
  split_store4(v, oh + i * 4, ol + i * 4);
}

// transpose+split: in[K][N] fp32 -> oh/ol [N][K] bf16. grid (N/32, K/32), 256 thr.
__global__ void __launch_bounds__(256) transpose_split(const float* __restrict__ in,
                                                       bf16* __restrict__ oh, bf16* __restrict__ ol,
                                                       int K, int N) {
  __shared__ float t[32][33];
  int k0 = blockIdx.y * 32, n0 = blockIdx.x * 32;
  int tx = threadIdx.x & 31, ty = threadIdx.x >> 5;
  #pragma unroll
  for (int j = 0; j < 4; j++)
    t[ty + 8 * j][tx] = in[(size_t)(k0 + ty + 8 * j) * N + n0 + tx];
  __syncthreads();
  #pragma unroll
  for (int j = 0; j < 4; j++) {
    float v = t[tx][ty + 8 * j];
    bf16 h = __float2bfloat16_rn(v);
    bf16 l = __float2bfloat16_rn(v - __bfloat162float(h));
    size_t o = (size_t)(n0 + ty + 8 * j) * K + k0 + tx;
    oh[o] = h; ol[o] = l;
  }
}

// ---------------- RMSNorm: one block per token, emits hi/lo bf16 ----------------
__global__ void __launch_bounds__(256) rmsnorm_split(const float* __restrict__ x,
                                                     const float* __restrict__ w,
                                                     bf16* __restrict__ oh, bf16* __restrict__ ol) {
  const int t = blockIdx.x;
  const float4* xr = (const float4*)(x + (size_t)t * H_);
  const float4* wr = (const float4*)w;
  const int i0 = threadIdx.x, i1 = threadIdx.x + 256;
  float4 v0 = xr[i0], v1 = xr[i1];
  float s = v0.x*v0.x+v0.y*v0.y+v0.z*v0.z+v0.w*v0.w
          + v1.x*v1.x+v1.y*v1.y+v1.z*v1.z+v1.w*v1.w;
  #pragma unroll
  for (int off = 16; off; off >>= 1) s += __shfl_xor_sync(0xffffffffu, s, off);
  __shared__ float red[8];
  __shared__ float sinv;
  if ((threadIdx.x & 31) == 0) red[threadIdx.x >> 5] = s;
  __syncthreads();
  if (threadIdx.x == 0) {
    float tt = 0.f;
    #pragma unroll
    for (int k = 0; k < 8; k++) tt += red[k];
    sinv = rsqrtf(tt * (1.f / H_) + 1e-5f);
  }
  __syncthreads();
  float r = sinv;
  float4 w0 = wr[i0], w1 = wr[i1];
  float4 o0, o1;
  o0.x=v0.x*r*w0.x; o0.y=v0.y*r*w0.y; o0.z=v0.z*r*w0.z; o0.w=v0.w*r*w0.w;
  o1.x=v1.x*r*w1.x; o1.y=v1.y*r*w1.y; o1.z=v1.z*r*w1.z; o1.w=v1.w*r*w1.w;
  size_t base = (size_t)t * H_;
  split_store4(o0, oh + base + i0 * 4, ol + base + i0 * 4);
  split_store4(o1, oh + base + i1 * 4, ol + base + i1 * 4);
}

// ---------------- mma.sync split-bf16 GEMM ----------------
// D[row, n] = sum_k A[row,k]*B[n,k], fp32 out. A,B as hi/lo bf16, K-major [*,K].
// CTA tile 128x128, 8 warps (4m x 2n), warp tile 32x64, K-chunk 32, 2-stage cp.async.
// grouped: 0=dense, 1=gather A rows via g_ptok, 2=slot rows. C rows = expert-slot order.
// smem: 2 stages x 4 mats(Ah,Al,Bh,Bl) x 128 rows x 40 halves (80B row stride) = 81920B; +512B rowmap.
#define MMA_SMEM (81920 + 512)
__global__ void __launch_bounds__(256) mma_gemm(const bf16* __restrict__ Ah, const bf16* __restrict__ Al,
                                                const bf16* __restrict__ Bh, const bf16* __restrict__ Bl,
                                                float* __restrict__ C, int N, int K, int grouped) {
  extern __shared__ char smem[];
  const int tid = threadIdx.x, wid = tid >> 5, lane = tid & 31;
  const int e = blockIdx.z;
  int count = 0, sbase = 0;
  if (grouped) {
    count = g_cnt[e];
    if ((int)(blockIdx.y << 7) >= count) return;
    sbase = g_off[e];
  }
  const bf16* BhE = Bh + (size_t)e * N * K;
  const bf16* BlE = Bl + (size_t)e * N * K;
  const int m0 = blockIdx.y << 7, n0 = blockIdx.x << 7;
  unsigned sb = smem_u32(smem);
  int* rowmap = (int*)(smem + 81920);

  if (tid < 128) {
    int gr = m0 + tid;
    if (grouped) {
      if (m0 + tid < count) {
        int slot = sbase + m0 + tid;
        gr = (grouped == 1) ? g_ptok[slot] : slot;
      } else gr = -1;
    }
    rowmap[tid] = gr;
  }
  __syncthreads();

  const int nk = K >> 5;
  auto load_chunk = [&](int c, int st) {
    #pragma unroll
    for (int i = 0; i < 8; i++) {
      int s = tid + (i << 8);
      int mat = s >> 9, r = (s >> 2) & 127, cq = s & 3;
      unsigned dst = sb + (unsigned)st * 40960u + (unsigned)mat * 10240u + (unsigned)(r * 80 + cq * 16);
      const bf16* src;
      bool valid = true;
      if (mat < 2) {
        int gr = rowmap[r];
        if (gr < 0) { valid = false; gr = 0; }
        src = (mat ? Al : Ah) + (size_t)gr * K + (c << 5) + (cq << 3);
      } else {
        src = (mat == 2 ? BhE : BlE) + (size_t)(n0 + r) * K + (c << 5) + (cq << 3);
      }
      cp16(dst, src, valid);
    }
    CP_COMMIT();
  };

  float acc[2][8][4];
  #pragma unroll
  for (int i = 0; i < 2; i++)
    #pragma unroll
    for (int j = 0; j < 8; j++)
      #pragma unroll
      for (int k = 0; k < 4; k++) acc[i][j][k] = 0.f;

  const int wm = (wid >> 1) << 5;           // warp m offset (0..96)
  const int wn = (wid & 1) << 6;            // warp n offset (0 or 64)
  const int ar  = lane & 15;                // A ldmatrix row-in-tile
  const int akh = (lane < 16) ? 0 : 8;      // A ldmatrix k-half
  const int bn  = (lane & 7) + ((lane & 16) ? 8 : 0);  // B ldmatrix n row
  const int bkh = (lane & 8) ? 8 : 0;       // B ldmatrix k-half

  load_chunk(0, 0);
  for (int c = 0; c < nk; c++) {
    const int st = c & 1;
    if (c + 1 < nk) { load_chunk(c + 1, st ^ 1); CP_WAIT(1); }
    else CP_WAIT(0);
    __syncthreads();
    const unsigned stb = sb + (unsigned)st * 40960u;
    #pragma unroll
    for (int ks = 0; ks < 2; ks++) {
      const unsigned kb = (unsigned)(ks * 16) * 2u;
      unsigned ahf[2][4], alf[2][4];
      #pragma unroll
      for (int mi = 0; mi < 2; mi++) {
        unsigned rowA = (unsigned)((wm + mi * 16 + ar) * 80);
        ldsm4(ahf[mi], stb +          rowA + kb + akh * 2);
        ldsm4(alf[mi], stb + 10240u + rowA + kb + akh * 2);
      }
      #pragma unroll
      for (int nb = 0; nb < 4; nb++) {
        unsigned rowB = (unsigned)((wn + nb * 16 + bn) * 80);
        unsigned bhf[4], blf[4];
        ldsm4(bhf, stb + 20480u + rowB + kb + bkh * 2);
        ldsm4(blf, stb + 30720u + rowB + kb + bkh * 2);
        #pragma unroll
        for (int mi = 0; mi < 2; mi++) {
          #pragma unroll
          for (int half = 0; half < 2; half++) {
            float* d = acc[mi][nb * 2 + half];
            mma16816(d, ahf[mi], bhf[half * 2], bhf[half * 2 + 1]);
            mma16816(d, alf[mi], bhf[half * 2], bhf[half * 2 + 1]);
            mma16816(d, ahf[mi], blf[half * 2], blf[half * 2 + 1]);
          }
        }
      }
    }
    __syncthreads();
  }

  // epilogue: thread (mi, nt) rows = wm+mi*16+(lane>>2) and +8, cols = wn+nt*8+(lane&3)*2
  #pragma unroll
  for (int mi = 0; mi < 2; mi++) {
    const int lr0 = wm + mi * 16 + (lane >> 2);
    const int gr0 = m0 + lr0;
    const bool s0 = !grouped || (gr0 < count);
    const bool s1 = !grouped || (gr0 + 8 < count);
    const size_t row0 = (size_t)((grouped ? sbase : 0) + gr0);
    #pragma unroll
    for (int nt = 0; nt < 8; nt++) {
      const int col = n0 + wn + nt * 8 + ((lane & 3) << 1);
      float* d = acc[mi][nt];
      if (s0) *(float2*)(C + row0 * N + col)       = make_float2(d[0], d[1]);
      if (s1) *(float2*)(C + (row0 + 8) * N + col) = make_float2(d[2], d[3]);
    }
  }
}

// ---------------- RoPE (neox) on q and k heads, in place ----------------
__global__ void rope_kernel(float* __restrict__ qkv) {
  const int t = blockIdx.x, hh = blockIdx.y, i = threadIdx.x;   // 64 threads
  float* bptr = qkv + (size_t)t*QKVW_ + (hh < NH_ ? hh*HD_ : NH_*HD_ + (hh-NH_)*HD_);
  float p = (float)t;
  float fr = powf(10000.f, -(float)(2*i) * (1.f/HD_));
  float ang = p * fr;
  float sn, cs; sincosf(ang, &sn, &cs);
  float x1 = bptr[i], x2 = bptr[i+64];
  bptr[i]    = x1*cs - x2*sn;
  bptr[i+64] = x2*cs + x1*sn;
}

// ---------------- Flash attention: block = (head, q-tile of 64) ----------------
#define ATTN_SMEM (20928*4)
__global__ void __launch_bounds__(256) attn_kernel(const float* __restrict__ qkv,
                                                   bf16* __restrict__ outh,
                                                   bf16* __restrict__ outl) {
  extern __shared__ float sm[];
  float* Qs  = sm;              // [128][64] d-major
  float* KVs = sm + 8192;       // Ks [128][64] then Vs [64][128]
  float* Ss  = sm + 16384;      // [64][68]
  float* rm  = sm + 16384 + 64*68;
  float* rl  = rm + 64;
  float* ra  = rl + 64;

  const int h  = blockIdx.x;
  const int q0 = blockIdx.y * 64;
  const int kvh = h >> 2;               // NH/NKV = 4
  const int tid = threadIdx.x;
  const int ty = tid >> 4, tx = tid & 15;

  for (int i = tid; i < 2048; i += 256) {
    int r = i >> 5, dq = (i & 31) << 2;
    float4 v = *(const float4*)(qkv + (size_t)(q0+r)*QKVW_ + h*HD_ + dq);
    Qs[(dq+0)*64 + r] = v.x; Qs[(dq+1)*64 + r] = v.y;
    Qs[(dq+2)*64 + r] = v.z; Qs[(dq+3)*64 + r] = v.w;
  }
  if (tid < 64) { rm[tid] = neg_inff(); rl[tid] = 0.f; }
  float o[4][8];
  #pragma unroll
  for (int i=0;i<4;i++)
    #pragma unroll
    for (int j=0;j<8;j++) o[i][j]=0.f;
  __syncthreads();

  const float scale = 0.08838834764831845f;   // 1/sqrt(128)
  const int ntiles = blockIdx.y + 1;
  for (int kt = 0; kt < ntiles; kt++) {
    const int k0 = kt * 64;
    for (int i = tid; i < 2048; i += 256) {
      int s = i >> 5, dq = (i & 31) << 2;
      float4 v = *(const float4*)(qkv + (size_t)(k0+s)*QKVW_ + NH_*HD_ + kvh*HD_ + dq);
      KVs[(dq+0)*64+s]=v.x; KVs[(dq+1)*64+s]=v.y;
      KVs[(dq+2)*64+s]=v.z; KVs[(dq+3)*64+s]=v.w;
    }
    __syncthreads();
    float acc[4][4] = {};
    #pragma unroll 4
    for (int d = 0; d < 128; d++) {
      float4 qa = *(const float4*)&Qs[d*64 + ty*4];
      float4 kb = *(const float4*)&KVs[d*64 + tx*4];
      float av[4]={qa.x,qa.y,qa.z,qa.w}, bv[4]={kb.x,kb.y,kb.z,kb.w};
      #pragma unroll
      for (int i=0;i<4;i++)
        #pragma unroll
        for (int j=0;j<4;j++) acc[i][j] += av[i]*bv[j];
    }
    __syncthreads();
    #pragma unroll
    for (int i=0;i<4;i++) {
      int qq = q0 + ty*4 + i;
      #pragma unroll
      for (int j=0;j<4;j++) {
        int kk = k0 + tx*4 + j;
        Ss[(ty*4+i)*68 + tx*4+j] = (kk <= qq) ? acc[i][j]*scale : neg_inff();
      }
    }
    __syncthreads();
    if (tid < 64) {
      float mold = rm[tid];
      float mmax = mold;
      float* srw = Ss + tid*68;
      for (int c=0;c<64;c++) mmax = fmaxf(mmax, srw[c]);
      float sum = 0.f;
      for (int c=0;c<64;c++){ float p = __expf(srw[c]-mmax); srw[c]=p; sum+=p; }
      float al = (mold == neg_inff()) ? 0.f : __expf(mold - mmax);
      rl[tid] = rl[tid]*al + sum;
      rm[tid] = mmax;
      ra[tid] = al;
    }
    __syncthreads();
    for (int i = tid; i < 2048; i += 256) {   // V tile, s-major [64][128]
      int s = i >> 5, dq = (i & 31) << 2;
      float4 v = *(const float4*)(qkv + (size_t)(k0+s)*QKVW_ + (NH_+NKV_)*HD_ + kvh*HD_ + dq);
      *(float4*)&KVs[s*128 + dq] = v;
    }
    __syncthreads();
    float alr[4];
    #pragma unroll
    for (int i=0;i<4;i++) alr[i] = ra[ty*4+i];
    #pragma unroll
    for (int i=0;i<4;i++)
      #pragma unroll
      for (int j=0;j<8;j++) o[i][j] *= alr[i];
    for (int s=0;s<64;s++) {
      float4 v0 = *(const float4*)&KVs[s*128 + tx*8];
      float4 v1 = *(const float4*)&KVs[s*128 + tx*8 + 4];
      float pv[4];
      #pragma unroll
      for (int i=0;i<4;i++) pv[i] = Ss[(ty*4+i)*68 + s];
      #pragma unroll
      for (int i=0;i<4;i++) {
        o[i][0]+=pv[i]*v0.x; o[i][1]+=pv[i]*v0.y; o[i][2]+=pv[i]*v0.z; o[i][3]+=pv[i]*v0.w;
        o[i][4]+=pv[i]*v1.x; o[i][5]+=pv[i]*v1.y; o[i][6]+=pv[i]*v1.z; o[i][7]+=pv[i]*v1.w;
      }
    }
    __syncthreads();
  }
  #pragma unroll
  for (int i=0;i<4;i++) {
    float inv = 1.f / rl[ty*4+i];
    int r = q0 + ty*4 + i;
    size_t bidx = (size_t)r*H_ + h*HD_ + tx*8;
    float4 a = make_float4(o[i][0]*inv, o[i][1]*inv, o[i][2]*inv, o[i][3]*inv);
    float4 b = make_float4(o[i][4]*inv, o[i][5]*inv, o[i][6]*inv, o[i][7]*inv);
    split_store4(a, outh + bidx,     outl + bidx);
    split_store4(b, outh + bidx + 4, outl + bidx + 4);
  }
}

// ---------------- elementwise ----------------
__global__ void add_kernel(const float* __restrict__ a, const float* __restrict__ b,
                           float* __restrict__ c) {
  int i = blockIdx.x*256 + threadIdx.x;
  float4 va = ((const float4*)a)[i], vb = ((const float4*)b)[i];
  ((float4*)c)[i] = make_float4(va.x+vb.x, va.y+vb.y, va.z+vb.z, va.w+vb.w);
}

__device__ __forceinline__ float siluf(float g){ return g / (1.f + expf(-g)); }

__global__ void silu_resmlp_kernel() {
  int idx = blockIdx.x*256 + threadIdx.x;       // over T_*H_/4
  int t = idx >> 9;
  int jq = idx & 511;
  const float4* gp = (const float4*)(g_gu + (size_t)t*2*H_);
  float4 g4 = gp[jq], u4 = gp[jq + 512];
  float4 o = make_float4(siluf(g4.x)*u4.x, siluf(g4.y)*u4.y, siluf(g4.z)*u4.z, siluf(g4.w)*u4.w);
  size_t b = (size_t)t*H_ + jq*4;
  split_store4(o, g_hmid_h + b, g_hmid_l + b);
}

__global__ void silu_moe_kernel() {
  int idx = blockIdx.x*256 + threadIdx.x;       // over P_*I_/4
  int p = idx >> 8;
  int jq = idx & 255;
  const float4* gp = (const float4*)(g_gum + (size_t)p*2*I_);
  float4 g4 = gp[jq], u4 = gp[jq + 256];
  float4 o = make_float4(siluf(g4.x)*u4.x, siluf(g4.y)*u4.y, siluf(g4.z)*u4.z, siluf(g4.w)*u4.w);
  size_t b = (size_t)p*I_ + jq*4;
  split_store4(o, g_hmm_h + b, g_hmm_l + b);
}

// ---------------- gating + routing ----------------
__global__ void __launch_bounds__(256) gate_kernel(const float* __restrict__ gw) {
  const int t = blockIdx.x;
  __shared__ float part[256];
  const int tid = threadIdx.x;
  const int e = tid & 15, c = tid >> 4;
  const bf16* xh = g_h3n_h + (size_t)t*H_;
  const bf16* xl = g_h3n_l + (size_t)t*H_;
  float s = 0.f;
  for (int h = c*128; h < c*128+128; h++)
    s += (__bfloat162float(xh[h]) + __bfloat162float(xl[h])) * gw[h*E_ + e];
  part[tid] = s;
  __syncthreads();
  if (tid == 0) {
    float lg[16];
    for (int ee=0; ee<16; ee++){ float v=0.f; for (int cc=0; cc<16; cc++) v += part[cc*16+ee]; lg[ee]=v; }
    int i1 = 0;
    for (int ee=1; ee<16; ee++) if (lg[ee] > lg[i1]) i1 = ee;
    int i2 = (i1==0) ? 1 : 0;
    for (int ee=0; ee<16; ee++) if (ee!=i1 && lg[ee] > lg[i2]) i2 = ee;
    float mx = lg[i1];
    float p1 = expf(lg[i1]-mx), p2 = expf(lg[i2]-mx);
    float d = p1 + p2;
    g_topi[t*2]=i1; g_topi[t*2+1]=i2;
    g_topw[t*2]=p1/d; g_topw[t*2+1]=p2/d;
  }
}

__global__ void moe_zero_kernel(){ if (threadIdx.x < E_){ g_cnt[threadIdx.x]=0; g_cur[threadIdx.x]=0; } }
__global__ void moe_count_kernel(){ int i = blockIdx.x*256+threadIdx.x; if (i < P_) atomicAdd(&g_cnt[g_topi[i]], 1); }
__global__ void moe_scan_kernel(){ if (threadIdx.x==0){ int o=0; for (int e=0;e<E_;e++){ g_off[e]=o; o+=g_cnt[e]; } } }
__global__ void moe_scatter_kernel(){
  int i = blockIdx.x*256+threadIdx.x;
  if (i < P_) {
    int e = g_topi[i];
    int pos = g_off[e] + atomicAdd(&g_cur[e], 1);
    g_ptok[pos] = i >> 1;
    g_pslot[i]  = pos;
  }
}

// ---------------- final combine: out = resattn + mlp + w0*y0 + w1*y1 ----------------
__global__ void final_kernel(float* __restrict__ out) {
  const int t = blockIdx.x;
  const int p0 = g_pslot[t*2], p1 = g_pslot[t*2+1];
  const float w0 = g_topw[t*2], w1 = g_topw[t*2+1];
  const float4* ra = (const float4*)(g_resat + (size_t)t*H_);
  const float4* ml = (const float4*)(g_mlp   + (size_t)t*H_);
  const float4* y0 = (const float4*)(g_ym    + (size_t)p0*H_);
  const float4* y1 = (const float4*)(g_ym    + (size_t)p1*H_);
  float4* op = (float4*)(out + (size_t)t*H_);
  for (int i = threadIdx.x; i < 512; i += 256) {
    float4 A=ra[i], B=ml[i], C=y0[i], D=y1[i];
    op[i] = make_float4(A.x+B.x+w0*C.x+w1*D.x, A.y+B.y+w0*C.y+w1*D.y,
                        A.z+B.z+w0*C.z+w1*D.z, A.w+B.w+w0*C.w+w1*D.w);
  }
}

// ---------------- host ----------------
extern "C" void kernel_launch(void* const* d_in, const int* in_sizes, int n_in,
                              void* d_out, int out_size) {
  (void)in_sizes; (void)n_in; (void)out_size;
  const float* x      = (const float*)d_in[0];
  const float* ln_in  = (const float*)d_in[1];
  const float* ln_post= (const float*)d_in[2];
  const float* ln_res = (const float*)d_in[3];
  const float* wqkv   = (const float*)d_in[4];
  const float* wo     = (const float*)d_in[5];
  const float* w13    = (const float*)d_in[6];
  const float* w2     = (const float*)d_in[7];
  const float* gw     = (const float*)d_in[8];
  const float* ws     = (const float*)d_in[9];
  const float* w2s    = (const float*)d_in[10];
  float* out = (float*)d_out;

  float *qkv,*aproj,*resat,*gu,*mlp,*gum,*ym;
  cudaGetSymbolAddress((void**)&qkv,  g_qkv);
  cudaGetSymbolAddress((void**)&aproj,g_aproj);
  cudaGetSymbolAddress((void**)&resat,g_resat);
  cudaGetSymbolAddress((void**)&gu,   g_gu);
  cudaGetSymbolAddress((void**)&mlp,  g_mlp);
  cudaGetSymbolAddress((void**)&gum,  g_gum);
  cudaGetSymbolAddress((void**)&ym,   g_ym);

  bf16 *xnh,*xnl,*ath,*atl,*h2h,*h2l,*hmh,*hml,*h3h,*h3l,*hmmh,*hmml;
  cudaGetSymbolAddress((void**)&xnh, g_xn_h);   cudaGetSymbolAddress((void**)&xnl, g_xn_l);
  cudaGetSymbolAddress((void**)&ath, g_attn_h); cudaGetSymbolAddress((void**)&atl, g_attn_l);
  cudaGetSymbolAddress((void**)&h2h, g_h2n_h);  cudaGetSymbolAddress((void**)&h2l, g_h2n_l);
  cudaGetSymbolAddress((void**)&hmh, g_hmid_h); cudaGetSymbolAddress((void**)&hml, g_hmid_l);
  cudaGetSymbolAddress((void**)&h3h, g_h3n_h);  cudaGetSymbolAddress((void**)&h3l, g_h3n_l);
  cudaGetSymbolAddress((void**)&hmmh,g_hmm_h);  cudaGetSymbolAddress((void**)&hmml,g_hmm_l);

  bf16 *wqh,*wql,*woh,*wol,*w13h,*w13l,*w2h,*w2l,*wsh,*wsl,*w2sh,*w2sl;
  cudaGetSymbolAddress((void**)&wqh, g_wqkvT_h); cudaGetSymbolAddress((void**)&wql, g_wqkvT_l);
  cudaGetSymbolAddress((void**)&woh, g_woT_h);   cudaGetSymbolAddress((void**)&wol, g_woT_l);
  cudaGetSymbolAddress((void**)&w13h,g_w13T_h);  cudaGetSymbolAddress((void**)&w13l,g_w13T_l);
  cudaGetSymbolAddress((void**)&w2h, g_w2T_h);   cudaGetSymbolAddress((void**)&w2l, g_w2T_l);
  cudaGetSymbolAddress((void**)&wsh, g_ws_h);    cudaGetSymbolAddress((void**)&wsl, g_ws_l);
  cudaGetSymbolAddress((void**)&w2sh,g_w2s_h);   cudaGetSymbolAddress((void**)&w2sl,g_w2s_l);

  cudaFuncSetAttribute(attn_kernel, cudaFuncAttributeMaxDynamicSharedMemorySize, ATTN_SMEM);
  cudaFuncSetAttribute(mma_gemm,    cudaFuncAttributeMaxDynamicSharedMemorySize, MMA_SMEM);

  // ---- weight prep (split + transpose where needed) ----
  transpose_split<<<dim3(QKVW_/32, H_/32), 256>>>(wqkv, wqh, wql, H_, QKVW_);
  transpose_split<<<dim3(H_/32,    H_/32), 256>>>(wo,   woh, wol, H_, H_);
  transpose_split<<<dim3(2*H_/32,  H_/32), 256>>>(w13,  w13h,w13l,H_, 2*H_);
  transpose_split<<<dim3(H_/32,    H_/32), 256>>>(w2,   w2h, w2l, H_, H_);
  convert_split<<<(E_*2*I_*H_)/1024, 256>>>(ws,  wsh,  wsl);
  convert_split<<<(E_*H_*I_)/1024,   256>>>(w2s, w2sh, w2sl);

  // ---- attention branch ----
  rmsnorm_split<<<T_, 256>>>(x, ln_in, xnh, xnl);
  mma_gemm<<<dim3(QKVW_/128, T_/128, 1), 256, MMA_SMEM>>>(xnh, xnl, wqh, wql, qkv, QKVW_, H_, 0);
  rope_kernel<<<dim3(T_, NH_+NKV_), 64>>>(qkv);
  attn_kernel<<<dim3(NH_, T_/64), 256, ATTN_SMEM>>>(qkv, ath, atl);
  mma_gemm<<<dim3(H_/128, T_/128, 1), 256, MMA_SMEM>>>(ath, atl, woh, wol, aproj, H_, H_, 0);
  add_kernel<<<(T_*H_)/1024, 256>>>(x, aproj, resat);

  // ---- residual MLP branch ----
  rmsnorm_split<<<T_, 256>>>(resat, ln_res, h2h, h2l);
  mma_gemm<<<dim3(2*H_/128, T_/128, 1), 256, MMA_SMEM>>>(h2h, h2l, w13h, w13l, gu, 2*H_, H_, 0);
  silu_resmlp_kernel<<<(T_*H_)/1024, 256>>>();
  mma_gemm<<<dim3(H_/128, T_/128, 1), 256, MMA_SMEM>>>(hmh, hml, w2h, w2l, mlp, H_, H_, 0);

  // ---- MoE branch ----
  rmsnorm_split<<<T_, 256>>>(x, ln_post, h3h, h3l);
  gate_kernel<<<T_, 256>>>(gw);
  moe_zero_kernel<<<1, 32>>>();
  moe_count_kernel<<<P_/256, 256>>>();
  moe_scan_kernel<<<1, 32>>>();
  moe_scatter_kernel<<<P_/256, 256>>>();
  mma_gemm<<<dim3(2*I_/128, T_/128, E_), 256, MMA_SMEM>>>(h3h, h3l, wsh, wsl, gum, 2*I_, H_, 1);
  silu_moe_kernel<<<(P_*I_)/1024, 256>>>();
  mma_gemm<<<dim3(H_/128, T_/128, E_), 256, MMA_SMEM>>>(hmmh, hmml, w2sh, w2sl, ym, H_, I_, 2);

  // ---- combine ----
  final_kernel<<<T_, 256>>>(out);
}

// round 8
// speedup vs baseline: 2.5393x; 1.3725x over previous
#include <cuda_runtime.h>
#include <cuda_bf16.h>
#include <math.h>

#define T_ 2048
#define H_ 2048
#define NH_ 16
#define NKV_ 4
#define HD_ 128
#define I_ 1024
#define E_ 16
#define TOPK_ 2
#define P_ (T_*TOPK_)
#define QKVW_ 3072

typedef __nv_bfloat16 bf16;

// ---------------- scratch (device globals; no allocations allowed) ----------------
__device__ float g_qkv[T_*QKVW_];
__device__ float g_aproj[T_*H_];
__device__ float g_resat[T_*H_];
__device__ float g_gu[T_*2*H_];
__device__ float g_mlp[T_*H_];
__device__ float g_gum[P_*2*I_];
__device__ float g_ym[P_*H_];

__device__ bf16 g_xn_h[T_*H_],   g_xn_l[T_*H_];
__device__ bf16 g_attn_h[T_*H_], g_attn_l[T_*H_];
__device__ bf16 g_h2n_h[T_*H_],  g_h2n_l[T_*H_];
__device__ bf16 g_hmid_h[T_*H_], g_hmid_l[T_*H_];
__device__ bf16 g_h3n_h[T_*H_],  g_h3n_l[T_*H_];
__device__ bf16 g_hmm_h[P_*I_],  g_hmm_l[P_*I_];

__device__ bf16 g_q_h[NH_*T_*HD_],  g_q_l[NH_*T_*HD_];
__device__ bf16 g_k_h[NKV_*T_*HD_], g_k_l[NKV_*T_*HD_];
__device__ bf16 g_v_h[NKV_*T_*HD_], g_v_l[NKV_*T_*HD_];

__device__ bf16 g_wqkvT_h[QKVW_*H_], g_wqkvT_l[QKVW_*H_];
__device__ bf16 g_woT_h[H_*H_],      g_woT_l[H_*H_];
__device__ bf16 g_w13T_h[2*H_*H_],   g_w13T_l[2*H_*H_];
__device__ bf16 g_w2T_h[H_*H_],      g_w2T_l[H_*H_];
__device__ bf16 g_ws_h[E_*2*I_*H_],  g_ws_l[E_*2*I_*H_];
__device__ bf16 g_w2s_h[E_*H_*I_],   g_w2s_l[E_*H_*I_];

__device__ int   g_topi[P_];
__device__ float g_topw[P_];
__device__ int   g_cnt[E_];
__device__ int   g_off[E_];
__device__ int   g_cur[E_];
__device__ int   g_ptok[P_];
__device__ int   g_pslot[P_];

// ---------------- ptx helpers (base compute_103-safe) ----------------
__device__ __forceinline__ unsigned smem_u32(const void* p) {
  unsigned a;
  asm("{ .reg .u64 t; cvta.to.shared.u64 t, %1; cvt.u32.u64 %0, t; }" : "=r"(a) : "l"(p));
  return a;
}
__device__ __forceinline__ void cp16(unsigned dst, const void* src, bool valid) {
  int sz = valid ? 16 : 0;
  asm volatile("cp.async.cg.shared.global [%0], [%1], 16, %2;"
               :: "r"(dst), "l"(src), "r"(sz) : "memory");
}
#define CP_COMMIT() asm volatile("cp.async.commit_group;" ::: "memory")
#define CP_WAIT(n)  asm volatile("cp.async.wait_group %0;" :: "n"(n) : "memory")

__device__ __forceinline__ void ldsm4(unsigned* r, unsigned addr) {
  asm volatile("ldmatrix.sync.aligned.m8n8.x4.shared.b16 {%0,%1,%2,%3}, [%4];"
               : "=r"(r[0]), "=r"(r[1]), "=r"(r[2]), "=r"(r[3]) : "r"(addr));
}
__device__ __forceinline__ void ldsm4t(unsigned* r, unsigned addr) {
  asm volatile("ldmatrix.sync.aligned.m8n8.x4.trans.shared.b16 {%0,%1,%2,%3}, [%4];"
               : "=r"(r[0]), "=r"(r[1]), "=r"(r[2]), "=r"(r[3]) : "r"(addr));
}
__device__ __forceinline__ void mma16816(float* d, const unsigned* a, unsigned b0, unsigned b1) {
  asm volatile("mma.sync.aligned.m16n8k16.row.col.f32.bf16.bf16.f32 "
               "{%0,%1,%2,%3}, {%4,%5,%6,%7}, {%8,%9}, {%0,%1,%2,%3};"
               : "+f"(d[0]), "+f"(d[1]), "+f"(d[2]), "+f"(d[3])
               : "r"(a[0]), "r"(a[1]), "r"(a[2]), "r"(a[3]), "r"(b0), "r"(b1));
}

// fast 2^y on the FMA pipe (y in [-1e30, 0]); rel err < 3e-6
__device__ __forceinline__ float fexp2(float y) {
  y = fmaxf(y, -120.f);
  float z = y + 12582912.0f;                 // round-to-nearest-int via magic
  int   n = __float_as_int(z) - 0x4B400000;
  float f = y - (z - 12582912.0f);           // f in [-0.5, 0.5]
  float p = 0.0013333558f;
  p = fmaf(p, f, 0.0096181291f);
  p = fmaf(p, f, 0.0555041087f);
  p = fmaf(p, f, 0.2402265069f);
  p = fmaf(p, f, 0.6931471806f);
  p = fmaf(p, f, 1.0f);
  return p * __int_as_float((n + 127) << 23);
}

// ---------------- bf16 split helpers ----------------
__device__ __forceinline__ unsigned pack_bf16(float a, float b) {
  __nv_bfloat162 t = __floats2bfloat162_rn(a, b);
  return *(unsigned*)&t;
}
__device__ __forceinline__ void split_store4(float4 v, bf16* ph, bf16* pl) {
  float a[4] = {v.x, v.y, v.z, v.w};
  bf16 h[4], l[4];
  #pragma unroll
  for (int i = 0; i < 4; i++) {
    h[i] = __float2bfloat16_rn(a[i]);
    l[i] = __float2bfloat16_rn(a[i] - __bfloat162float(h[i]));
  }
  *(uint2*)ph = *(uint2*)h;
  *(uint2*)pl = *(uint2*)l;
}
__device__ __forceinline__ void split_store2(float a, float b, bf16* ph, bf16* pl) {
  unsigned hi = pack_bf16(a, b);
  __nv_bfloat162 hb = *(__nv_bfloat162*)&hi;
  unsigned lo = pack_bf16(a - __bfloat162float(hb.x), b - __bfloat162float(hb.y));
  *(unsigned*)ph = hi;
  *(unsigned*)pl = lo;
}
__device__ __forceinline__ void split_store1(float a, bf16* ph, bf16* pl) {
  bf16 h = __float2bfloat16_rn(a);
  *ph = h;
  *pl = __float2bfloat16_rn(a - __bfloat162float(h));
}

// ---------------- weight prep ----------------
__global__ void __launch_bounds__(256) convert_split(const float* __restrict__ in,
                                                     bf16* __restrict__ oh, bf16* __restrict__ ol) {
  size_t i = (size_t)blockIdx.x * 256 + threadIdx.x;
  float4 v = ((const float4*)in)[i];
  split_store4(v, oh + i * 4, ol + i * 4);
}

__global__ void __launch_bounds__(256) transpose_split(const float* __restrict__ in,
                                                       bf16* __restrict__ oh, bf16* __restrict__ ol,
                                                       int K, int N) {
  __shared__ float t[32][33];
  int k0 = blockIdx.y * 32, n0 = blockIdx.x * 32;
  int tx = threadIdx.x & 31, ty = threadIdx.x >> 5;
  #pragma unroll
  for (int j = 0; j < 4; j++)
    t[ty + 8 * j][tx] = in[(size_t)(k0 + ty + 8 * j) * N + n0 + tx];
  __syncthreads();
  #pragma unroll
  for (int j = 0; j < 4; j++) {
    float v = t[tx][ty + 8 * j];
    bf16 h = __float2bfloat16_rn(v);
    bf16 l = __float2bfloat16_rn(v - __bfloat162float(h));
    size_t o = (size_t)(n0 + ty + 8 * j) * K + k0 + tx;
    oh[o] = h; ol[o] = l;
  }
}

// ---------------- RMSNorm: one block per token, emits hi/lo bf16 ----------------
__global__ void __launch_bounds__(256) rmsnorm_split(const float* __restrict__ x,
                                                     const float* __restrict__ w,
                                                     bf16* __restrict__ oh, bf16* __restrict__ ol) {
  const int t = blockIdx.x;
  const float4* xr = (const float4*)(x + (size_t)t * H_);
  const float4* wr = (const float4*)w;
  const int i0 = threadIdx.x, i1 = threadIdx.x + 256;
  float4 v0 = xr[i0], v1 = xr[i1];
  float s = v0.x*v0.x+v0.y*v0.y+v0.z*v0.z+v0.w*v0.w
          + v1.x*v1.x+v1.y*v1.y+v1.z*v1.z+v1.w*v1.w;
  #pragma unroll
  for (int off = 16; off; off >>= 1) s += __shfl_xor_sync(0xffffffffu, s, off);
  __shared__ float red[8];
  __shared__ float sinv;
  if ((threadIdx.x & 31) == 0) red[threadIdx.x >> 5] = s;
  __syncthreads();
  if (threadIdx.x == 0) {
    float tt = 0.f;
    #pragma unroll
    for (int k = 0; k < 8; k++) tt += red[k];
    sinv = rsqrtf(tt * (1.f / H_) + 1e-5f);
  }
  __syncthreads();
  float r = sinv;
  float4 w0 = wr[i0], w1 = wr[i1];
  float4 o0, o1;
  o0.x=v0.x*r*w0.x; o0.y=v0.y*r*w0.y; o0.z=v0.z*r*w0.z; o0.w=v0.w*r*w0.w;
  o1.x=v1.x*r*w1.x; o1.y=v1.y*r*w1.y; o1.z=v1.z*r*w1.z; o1.w=v1.w*r*w1.w;
  size_t base = (size_t)t * H_;
  split_store4(o0, oh + base + i0 * 4, ol + base + i0 * 4);
  split_store4(o1, oh + base + i1 * 4, ol + base + i1 * 4);
}

// ---------------- mma.sync split-bf16 GEMM (unchanged from R7) ----------------
#define MMA_SMEM (81920 + 512)
__global__ void __launch_bounds__(256) mma_gemm(const bf16* __restrict__ Ah, const bf16* __restrict__ Al,
                                                const bf16* __restrict__ Bh, const bf16* __restrict__ Bl,
                                                float* __restrict__ C, int N, int K, int grouped) {
  extern __shared__ char smem[];
  const int tid = threadIdx.x, wid = tid >> 5, lane = tid & 31;
  const int e = blockIdx.z;
  int count = 0, sbase = 0;
  if (grouped) {
    count = g_cnt[e];
    if ((int)(blockIdx.y << 7) >= count) return;
    sbase = g_off[e];
  }
  const bf16* BhE = Bh + (size_t)e * N * K;
  const bf16* BlE = Bl + (size_t)e * N * K;
  const int m0 = blockIdx.y << 7, n0 = blockIdx.x << 7;
  unsigned sb = smem_u32(smem);
  int* rowmap = (int*)(smem + 81920);

  if (tid < 128) {
    int gr = m0 + tid;
    if (grouped) {
      if (m0 + tid < count) {
        int slot = sbase + m0 + tid;
        gr = (grouped == 1) ? g_ptok[slot] : slot;
      } else gr = -1;
    }
    rowmap[tid] = gr;
  }
  __syncthreads();

  const int nk = K >> 5;
  auto load_chunk = [&](int c, int st) {
    #pragma unroll
    for (int i = 0; i < 8; i++) {
      int s = tid + (i << 8);
      int mat = s >> 9, r = (s >> 2) & 127, cq = s & 3;
      unsigned dst = sb + (unsigned)st * 40960u + (unsigned)mat * 10240u + (unsigned)(r * 80 + cq * 16);
      const bf16* src;
      bool valid = true;
      if (mat < 2) {
        int gr = rowmap[r];
        if (gr < 0) { valid = false; gr = 0; }
        src = (mat ? Al : Ah) + (size_t)gr * K + (c << 5) + (cq << 3);
      } else {
        src = (mat == 2 ? BhE : BlE) + (size_t)(n0 + r) * K + (c << 5) + (cq << 3);
      }
      cp16(dst, src, valid);
    }
    CP_COMMIT();
  };

  float acc[2][8][4];
  #pragma unroll
  for (int i = 0; i < 2; i++)
    #pragma unroll
    for (int j = 0; j < 8; j++)
      #pragma unroll
      for (int k = 0; k < 4; k++) acc[i][j][k] = 0.f;

  const int wm = (wid >> 1) << 5;
  const int wn = (wid & 1) << 6;
  const int ar  = lane & 15;
  const int akh = (lane < 16) ? 0 : 8;
  const int bn  = (lane & 7) + ((lane & 16) ? 8 : 0);
  const int bkh = (lane & 8) ? 8 : 0;

  load_chunk(0, 0);
  for (int c = 0; c < nk; c++) {
    const int st = c & 1;
    if (c + 1 < nk) { load_chunk(c + 1, st ^ 1); CP_WAIT(1); }
    else CP_WAIT(0);
    __syncthreads();
    const unsigned stb = sb + (unsigned)st * 40960u;
    #pragma unroll
    for (int ks = 0; ks < 2; ks++) {
      const unsigned kb = (unsigned)(ks * 16) * 2u;
      unsigned ahf[2][4], alf[2][4];
      #pragma unroll
      for (int mi = 0; mi < 2; mi++) {
        unsigned rowA = (unsigned)((wm + mi * 16 + ar) * 80);
        ldsm4(ahf[mi], stb +          rowA + kb + akh * 2);
        ldsm4(alf[mi], stb + 10240u + rowA + kb + akh * 2);
      }
      #pragma unroll
      for (int nb = 0; nb < 4; nb++) {
        unsigned rowB = (unsigned)((wn + nb * 16 + bn) * 80);
        unsigned bhf[4], blf[4];
        ldsm4(bhf, stb + 20480u + rowB + kb + bkh * 2);
        ldsm4(blf, stb + 30720u + rowB + kb + bkh * 2);
        #pragma unroll
        for (int mi = 0; mi < 2; mi++) {
          #pragma unroll
          for (int half = 0; half < 2; half++) {
            float* d = acc[mi][nb * 2 + half];
            mma16816(d, ahf[mi], bhf[half * 2], bhf[half * 2 + 1]);
            mma16816(d, alf[mi], bhf[half * 2], bhf[half * 2 + 1]);
            mma16816(d, ahf[mi], blf[half * 2], blf[half * 2 + 1]);
          }
        }
      }
    }
    __syncthreads();
  }

  #pragma unroll
  for (int mi = 0; mi < 2; mi++) {
    const int lr0 = wm + mi * 16 + (lane >> 2);
    const int gr0 = m0 + lr0;
    const bool s0 = !grouped || (gr0 < count);
    const bool s1 = !grouped || (gr0 + 8 < count);
    const size_t row0 = (size_t)((grouped ? sbase : 0) + gr0);
    #pragma unroll
    for (int nt = 0; nt < 8; nt++) {
      const int col = n0 + wn + nt * 8 + ((lane & 3) << 1);
      float* d = acc[mi][nt];
      if (s0) *(float2*)(C + row0 * N + col)       = make_float2(d[0], d[1]);
      if (s1) *(float2*)(C + (row0 + 8) * N + col) = make_float2(d[2], d[3]);
    }
  }
}

// ---------------- RoPE + split into per-head bf16 hi/lo layouts ----------------
// grid (T, NH + 2*NKV), 64 threads. q -> g_q_*[h][t][d], k -> g_k_*, v (no rope) -> g_v_*
__global__ void rope_split_kernel(const float* __restrict__ qkv) {
  const int t = blockIdx.x, hh = blockIdx.y, i = threadIdx.x;
  if (hh < NH_ + NKV_) {
    const float* b;
    bf16 *dh, *dl;
    if (hh < NH_) {
      b = qkv + (size_t)t*QKVW_ + hh*HD_;
      size_t o = ((size_t)hh*T_ + t) * HD_;
      dh = g_q_h + o; dl = g_q_l + o;
    } else {
      int k = hh - NH_;
      b = qkv + (size_t)t*QKVW_ + NH_*HD_ + k*HD_;
      size_t o = ((size_t)k*T_ + t) * HD_;
      dh = g_k_h + o; dl = g_k_l + o;
    }
    float fr = powf(10000.f, -(float)(2*i) * (1.f/HD_));
    float ang = (float)t * fr;
    float sn, cs; sincosf(ang, &sn, &cs);
    float x1 = b[i], x2 = b[i+64];
    split_store1(x1*cs - x2*sn, dh + i,      dl + i);
    split_store1(x2*cs + x1*sn, dh + i + 64, dl + i + 64);
  } else {
    int v = hh - NH_ - NKV_;
    const float* b = qkv + (size_t)t*QKVW_ + (NH_+NKV_)*HD_ + v*HD_;
    size_t o = ((size_t)v*T_ + t) * HD_;
    split_store1(b[i],    g_v_h + o + i,      g_v_l + o + i);
    split_store1(b[i+64], g_v_h + o + i + 64, g_v_l + o + i + 64);
  }
}

// ---------------- mma.sync flash attention ----------------
// block = (head, q-tile of 128), 8 warps x 16 rows. BK=64. hi/lo split QK and PV.
#define AT_RS  272
#define AT_QSZ (128*AT_RS)
#define AT_TSZ (64*AT_RS)
#define AT_SMEM (2*AT_QSZ + 2*4*AT_TSZ)   // 208896
__global__ void __launch_bounds__(256) attn_mma(bf16* __restrict__ outh, bf16* __restrict__ outl) {
  extern __shared__ char smc[];
  const int h = blockIdx.x;
  const int q0 = ((int)gridDim.y - 1 - (int)blockIdx.y) << 7;   // heavy tiles first
  const int kvh = h >> 2;
  const int tid = threadIdx.x, wid = tid >> 5, lane = tid & 31;
  const unsigned sb = smem_u32(smc);
  const unsigned Ql_o = AT_QSZ, KV_o = 2*AT_QSZ;

  // load Q tile (128 rows x 128 bf16), hi+lo: 4096 cp16 -> 16/thread
  #pragma unroll
  for (int i = 0; i < 16; i++) {
    int s = tid + (i << 8);
    int mat = s >> 11, r = (s >> 4) & 127, cq = s & 15;
    unsigned dst = sb + (mat ? Ql_o : 0u) + (unsigned)(r * AT_RS + cq * 16);
    const bf16* src = (mat ? g_q_l : g_q_h) + (((size_t)h*T_ + q0 + r) << 7) + cq*8;
    cp16(dst, src, true);
  }
  CP_COMMIT();

  auto load_kv = [&](int c, int st) {
    unsigned base = sb + KV_o + (unsigned)st * (4*AT_TSZ);
    #pragma unroll
    for (int i = 0; i < 16; i++) {
      int s = tid + (i << 8);
      int mat = s >> 10, r = (s >> 4) & 63, cq = s & 15;
      unsigned dst = base + (unsigned)mat * AT_TSZ + (unsigned)(r * AT_RS + cq * 16);
      const bf16* ap = (mat == 0) ? g_k_h : (mat == 1) ? g_k_l : (mat == 2) ? g_v_h : g_v_l;
      cp16(dst, ap + (((size_t)kvh*T_ + c*64 + r) << 7) + cq*8, true);
    }
    CP_COMMIT();
  };

  const int wr0 = wid << 4;
  const int rlo = q0 + wr0 + (lane >> 2);          // this thread's low row
  float m0 = -1e30f, m1 = -1e30f, l0 = 0.f, l1 = 0.f;
  float o[16][4];
  #pragma unroll
  for (int i = 0; i < 16; i++)
    #pragma unroll
    for (int j = 0; j < 4; j++) o[i][j] = 0.f;

  const int ntl = (q0 >> 6) + 2;
  load_kv(0, 0);

  const int ar  = lane & 15;
  const int aco = (lane >> 4) << 4;                // A/V k-block byte offset (8 halves)
  const int bnr = (lane & 7) + ((lane & 16) ? 8 : 0);
  const int bko = (lane & 8) ? 16 : 0;
  const float sc = 0.12751744f;                    // (1/sqrt(128)) * log2(e)

  for (int c = 0; c < ntl; c++) {
    const int st = c & 1;
    if (c + 1 < ntl) { load_kv(c + 1, st ^ 1); CP_WAIT(1); }
    else CP_WAIT(0);
    __syncthreads();
    const int s0 = c << 6;
    const bool active = (s0 <= q0 + wr0 + 15);     // any unmasked col for this warp?
    if (active) {
      const unsigned kvb = sb + KV_o + (unsigned)st * (4*AT_TSZ);
      // ---- scores: S = Q K^T ----
      float s8[8][4];
      #pragma unroll
      for (int i = 0; i < 8; i++)
        #pragma unroll
        for (int j = 0; j < 4; j++) s8[i][j] = 0.f;
      #pragma unroll
      for (int kk = 0; kk < 8; kk++) {
        const unsigned qoff = (unsigned)((wr0 + ar) * AT_RS + kk * 32 + aco);
        unsigned ah[4], al[4];
        ldsm4(ah, sb + qoff);
        ldsm4(al, sb + Ql_o + qoff);
        #pragma unroll
        for (int ntp = 0; ntp < 4; ntp++) {
          const unsigned koff = (unsigned)((bnr + ntp * 16) * AT_RS + kk * 32 + bko);
          unsigned bh[4], bl[4];
          ldsm4(bh, kvb + koff);
          ldsm4(bl, kvb + AT_TSZ + koff);
          #pragma unroll
          for (int hf = 0; hf < 2; hf++) {
            float* d = s8[ntp * 2 + hf];
            mma16816(d, ah, bh[hf*2], bh[hf*2+1]);
            mma16816(d, al, bh[hf*2], bh[hf*2+1]);
            mma16816(d, ah, bl[hf*2], bl[hf*2+1]);
          }
        }
      }
      // ---- scale + causal mask ----
      #pragma unroll
      for (int nt = 0; nt < 8; nt++)
        #pragma unroll
        for (int j = 0; j < 4; j++) s8[nt][j] *= sc;
      if (s0 + 63 > q0 + wr0) {
        const int cb = s0 + ((lane & 3) << 1);
        #pragma unroll
        for (int nt = 0; nt < 8; nt++) {
          #pragma unroll
          for (int j = 0; j < 2; j++) {
            int col = cb + nt * 8 + j;
            if (col > rlo)     s8[nt][j]     = -1e30f;
            if (col > rlo + 8) s8[nt][j + 2] = -1e30f;
          }
        }
      }
      // ---- online softmax (base-2 domain) ----
      float tm0 = -1e30f, tm1 = -1e30f;
      #pragma unroll
      for (int nt = 0; nt < 8; nt++) {
        tm0 = fmaxf(tm0, fmaxf(s8[nt][0], s8[nt][1]));
        tm1 = fmaxf(tm1, fmaxf(s8[nt][2], s8[nt][3]));
      }
      tm0 = fmaxf(tm0, __shfl_xor_sync(0xffffffffu, tm0, 1));
      tm0 = fmaxf(tm0, __shfl_xor_sync(0xffffffffu, tm0, 2));
      tm1 = fmaxf(tm1, __shfl_xor_sync(0xffffffffu, tm1, 1));
      tm1 = fmaxf(tm1, __shfl_xor_sync(0xffffffffu, tm1, 2));
      const float mn0 = fmaxf(m0, tm0), mn1 = fmaxf(m1, tm1);
      const float aa0 = fexp2(m0 - mn0), aa1 = fexp2(m1 - mn1);
      m0 = mn0; m1 = mn1;
      float ts0 = 0.f, ts1 = 0.f;
      unsigned pH[4][4], pL[4][4];
      #pragma unroll
      for (int kc = 0; kc < 4; kc++) {
        float e00 = fexp2(s8[2*kc][0]   - m0), e01 = fexp2(s8[2*kc][1]   - m0);
        float e02 = fexp2(s8[2*kc][2]   - m1), e03 = fexp2(s8[2*kc][3]   - m1);
        float e10 = fexp2(s8[2*kc+1][0] - m0), e11 = fexp2(s8[2*kc+1][1] - m0);
        float e12 = fexp2(s8[2*kc+1][2] - m1), e13 = fexp2(s8[2*kc+1][3] - m1);
        ts0 += e00 + e01 + e10 + e11;
        ts1 += e02 + e03 + e12 + e13;
        // hi parts
        pH[kc][0] = pack_bf16(e00, e01);
        pH[kc][1] = pack_bf16(e02, e03);
        pH[kc][2] = pack_bf16(e10, e11);
        pH[kc][3] = pack_bf16(e12, e13);
        // lo parts
        __nv_bfloat162 h0 = *(__nv_bfloat162*)&pH[kc][0];
        __nv_bfloat162 h1 = *(__nv_bfloat162*)&pH[kc][1];
        __nv_bfloat162 h2 = *(__nv_bfloat162*)&pH[kc][2];
        __nv_bfloat162 h3 = *(__nv_bfloat162*)&pH[kc][3];
        pL[kc][0] = pack_bf16(e00 - __bfloat162float(h0.x), e01 - __bfloat162float(h0.y));
        pL[kc][1] = pack_bf16(e02 - __bfloat162float(h1.x), e03 - __bfloat162float(h1.y));
        pL[kc][2] = pack_bf16(e10 - __bfloat162float(h2.x), e11 - __bfloat162float(h2.y));
        pL[kc][3] = pack_bf16(e12 - __bfloat162float(h3.x), e13 - __bfloat162float(h3.y));
      }
      ts0 += __shfl_xor_sync(0xffffffffu, ts0, 1);
      ts0 += __shfl_xor_sync(0xffffffffu, ts0, 2);
      ts1 += __shfl_xor_sync(0xffffffffu, ts1, 1);
      ts1 += __shfl_xor_sync(0xffffffffu, ts1, 2);
      l0 = l0 * aa0 + ts0;
      l1 = l1 * aa1 + ts1;
      #pragma unroll
      for (int nt = 0; nt < 16; nt++) {
        o[nt][0] *= aa0; o[nt][1] *= aa0;
        o[nt][2] *= aa1; o[nt][3] *= aa1;
      }
      // ---- PV: O += P V (V via ldmatrix.trans) ----
      #pragma unroll
      for (int kc = 0; kc < 4; kc++) {
        #pragma unroll
        for (int ntp = 0; ntp < 8; ntp++) {
          const unsigned voff = (unsigned)((kc * 16 + ar) * AT_RS + ntp * 32 + aco);
          unsigned vh[4], vl[4];
          ldsm4t(vh, kvb + 2*AT_TSZ + voff);
          ldsm4t(vl, kvb + 3*AT_TSZ + voff);
          #pragma unroll
          for (int hf = 0; hf < 2; hf++) {
            float* d = o[ntp * 2 + hf];
            mma16816(d, pH[kc], vh[hf*2], vh[hf*2+1]);
            mma16816(d, pL[kc], vh[hf*2], vh[hf*2+1]);
            mma16816(d, pH[kc], vl[hf*2], vl[hf*2+1]);
          }
        }
      }
    }
    __syncthreads();
  }

  // ---- epilogue: normalize and split-store ----
  const float inv0 = 1.f / l0, inv1 = 1.f / l1;
  #pragma unroll
  for (int nt = 0; nt < 16; nt++) {
    const int col = h * HD_ + nt * 8 + ((lane & 3) << 1);
    size_t b0 = (size_t)rlo * H_ + col;
    size_t b1 = (size_t)(rlo + 8) * H_ + col;
    split_store2(o[nt][0] * inv0, o[nt][1] * inv0, outh + b0, outl + b0);
    split_store2(o[nt][2] * inv1, o[nt][3] * inv1, outh + b1, outl + b1);
  }
}

// ---------------- elementwise ----------------
__global__ void add_kernel(const float* __restrict__ a, const float* __restrict__ b,
                           float* __restrict__ c) {
  int i = blockIdx.x*256 + threadIdx.x;
  float4 va = ((const float4*)a)[i], vb = ((const float4*)b)[i];
  ((float4*)c)[i] = make_float4(va.x+vb.x, va.y+vb.y, va.z+vb.z, va.w+vb.w);
}

__device__ __forceinline__ float siluf(float g){ return g / (1.f + expf(-g)); }

__global__ void silu_resmlp_kernel() {
  int idx = blockIdx.x*256 + threadIdx.x;
  int t = idx >> 9;
  int jq = idx & 511;
  const float4* gp = (const float4*)(g_gu + (size_t)t*2*H_);
  float4 g4 = gp[jq], u4 = gp[jq + 512];
  float4 o = make_float4(siluf(g4.x)*u4.x, siluf(g4.y)*u4.y, siluf(g4.z)*u4.z, siluf(g4.w)*u4.w);
  size_t b = (size_t)t*H_ + jq*4;
  split_store4(o, g_hmid_h + b, g_hmid_l + b);
}

__global__ void silu_moe_kernel() {
  int idx = blockIdx.x*256 + threadIdx.x;
  int p = idx >> 8;
  int jq = idx & 255;
  const float4* gp = (const float4*)(g_gum + (size_t)p*2*I_);
  float4 g4 = gp[jq], u4 = gp[jq + 256];
  float4 o = make_float4(siluf(g4.x)*u4.x, siluf(g4.y)*u4.y, siluf(g4.z)*u4.z, siluf(g4.w)*u4.w);
  size_t b = (size_t)p*I_ + jq*4;
  split_store4(o, g_hmm_h + b, g_hmm_l + b);
}

// ---------------- gating + routing ----------------
__global__ void __launch_bounds__(256) gate_kernel(const float* __restrict__ gw) {
  const int t = blockIdx.x;
  __shared__ float part[256];
  const int tid = threadIdx.x;
  const int e = tid & 15, c = tid >> 4;
  const bf16* xh = g_h3n_h + (size_t)t*H_;
  const bf16* xl = g_h3n_l + (size_t)t*H_;
  float s = 0.f;
  for (int h = c*128; h < c*128+128; h++)
    s += (__bfloat162float(xh[h]) + __bfloat162float(xl[h])) * gw[h*E_ + e];
  part[tid] = s;
  __syncthreads();
  if (tid == 0) {
    float lg[16];
    for (int ee=0; ee<16; ee++){ float v=0.f; for (int cc=0; cc<16; cc++) v += part[cc*16+ee]; lg[ee]=v; }
    int i1 = 0;
    for (int ee=1; ee<16; ee++) if (lg[ee] > lg[i1]) i1 = ee;
    int i2 = (i1==0) ? 1 : 0;
    for (int ee=0; ee<16; ee++) if (ee!=i1 && lg[ee] > lg[i2]) i2 = ee;
    float mx = lg[i1];
    float p1 = expf(lg[i1]-mx), p2 = expf(lg[i2]-mx);
    float d = p1 + p2;
    g_topi[t*2]=i1; g_topi[t*2+1]=i2;
    g_topw[t*2]=p1/d; g_topw[t*2+1]=p2/d;
  }
}

__global__ void moe_zero_kernel(){ if (threadIdx.x < E_){ g_cnt[threadIdx.x]=0; g_cur[threadIdx.x]=0; } }
__global__ void moe_count_kernel(){ int i = blockIdx.x*256+threadIdx.x; if (i < P_) atomicAdd(&g_cnt[g_topi[i]], 1); }
__global__ void moe_scan_kernel(){ if (threadIdx.x==0){ int o=0; for (int e=0;e<E_;e++){ g_off[e]=o; o+=g_cnt[e]; } } }
__global__ void moe_scatter_kernel(){
  int i = blockIdx.x*256+threadIdx.x;
  if (i < P_) {
    int e = g_topi[i];
    int pos = g_off[e] + atomicAdd(&g_cur[e], 1);
    g_ptok[pos] = i >> 1;
    g_pslot[i]  = pos;
  }
}

// ---------------- final combine ----------------
__global__ void final_kernel(float* __restrict__ out) {
  const int t = blockIdx.x;
  const int p0 = g_pslot[t*2], p1 = g_pslot[t*2+1];
  const float w0 = g_topw[t*2], w1 = g_topw[t*2+1];
  const float4* ra = (const float4*)(g_resat + (size_t)t*H_);
  const float4* ml = (const float4*)(g_mlp   + (size_t)t*H_);
  const float4* y0 = (const float4*)(g_ym    + (size_t)p0*H_);
  const float4* y1 = (const float4*)(g_ym    + (size_t)p1*H_);
  float4* op = (float4*)(out + (size_t)t*H_);
  for (int i = threadIdx.x; i < 512; i += 256) {
    float4 A=ra[i], B=ml[i], C=y0[i], D=y1[i];
    op[i] = make_float4(A.x+B.x+w0*C.x+w1*D.x, A.y+B.y+w0*C.y+w1*D.y,
                        A.z+B.z+w0*C.z+w1*D.z, A.w+B.w+w0*C.w+w1*D.w);
  }
}

// ---------------- host ----------------
extern "C" void kernel_launch(void* const* d_in, const int* in_sizes, int n_in,
                              void* d_out, int out_size) {
  (void)in_sizes; (void)n_in; (void)out_size;
  const float* x      = (const float*)d_in[0];
  const float* ln_in  = (const float*)d_in[1];
  const float* ln_post= (const float*)d_in[2];
  const float* ln_res = (const float*)d_in[3];
  const float* wqkv   = (const float*)d_in[4];
  const float* wo     = (const float*)d_in[5];
  const float* w13    = (const float*)d_in[6];
  const float* w2     = (const float*)d_in[7];
  const float* gw     = (const float*)d_in[8];
  const float* ws     = (const float*)d_in[9];
  const float* w2s    = (const float*)d_in[10];
  float* out = (float*)d_out;

  float *qkv,*aproj,*resat,*gu,*mlp,*gum,*ym;
  cudaGetSymbolAddress((void**)&qkv,  g_qkv);
  cudaGetSymbolAddress((void**)&aproj,g_aproj);
  cudaGetSymbolAddress((void**)&resat,g_resat);
  cudaGetSymbolAddress((void**)&gu,   g_gu);
  cudaGetSymbolAddress((void**)&mlp,  g_mlp);
  cudaGetSymbolAddress((void**)&gum,  g_gum);
  cudaGetSymbolAddress((void**)&ym,   g_ym);

  bf16 *xnh,*xnl,*ath,*atl,*h2h,*h2l,*hmh,*hml,*h3h,*h3l,*hmmh,*hmml;
  cudaGetSymbolAddress((void**)&xnh, g_xn_h);   cudaGetSymbolAddress((void**)&xnl, g_xn_l);
  cudaGetSymbolAddress((void**)&ath, g_attn_h); cudaGetSymbolAddress((void**)&atl, g_attn_l);
  cudaGetSymbolAddress((void**)&h2h, g_h2n_h);  cudaGetSymbolAddress((void**)&h2l, g_h2n_l);
  cudaGetSymbolAddress((void**)&hmh, g_hmid_h); cudaGetSymbolAddress((void**)&hml, g_hmid_l);
  cudaGetSymbolAddress((void**)&h3h, g_h3n_h);  cudaGetSymbolAddress((void**)&h3l, g_h3n_l);
  cudaGetSymbolAddress((void**)&hmmh,g_hmm_h);  cudaGetSymbolAddress((void**)&hmml,g_hmm_l);

  bf16 *wqh,*wql,*woh,*wol,*w13h,*w13l,*w2h,*w2l,*wsh,*wsl,*w2sh,*w2sl;
  cudaGetSymbolAddress((void**)&wqh, g_wqkvT_h); cudaGetSymbolAddress((void**)&wql, g_wqkvT_l);
  cudaGetSymbolAddress((void**)&woh, g_woT_h);   cudaGetSymbolAddress((void**)&wol, g_woT_l);
  cudaGetSymbolAddress((void**)&w13h,g_w13T_h);  cudaGetSymbolAddress((void**)&w13l,g_w13T_l);
  cudaGetSymbolAddress((void**)&w2h, g_w2T_h);   cudaGetSymbolAddress((void**)&w2l, g_w2T_l);
  cudaGetSymbolAddress((void**)&wsh, g_ws_h);    cudaGetSymbolAddress((void**)&wsl, g_ws_l);
  cudaGetSymbolAddress((void**)&w2sh,g_w2s_h);   cudaGetSymbolAddress((void**)&w2sl,g_w2s_l);

  cudaFuncSetAttribute(mma_gemm, cudaFuncAttributeMaxDynamicSharedMemorySize, MMA_SMEM);
  cudaFuncSetAttribute(attn_mma, cudaFuncAttributeMaxDynamicSharedMemorySize, AT_SMEM);

  // ---- weight prep ----
  transpose_split<<<dim3(QKVW_/32, H_/32), 256>>>(wqkv, wqh, wql, H_, QKVW_);
  transpose_split<<<dim3(H_/32,    H_/32), 256>>>(wo,   woh, wol, H_, H_);
  transpose_split<<<dim3(2*H_/32,  H_/32), 256>>>(w13,  w13h,w13l,H_, 2*H_);
  transpose_split<<<dim3(H_/32,    H_/32), 256>>>(w2,   w2h, w2l, H_, H_);
  convert_split<<<(E_*2*I_*H_)/1024, 256>>>(ws,  wsh,  wsl);
  convert_split<<<(E_*H_*I_)/1024,   256>>>(w2s, w2sh, w2sl);

  // ---- attention branch ----
  rmsnorm_split<<<T_, 256>>>(x, ln_in, xnh, xnl);
  mma_gemm<<<dim3(QKVW_/128, T_/128, 1), 256, MMA_SMEM>>>(xnh, xnl, wqh, wql, qkv, QKVW_, H_, 0);
  rope_split_kernel<<<dim3(T_, NH_ + 2*NKV_), 64>>>(qkv);
  attn_mma<<<dim3(NH_, T_/128), 256, AT_SMEM>>>(ath, atl);
  mma_gemm<<<dim3(H_/128, T_/128, 1), 256, MMA_SMEM>>>(ath, atl, woh, wol, aproj, H_, H_, 0);
  add_kernel<<<(T_*H_)/1024, 256>>>(x, aproj, resat);

  // ---- residual MLP branch ----
  rmsnorm_split<<<T_, 256>>>(resat, ln_res, h2h, h2l);
  mma_gemm<<<dim3(2*H_/128, T_/128, 1), 256, MMA_SMEM>>>(h2h, h2l, w13h, w13l, gu, 2*H_, H_, 0);
  silu_resmlp_kernel<<<(T_*H_)/1024, 256>>>();
  mma_gemm<<<dim3(H_/128, T_/128, 1), 256, MMA_SMEM>>>(hmh, hml, w2h, w2l, mlp, H_, H_, 0);

  // ---- MoE branch ----
  rmsnorm_split<<<T_, 256>>>(x, ln_post, h3h, h3l);
  gate_kernel<<<T_, 256>>>(gw);
  moe_zero_kernel<<<1, 32>>>();
  moe_count_kernel<<<P_/256, 256>>>();
  moe_scan_kernel<<<1, 32>>>();
  moe_scatter_kernel<<<P_/256, 256>>>();
  mma_gemm<<<dim3(2*I_/128, T_/128, E_), 256, MMA_SMEM>>>(h3h, h3l, wsh, wsl, gum, 2*I_, H_, 1);
  silu_moe_kernel<<<(P_*I_)/1024, 256>>>();
  mma_gemm<<<dim3(H_/128, T_/128, E_), 256, MMA_SMEM>>>(hmmh, hmml, w2sh, w2sl, ym, H_, I_, 2);

  // ---- combine ----
  final_kernel<<<T_, 256>>>(out);
}

// round 9
// speedup vs baseline: 2.5745x; 1.0139x over previous
#include <cuda_runtime.h>
#include <cuda_bf16.h>
#include <math.h>

#define T_ 2048
#define H_ 2048
#define NH_ 16
#define NKV_ 4
#define HD_ 128
#define I_ 1024
#define E_ 16
#define TOPK_ 2
#define P_ (T_*TOPK_)
#define QKVW_ 3072

typedef __nv_bfloat16 bf16;

// ---------------- scratch (device globals; no allocations allowed) ----------------
__device__ float g_qkv[T_*QKVW_];
__device__ float g_aproj[T_*H_];
__device__ float g_resat[T_*H_];
__device__ float g_gu[T_*2*H_];
__device__ float g_mlp[T_*H_];
__device__ float g_gum[P_*2*I_];
__device__ float g_ym[P_*H_];

__device__ bf16 g_xn_h[T_*H_],   g_xn_l[T_*H_];
__device__ bf16 g_attn_h[T_*H_], g_attn_l[T_*H_];
__device__ bf16 g_h2n_h[T_*H_],  g_h2n_l[T_*H_];
__device__ bf16 g_hmid_h[T_*H_], g_hmid_l[T_*H_];
__device__ bf16 g_h3n_h[T_*H_],  g_h3n_l[T_*H_];
__device__ bf16 g_hmm_h[P_*I_],  g_hmm_l[P_*I_];

__device__ bf16 g_q_h[NH_*T_*HD_],  g_q_l[NH_*T_*HD_];
__device__ bf16 g_k_h[NKV_*T_*HD_], g_k_l[NKV_*T_*HD_];
__device__ bf16 g_v_h[NKV_*T_*HD_], g_v_l[NKV_*T_*HD_];

__device__ bf16 g_wqkvT_h[QKVW_*H_], g_wqkvT_l[QKVW_*H_];
__device__ bf16 g_woT_h[H_*H_],      g_woT_l[H_*H_];
__device__ bf16 g_w13T_h[2*H_*H_],   g_w13T_l[2*H_*H_];
__device__ bf16 g_w2T_h[H_*H_],      g_w2T_l[H_*H_];
__device__ bf16 g_ws_h[E_*2*I_*H_],  g_ws_l[E_*2*I_*H_];
__device__ bf16 g_w2s_h[E_*H_*I_],   g_w2s_l[E_*H_*I_];

__device__ int   g_topi[P_];
__device__ float g_topw[P_];
__device__ int   g_cnt[E_];
__device__ int   g_off[E_];
__device__ int   g_cur[E_];
__device__ int   g_ptok[P_];
__device__ int   g_pslot[P_];

// ---------------- ptx helpers (base compute_103-safe) ----------------
__device__ __forceinline__ unsigned smem_u32(const void* p) {
  unsigned a;
  asm("{ .reg .u64 t; cvta.to.shared.u64 t, %1; cvt.u32.u64 %0, t; }" : "=r"(a) : "l"(p));
  return a;
}
__device__ __forceinline__ void cp16(unsigned dst, const void* src, bool valid) {
  int sz = valid ? 16 : 0;
  asm volatile("cp.async.cg.shared.global [%0], [%1], 16, %2;"
               :: "r"(dst), "l"(src), "r"(sz) : "memory");
}
#define CP_COMMIT() asm volatile("cp.async.commit_group;" ::: "memory")
#define CP_WAIT(n)  asm volatile("cp.async.wait_group %0;" :: "n"(n) : "memory")

__device__ __forceinline__ void ldsm4(unsigned* r, unsigned addr) {
  asm volatile("ldmatrix.sync.aligned.m8n8.x4.shared.b16 {%0,%1,%2,%3}, [%4];"
               : "=r"(r[0]), "=r"(r[1]), "=r"(r[2]), "=r"(r[3]) : "r"(addr));
}
__device__ __forceinline__ void ldsm4t(unsigned* r, unsigned addr) {
  asm volatile("ldmatrix.sync.aligned.m8n8.x4.trans.shared.b16 {%0,%1,%2,%3}, [%4];"
               : "=r"(r[0]), "=r"(r[1]), "=r"(r[2]), "=r"(r[3]) : "r"(addr));
}
__device__ __forceinline__ void mma16816(float* d, const unsigned* a, unsigned b0, unsigned b1) {
  asm volatile("mma.sync.aligned.m16n8k16.row.col.f32.bf16.bf16.f32 "
               "{%0,%1,%2,%3}, {%4,%5,%6,%7}, {%8,%9}, {%0,%1,%2,%3};"
               : "+f"(d[0]), "+f"(d[1]), "+f"(d[2]), "+f"(d[3])
               : "r"(a[0]), "r"(a[1]), "r"(a[2]), "r"(a[3]), "r"(b0), "r"(b1));
}

// fast 2^y on the FMA pipe (y in [-1e30, 0]); rel err < 3e-6
__device__ __forceinline__ float fexp2(float y) {
  y = fmaxf(y, -120.f);
  float z = y + 12582912.0f;                 // round-to-nearest-int via magic
  int   n = __float_as_int(z) - 0x4B400000;
  float f = y - (z - 12582912.0f);           // f in [-0.5, 0.5]
  float p = 0.0013333558f;
  p = fmaf(p, f, 0.0096181291f);
  p = fmaf(p, f, 0.0555041087f);
  p = fmaf(p, f, 0.2402265069f);
  p = fmaf(p, f, 0.6931471806f);
  p = fmaf(p, f, 1.0f);
  return p * __int_as_float((n + 127) << 23);
}

// ---------------- bf16 split helpers ----------------
__device__ __forceinline__ unsigned pack_bf16(float a, float b) {
  __nv_bfloat162 t = __floats2bfloat162_rn(a, b);
  return *(unsigned*)&t;
}
__device__ __forceinline__ void split_store4(float4 v, bf16* ph, bf16* pl) {
  float a[4] = {v.x, v.y, v.z, v.w};
  bf16 h[4], l[4];
  #pragma unroll
  for (int i = 0; i < 4; i++) {
    h[i] = __float2bfloat16_rn(a[i]);
    l[i] = __float2bfloat16_rn(a[i] - __bfloat162float(h[i]));
  }
  *(uint2*)ph = *(uint2*)h;
  *(uint2*)pl = *(uint2*)l;
}
__device__ __forceinline__ void split_store2(float a, float b, bf16* ph, bf16* pl) {
  unsigned hi = pack_bf16(a, b);
  __nv_bfloat162 hb = *(__nv_bfloat162*)&hi;
  unsigned lo = pack_bf16(a - __bfloat162float(hb.x), b - __bfloat162float(hb.y));
  *(unsigned*)ph = hi;
  *(unsigned*)pl = lo;
}
__device__ __forceinline__ void split_store1(float a, bf16* ph, bf16* pl) {
  bf16 h = __float2bfloat16_rn(a);
  *ph = h;
  *pl = __float2bfloat16_rn(a - __bfloat162float(h));
}

// ---------------- weight prep ----------------
__global__ void __launch_bounds__(256) convert_split(const float* __restrict__ in,
                                                     bf16* __restrict__ oh, bf16* __restrict__ ol) {
  size_t i = (size_t)blockIdx.x * 256 + threadIdx.x;
  float4 v = ((const float4*)in)[i];
  split_store4(v, oh + i * 4, ol + i * 4);
}

__global__ void __launch_bounds__(256) transpose_split(const float* __restrict__ in,
                                                       bf16* __restrict__ oh, bf16* __restrict__ ol,
                                                       int K, int N) {
  __shared__ float t[32][33];
  int k0 = blockIdx.y * 32, n0 = blockIdx.x * 32;
  int tx = threadIdx.x & 31, ty = threadIdx.x >> 5;
  #pragma unroll
  for (int j = 0; j < 4; j++)
    t[ty + 8 * j][tx] = in[(size_t)(k0 + ty + 8 * j) * N + n0 + tx];
  __syncthreads();
  #pragma unroll
  for (int j = 0; j < 4; j++) {
    float v = t[tx][ty + 8 * j];
    bf16 h = __float2bfloat16_rn(v);
    bf16 l = __float2bfloat16_rn(v - __bfloat162float(h));
    size_t o = (size_t)(n0 + ty + 8 * j) * K + k0 + tx;
    oh[o] = h; ol[o] = l;
  }
}

// ---------------- RMSNorm: one block per token, emits hi/lo bf16 ----------------
__global__ void __launch_bounds__(256) rmsnorm_split(const float* __restrict__ x,
                                                     const float* __restrict__ w,
                                                     bf16* __restrict__ oh, bf16* __restrict__ ol) {
  const int t = blockIdx.x;
  const float4* xr = (const float4*)(x + (size_t)t * H_);
  const float4* wr = (const float4*)w;
  const int i0 = threadIdx.x, i1 = threadIdx.x + 256;
  float4 v0 = xr[i0], v1 = xr[i1];
  float s = v0.x*v0.x+v0.y*v0.y+v0.z*v0.z+v0.w*v0.w
          + v1.x*v1.x+v1.y*v1.y+v1.z*v1.z+v1.w*v1.w;
  #pragma unroll
  for (int off = 16; off; off >>= 1) s += __shfl_xor_sync(0xffffffffu, s, off);
  __shared__ float red[8];
  __shared__ float sinv;
  if ((threadIdx.x & 31) == 0) red[threadIdx.x >> 5] = s;
  __syncthreads();
  if (threadIdx.x == 0) {
    float tt = 0.f;
    #pragma unroll
    for (int k = 0; k < 8; k++) tt += red[k];
    sinv = rsqrtf(tt * (1.f / H_) + 1e-5f);
  }
  __syncthreads();
  float r = sinv;
  float4 w0 = wr[i0], w1 = wr[i1];
  float4 o0, o1;
  o0.x=v0.x*r*w0.x; o0.y=v0.y*r*w0.y; o0.z=v0.z*r*w0.z; o0.w=v0.w*r*w0.w;
  o1.x=v1.x*r*w1.x; o1.y=v1.y*r*w1.y; o1.z=v1.z*r*w1.z; o1.w=v1.w*r*w1.w;
  size_t base = (size_t)t * H_;
  split_store4(o0, oh + base + i0 * 4, ol + base + i0 * 4);
  split_store4(o1, oh + base + i1 * 4, ol + base + i1 * 4);
}

// ---------------- mma.sync split-bf16 GEMM ----------------
// D[row, n] = sum_k A[row,k]*B[n,k], fp32 out. A,B hi/lo bf16, K-major.
// CTA tile 128x256, 8 warps (2m x 4n), warp tile 64x64, K-chunk 32, 3-stage cp.async.
// stage: Ah[128x80B] Al Bh[256x80B] Bl = 61440B; 3 stages + rowmap.
#define MMA_STG 61440
#define MMA_SMEM (3*MMA_STG + 512)
__global__ void __launch_bounds__(256) mma_gemm(const bf16* __restrict__ Ah, const bf16* __restrict__ Al,
                                                const bf16* __restrict__ Bh, const bf16* __restrict__ Bl,
                                                float* __restrict__ C, int N, int K, int grouped) {
  extern __shared__ char smem[];
  const int tid = threadIdx.x, wid = tid >> 5, lane = tid & 31;
  const int e = blockIdx.z;
  int count = 0, sbase = 0;
  if (grouped) {
    count = g_cnt[e];
    if ((int)(blockIdx.y << 7) >= count) return;
    sbase = g_off[e];
  }
  const bf16* BhE = Bh + (size_t)e * N * K;
  const bf16* BlE = Bl + (size_t)e * N * K;
  const int m0 = blockIdx.y << 7, n0 = blockIdx.x << 8;
  unsigned sb = smem_u32(smem);
  int* rowmap = (int*)(smem + 3*MMA_STG);

  if (tid < 128) {
    int gr = m0 + tid;
    if (grouped) {
      if (m0 + tid < count) {
        int slot = sbase + m0 + tid;
        gr = (grouped == 1) ? g_ptok[slot] : slot;
      } else gr = -1;
    }
    rowmap[tid] = gr;
  }
  __syncthreads();

  const int nk = K >> 5;
  auto load_chunk = [&](int c, int st) {
    unsigned base = sb + (unsigned)st * MMA_STG;
    #pragma unroll
    for (int i = 0; i < 4; i++) {              // A hi/lo: 1024 cp16
      int s = tid + (i << 8);
      int mat = s >> 9, r = (s >> 2) & 127, cq = s & 3;
      unsigned dst = base + (unsigned)mat * 10240u + (unsigned)(r * 80 + cq * 16);
      int gr = rowmap[r];
      bool valid = (gr >= 0);
      if (!valid) gr = 0;
      const bf16* src = (mat ? Al : Ah) + (size_t)gr * K + (c << 5) + (cq << 3);
      cp16(dst, src, valid);
    }
    #pragma unroll
    for (int i = 0; i < 8; i++) {              // B hi/lo: 2048 cp16
      int u = tid + (i << 8);
      int mat = u >> 10, r = (u >> 2) & 255, cq = u & 3;
      unsigned dst = base + 20480u + (unsigned)mat * 20480u + (unsigned)(r * 80 + cq * 16);
      const bf16* src = (mat ? BlE : BhE) + (size_t)(n0 + r) * K + (c << 5) + (cq << 3);
      cp16(dst, src, true);
    }
    CP_COMMIT();
  };

  float acc[4][8][4];
  #pragma unroll
  for (int i = 0; i < 4; i++)
    #pragma unroll
    for (int j = 0; j < 8; j++)
      #pragma unroll
      for (int k = 0; k < 4; k++) acc[i][j][k] = 0.f;

  const int wm = (wid >> 2) << 6;           // 0 or 64
  const int wn = (wid & 3) << 6;            // 0,64,128,192
  const int ar  = lane & 15;
  const unsigned aco = (lane & 16) ? 16u : 0u;
  const int bn  = (lane & 7) + ((lane & 16) ? 8 : 0);
  const unsigned bko = (lane & 8) ? 16u : 0u;

  load_chunk(0, 0);
  if (nk > 1) load_chunk(1, 1);
  for (int c = 0; c < nk; c++) {
    const int st = c - (c / 3) * 3;
    if (c + 1 < nk) CP_WAIT(1); else CP_WAIT(0);
    __syncthreads();
    if (c + 2 < nk) load_chunk(c + 2, (c + 2) - ((c + 2) / 3) * 3);
    const unsigned stb = sb + (unsigned)st * MMA_STG;
    #pragma unroll
    for (int ks = 0; ks < 2; ks++) {
      const unsigned kb = (unsigned)(ks << 5);
      unsigned ahf[4][4], alf[4][4];
      #pragma unroll
      for (int mi = 0; mi < 4; mi++) {
        unsigned rowA = (unsigned)((wm + mi * 16 + ar) * 80);
        ldsm4(ahf[mi], stb +          rowA + kb + aco);
        ldsm4(alf[mi], stb + 10240u + rowA + kb + aco);
      }
      #pragma unroll
      for (int nb = 0; nb < 4; nb++) {
        unsigned rowB = (unsigned)((wn + nb * 16 + bn) * 80);
        unsigned bhf[4], blf[4];
        ldsm4(bhf, stb + 20480u + rowB + kb + bko);
        ldsm4(blf, stb + 40960u + rowB + kb + bko);
        #pragma unroll
        for (int mi = 0; mi < 4; mi++) {
          #pragma unroll
          for (int half = 0; half < 2; half++) {
            float* d = acc[mi][nb * 2 + half];
            mma16816(d, ahf[mi], bhf[half * 2], bhf[half * 2 + 1]);
            mma16816(d, alf[mi], bhf[half * 2], bhf[half * 2 + 1]);
            mma16816(d, ahf[mi], blf[half * 2], blf[half * 2 + 1]);
          }
        }
      }
    }
    __syncthreads();
  }

  #pragma unroll
  for (int mi = 0; mi < 4; mi++) {
    const int lr0 = wm + mi * 16 + (lane >> 2);
    const int gr0 = m0 + lr0;
    const bool s0 = !grouped || (gr0 < count);
    const bool s1 = !grouped || (gr0 + 8 < count);
    const size_t row0 = (size_t)((grouped ? sbase : 0) + gr0);
    #pragma unroll
    for (int nt = 0; nt < 8; nt++) {
      const int col = n0 + wn + nt * 8 + ((lane & 3) << 1);
      float* d = acc[mi][nt];
      if (s0) *(float2*)(C + row0 * N + col)       = make_float2(d[0], d[1]);
      if (s1) *(float2*)(C + (row0 + 8) * N + col) = make_float2(d[2], d[3]);
    }
  }
}

// ---------------- RoPE + split into per-head bf16 hi/lo layouts ----------------
__global__ void rope_split_kernel(const float* __restrict__ qkv) {
  const int t = blockIdx.x, hh = blockIdx.y, i = threadIdx.x;
  if (hh < NH_ + NKV_) {
    const float* b;
    bf16 *dh, *dl;
    if (hh < NH_) {
      b = qkv + (size_t)t*QKVW_ + hh*HD_;
      size_t o = ((size_t)hh*T_ + t) * HD_;
      dh = g_q_h + o; dl = g_q_l + o;
    } else {
      int k = hh - NH_;
      b = qkv + (size_t)t*QKVW_ + NH_*HD_ + k*HD_;
      size_t o = ((size_t)k*T_ + t) * HD_;
      dh = g_k_h + o; dl = g_k_l + o;
    }
    float fr = powf(10000.f, -(float)(2*i) * (1.f/HD_));
    float ang = (float)t * fr;
    float sn, cs; sincosf(ang, &sn, &cs);
    float x1 = b[i], x2 = b[i+64];
    split_store1(x1*cs - x2*sn, dh + i,      dl + i);
    split_store1(x2*cs + x1*sn, dh + i + 64, dl + i + 64);
  } else {
    int v = hh - NH_ - NKV_;
    const float* b = qkv + (size_t)t*QKVW_ + (NH_+NKV_)*HD_ + v*HD_;
    size_t o = ((size_t)v*T_ + t) * HD_;
    split_store1(b[i],    g_v_h + o + i,      g_v_l + o + i);
    split_store1(b[i+64], g_v_h + o + i + 64, g_v_l + o + i + 64);
  }
}

// ---------------- mma.sync flash attention (unchanged from R8) ----------------
#define AT_RS  272
#define AT_QSZ (128*AT_RS)
#define AT_TSZ (64*AT_RS)
#define AT_SMEM (2*AT_QSZ + 2*4*AT_TSZ)   // 208896
__global__ void __launch_bounds__(256) attn_mma(bf16* __restrict__ outh, bf16* __restrict__ outl) {
  extern __shared__ char smc[];
  const int h = blockIdx.x;
  const int q0 = ((int)gridDim.y - 1 - (int)blockIdx.y) << 7;   // heavy tiles first
  const int kvh = h >> 2;
  const int tid = threadIdx.x, wid = tid >> 5, lane = tid & 31;
  const unsigned sb = smem_u32(smc);
  const unsigned Ql_o = AT_QSZ, KV_o = 2*AT_QSZ;

  #pragma unroll
  for (int i = 0; i < 16; i++) {
    int s = tid + (i << 8);
    int mat = s >> 11, r = (s >> 4) & 127, cq = s & 15;
    unsigned dst = sb + (mat ? Ql_o : 0u) + (unsigned)(r * AT_RS + cq * 16);
    const bf16* src = (mat ? g_q_l : g_q_h) + (((size_t)h*T_ + q0 + r) << 7) + cq*8;
    cp16(dst, src, true);
  }
  CP_COMMIT();

  auto load_kv = [&](int c, int st) {
    unsigned base = sb + KV_o + (unsigned)st * (4*AT_TSZ);
    #pragma unroll
    for (int i = 0; i < 16; i++) {
      int s = tid + (i << 8);
      int mat = s >> 10, r = (s >> 4) & 63, cq = s & 15;
      unsigned dst = base + (unsigned)mat * AT_TSZ + (unsigned)(r * AT_RS + cq * 16);
      const bf16* ap = (mat == 0) ? g_k_h : (mat == 1) ? g_k_l : (mat == 2) ? g_v_h : g_v_l;
      cp16(dst, ap + (((size_t)kvh*T_ + c*64 + r) << 7) + cq*8, true);
    }
    CP_COMMIT();
  };

  const int wr0 = wid << 4;
  const int rlo = q0 + wr0 + (lane >> 2);
  float m0 = -1e30f, m1 = -1e30f, l0 = 0.f, l1 = 0.f;
  float o[16][4];
  #pragma unroll
  for (int i = 0; i < 16; i++)
    #pragma unroll
    for (int j = 0; j < 4; j++) o[i][j] = 0.f;

  const int ntl = (q0 >> 6) + 2;
  load_kv(0, 0);

  const int ar  = lane & 15;
  const int aco = (lane >> 4) << 4;
  const int bnr = (lane & 7) + ((lane & 16) ? 8 : 0);
  const int bko = (lane & 8) ? 16 : 0;
  const float sc = 0.12751744f;                    // (1/sqrt(128)) * log2(e)

  for (int c = 0; c < ntl; c++) {
    const int st = c & 1;
    if (c + 1 < ntl) { load_kv(c + 1, st ^ 1); CP_WAIT(1); }
    else CP_WAIT(0);
    __syncthreads();
    const int s0 = c << 6;
    const bool active = (s0 <= q0 + wr0 + 15);
    if (active) {
      const unsigned kvb = sb + KV_o + (unsigned)st * (4*AT_TSZ);
      float s8[8][4];
      #pragma unroll
      for (int i = 0; i < 8; i++)
        #pragma unroll
        for (int j = 0; j < 4; j++) s8[i][j] = 0.f;
      #pragma unroll
      for (int kk = 0; kk < 8; kk++) {
        const unsigned qoff = (unsigned)((wr0 + ar) * AT_RS + kk * 32 + aco);
        unsigned ah[4], al[4];
        ldsm4(ah, sb + qoff);
        ldsm4(al, sb + Ql_o + qoff);
        #pragma unroll
        for (int ntp = 0; ntp < 4; ntp++) {
          const unsigned koff = (unsigned)((bnr + ntp * 16) * AT_RS + kk * 32 + bko);
          unsigned bh[4], bl[4];
          ldsm4(bh, kvb + koff);
          ldsm4(bl, kvb + AT_TSZ + koff);
          #pragma unroll
          for (int hf = 0; hf < 2; hf++) {
            float* d = s8[ntp * 2 + hf];
            mma16816(d, ah, bh[hf*2], bh[hf*2+1]);
            mma16816(d, al, bh[hf*2], bh[hf*2+1]);
            mma16816(d, ah, bl[hf*2], bl[hf*2+1]);
          }
        }
      }
      #pragma unroll
      for (int nt = 0; nt < 8; nt++)
        #pragma unroll
        for (int j = 0; j < 4; j++) s8[nt][j] *= sc;
      if (s0 + 63 > q0 + wr0) {
        const int cb = s0 + ((lane & 3) << 1);
        #pragma unroll
        for (int nt = 0; nt < 8; nt++) {
          #pragma unroll
          for (int j = 0; j < 2; j++) {
            int col = cb + nt * 8 + j;
            if (col > rlo)     s8[nt][j]     = -1e30f;
            if (col > rlo + 8) s8[nt][j + 2] = -1e30f;
          }
        }
      }
      float tm0 = -1e30f, tm1 = -1e30f;
      #pragma unroll
      for (int nt = 0; nt < 8; nt++) {
        tm0 = fmaxf(tm0, fmaxf(s8[nt][0], s8[nt][1]));
        tm1 = fmaxf(tm1, fmaxf(s8[nt][2], s8[nt][3]));
      }
      tm0 = fmaxf(tm0, __shfl_xor_sync(0xffffffffu, tm0, 1));
      tm0 = fmaxf(tm0, __shfl_xor_sync(0xffffffffu, tm0, 2));
      tm1 = fmaxf(tm1, __shfl_xor_sync(0xffffffffu, tm1, 1));
      tm1 = fmaxf(tm1, __shfl_xor_sync(0xffffffffu, tm1, 2));
      const float mn0 = fmaxf(m0, tm0), mn1 = fmaxf(m1, tm1);
      const float aa0 = fexp2(m0 - mn0), aa1 = fexp2(m1 - mn1);
      m0 = mn0; m1 = mn1;
      float ts0 = 0.f, ts1 = 0.f;
      unsigned pH[4][4], pL[4][4];
      #pragma unroll
      for (int kc = 0; kc < 4; kc++) {
        float e00 = fexp2(s8[2*kc][0]   - m0), e01 = fexp2(s8[2*kc][1]   - m0);
        float e02 = fexp2(s8[2*kc][2]   - m1), e03 = fexp2(s8[2*kc][3]   - m1);
        float e10 = fexp2(s8[2*kc+1][0] - m0), e11 = fexp2(s8[2*kc+1][1] - m0);
        float e12 = fexp2(s8[2*kc+1][2] - m1), e13 = fexp2(s8[2*kc+1][3] - m1);
        ts0 += e00 + e01 + e10 + e11;
        ts1 += e02 + e03 + e12 + e13;
        pH[kc][0] = pack_bf16(e00, e01);
        pH[kc][1] = pack_bf16(e02, e03);
        pH[kc][2] = pack_bf16(e10, e11);
        pH[kc][3] = pack_bf16(e12, e13);
        __nv_bfloat162 h0 = *(__nv_bfloat162*)&pH[kc][0];
        __nv_bfloat162 h1 = *(__nv_bfloat162*)&pH[kc][1];
        __nv_bfloat162 h2 = *(__nv_bfloat162*)&pH[kc][2];
        __nv_bfloat162 h3 = *(__nv_bfloat162*)&pH[kc][3];
        pL[kc][0] = pack_bf16(e00 - __bfloat162float(h0.x), e01 - __bfloat162float(h0.y));
        pL[kc][1] = pack_bf16(e02 - __bfloat162float(h1.x), e03 - __bfloat162float(h1.y));
        pL[kc][2] = pack_bf16(e10 - __bfloat162float(h2.x), e11 - __bfloat162float(h2.y));
        pL[kc][3] = pack_bf16(e12 - __bfloat162float(h3.x), e13 - __bfloat162float(h3.y));
      }
      ts0 += __shfl_xor_sync(0xffffffffu, ts0, 1);
      ts0 += __shfl_xor_sync(0xffffffffu, ts0, 2);
      ts1 += __shfl_xor_sync(0xffffffffu, ts1, 1);
      ts1 += __shfl_xor_sync(0xffffffffu, ts1, 2);
      l0 = l0 * aa0 + ts0;
      l1 = l1 * aa1 + ts1;
      #pragma unroll
      for (int nt = 0; nt < 16; nt++) {
        o[nt][0] *= aa0; o[nt][1] *= aa0;
        o[nt][2] *= aa1; o[nt][3] *= aa1;
      }
      #pragma unroll
      for (int kc = 0; kc < 4; kc++) {
        #pragma unroll
        for (int ntp = 0; ntp < 8; ntp++) {
          const unsigned voff = (unsigned)((kc * 16 + ar) * AT_RS + ntp * 32 + aco);
          unsigned vh[4], vl[4];
          ldsm4t(vh, kvb + 2*AT_TSZ + voff);
          ldsm4t(vl, kvb + 3*AT_TSZ + voff);
          #pragma unroll
          for (int hf = 0; hf < 2; hf++) {
            float* d = o[ntp * 2 + hf];
            mma16816(d, pH[kc], vh[hf*2], vh[hf*2+1]);
            mma16816(d, pL[kc], vh[hf*2], vh[hf*2+1]);
            mma16816(d, pH[kc], vl[hf*2], vl[hf*2+1]);
          }
        }
      }
    }
    __syncthreads();
  }

  const float inv0 = 1.f / l0, inv1 = 1.f / l1;
  #pragma unroll
  for (int nt = 0; nt < 16; nt++) {
    const int col = h * HD_ + nt * 8 + ((lane & 3) << 1);
    size_t b0 = (size_t)rlo * H_ + col;
    size_t b1 = (size_t)(rlo + 8) * H_ + col;
    split_store2(o[nt][0] * inv0, o[nt][1] * inv0, outh + b0, outl + b0);
    split_store2(o[nt][2] * inv1, o[nt][3] * inv1, outh + b1, outl + b1);
  }
}

// ---------------- elementwise ----------------
__global__ void add_kernel(const float* __restrict__ a, const float* __restrict__ b,
                           float* __restrict__ c) {
  int i = blockIdx.x*256 + threadIdx.x;
  float4 va = ((const float4*)a)[i], vb = ((const float4*)b)[i];
  ((float4*)c)[i] = make_float4(va.x+vb.x, va.y+vb.y, va.z+vb.z, va.w+vb.w);
}

__device__ __forceinline__ float siluf(float g){ return g / (1.f + expf(-g)); }

__global__ void silu_resmlp_kernel() {
  int idx = blockIdx.x*256 + threadIdx.x;
  int t = idx >> 9;
  int jq = idx & 511;
  const float4* gp = (const float4*)(g_gu + (size_t)t*2*H_);
  float4 g4 = gp[jq], u4 = gp[jq + 512];
  float4 o = make_float4(siluf(g4.x)*u4.x, siluf(g4.y)*u4.y, siluf(g4.z)*u4.z, siluf(g4.w)*u4.w);
  size_t b = (size_t)t*H_ + jq*4;
  split_store4(o, g_hmid_h + b, g_hmid_l + b);
}

__global__ void silu_moe_kernel() {
  int idx = blockIdx.x*256 + threadIdx.x;
  int p = idx >> 8;
  int jq = idx & 255;
  const float4* gp = (const float4*)(g_gum + (size_t)p*2*I_);
  float4 g4 = gp[jq], u4 = gp[jq + 256];
  float4 o = make_float4(siluf(g4.x)*u4.x, siluf(g4.y)*u4.y, siluf(g4.z)*u4.z, siluf(g4.w)*u4.w);
  size_t b = (size_t)p*I_ + jq*4;
  split_store4(o, g_hmm_h + b, g_hmm_l + b);
}

// ---------------- gating + routing ----------------
__global__ void __launch_bounds__(256) gate_kernel(const float* __restrict__ gw) {
  const int t = blockIdx.x;
  __shared__ float part[256];
  const int tid = threadIdx.x;
  const int e = tid & 15, c = tid >> 4;
  const bf16* xh = g_h3n_h + (size_t)t*H_;
  const bf16* xl = g_h3n_l + (size_t)t*H_;
  float s = 0.f;
  for (int h = c*128; h < c*128+128; h++)
    s += (__bfloat162float(xh[h]) + __bfloat162float(xl[h])) * gw[h*E_ + e];
  part[tid] = s;
  __syncthreads();
  if (tid == 0) {
    float lg[16];
    for (int ee=0; ee<16; ee++){ float v=0.f; for (int cc=0; cc<16; cc++) v += part[cc*16+ee]; lg[ee]=v; }
    int i1 = 0;
    for (int ee=1; ee<16; ee++) if (lg[ee] > lg[i1]) i1 = ee;
    int i2 = (i1==0) ? 1 : 0;
    for (int ee=0; ee<16; ee++) if (ee!=i1 && lg[ee] > lg[i2]) i2 = ee;
    float mx = lg[i1];
    float p1 = expf(lg[i1]-mx), p2 = expf(lg[i2]-mx);
    float d = p1 + p2;
    g_topi[t*2]=i1; g_topi[t*2+1]=i2;
    g_topw[t*2]=p1/d; g_topw[t*2+1]=p2/d;
  }
}

__global__ void moe_zero_kernel(){ if (threadIdx.x < E_){ g_cnt[threadIdx.x]=0; g_cur[threadIdx.x]=0; } }
__global__ void moe_count_kernel(){ int i = blockIdx.x*256+threadIdx.x; if (i < P_) atomicAdd(&g_cnt[g_topi[i]], 1); }
__global__ void moe_scan_kernel(){ if (threadIdx.x==0){ int o=0; for (int e=0;e<E_;e++){ g_off[e]=o; o+=g_cnt[e]; } } }
__global__ void moe_scatter_kernel(){
  int i = blockIdx.x*256+threadIdx.x;
  if (i < P_) {
    int e = g_topi[i];
    int pos = g_off[e] + atomicAdd(&g_cur[e], 1);
    g_ptok[pos] = i >> 1;
    g_pslot[i]  = pos;
  }
}

// ---------------- final combine ----------------
__global__ void final_kernel(float* __restrict__ out) {
  const int t = blockIdx.x;
  const int p0 = g_pslot[t*2], p1 = g_pslot[t*2+1];
  const float w0 = g_topw[t*2], w1 = g_topw[t*2+1];
  const float4* ra = (const float4*)(g_resat + (size_t)t*H_);
  const float4* ml = (const float4*)(g_mlp   + (size_t)t*H_);
  const float4* y0 = (const float4*)(g_ym    + (size_t)p0*H_);
  const float4* y1 = (const float4*)(g_ym    + (size_t)p1*H_);
  float4* op = (float4*)(out + (size_t)t*H_);
  for (int i = threadIdx.x; i < 512; i += 256) {
    float4 A=ra[i], B=ml[i], C=y0[i], D=y1[i];
    op[i] = make_float4(A.x+B.x+w0*C.x+w1*D.x, A.y+B.y+w0*C.y+w1*D.y,
                        A.z+B.z+w0*C.z+w1*D.z, A.w+B.w+w0*C.w+w1*D.w);
  }
}

// ---------------- host ----------------
extern "C" void kernel_launch(void* const* d_in, const int* in_sizes, int n_in,
                              void* d_out, int out_size) {
  (void)in_sizes; (void)n_in; (void)out_size;
  const float* x      = (const float*)d_in[0];
  const float* ln_in  = (const float*)d_in[1];
  const float* ln_post= (const float*)d_in[2];
  const float* ln_res = (const float*)d_in[3];
  const float* wqkv   = (const float*)d_in[4];
  const float* wo     = (const float*)d_in[5];
  const float* w13    = (const float*)d_in[6];
  const float* w2     = (const float*)d_in[7];
  const float* gw     = (const float*)d_in[8];
  const float* ws     = (const float*)d_in[9];
  const float* w2s    = (const float*)d_in[10];
  float* out = (float*)d_out;

  float *qkv,*aproj,*resat,*gu,*mlp,*gum,*ym;
  cudaGetSymbolAddress((void**)&qkv,  g_qkv);
  cudaGetSymbolAddress((void**)&aproj,g_aproj);
  cudaGetSymbolAddress((void**)&resat,g_resat);
  cudaGetSymbolAddress((void**)&gu,   g_gu);
  cudaGetSymbolAddress((void**)&mlp,  g_mlp);
  cudaGetSymbolAddress((void**)&gum,  g_gum);
  cudaGetSymbolAddress((void**)&ym,   g_ym);

  bf16 *xnh,*xnl,*ath,*atl,*h2h,*h2l,*hmh,*hml,*h3h,*h3l,*hmmh,*hmml;
  cudaGetSymbolAddress((void**)&xnh, g_xn_h);   cudaGetSymbolAddress((void**)&xnl, g_xn_l);
  cudaGetSymbolAddress((void**)&ath, g_attn_h); cudaGetSymbolAddress((void**)&atl, g_attn_l);
  cudaGetSymbolAddress((void**)&h2h, g_h2n_h);  cudaGetSymbolAddress((void**)&h2l, g_h2n_l);
  cudaGetSymbolAddress((void**)&hmh, g_hmid_h); cudaGetSymbolAddress((void**)&hml, g_hmid_l);
  cudaGetSymbolAddress((void**)&h3h, g_h3n_h);  cudaGetSymbolAddress((void**)&h3l, g_h3n_l);
  cudaGetSymbolAddress((void**)&hmmh,g_hmm_h);  cudaGetSymbolAddress((void**)&hmml,g_hmm_l);

  bf16 *wqh,*wql,*woh,*wol,*w13h,*w13l,*w2h,*w2l,*wsh,*wsl,*w2sh,*w2sl;
  cudaGetSymbolAddress((void**)&wqh, g_wqkvT_h); cudaGetSymbolAddress((void**)&wql, g_wqkvT_l);
  cudaGetSymbolAddress((void**)&woh, g_woT_h);   cudaGetSymbolAddress((void**)&wol, g_woT_l);
  cudaGetSymbolAddress((void**)&w13h,g_w13T_h);  cudaGetSymbolAddress((void**)&w13l,g_w13T_l);
  cudaGetSymbolAddress((void**)&w2h, g_w2T_h);   cudaGetSymbolAddress((void**)&w2l, g_w2T_l);
  cudaGetSymbolAddress((void**)&wsh, g_ws_h);    cudaGetSymbolAddress((void**)&wsl, g_ws_l);
  cudaGetSymbolAddress((void**)&w2sh,g_w2s_h);   cudaGetSymbolAddress((void**)&w2sl,g_w2s_l);

  cudaFuncSetAttribute(mma_gemm, cudaFuncAttributeMaxDynamicSharedMemorySize, MMA_SMEM);
  cudaFuncSetAttribute(attn_mma, cudaFuncAttributeMaxDynamicSharedMemorySize, AT_SMEM);

  // ---- weight prep ----
  transpose_split<<<dim3(QKVW_/32, H_/32), 256>>>(wqkv, wqh, wql, H_, QKVW_);
  transpose_split<<<dim3(H_/32,    H_/32), 256>>>(wo,   woh, wol, H_, H_);
  transpose_split<<<dim3(2*H_/32,  H_/32), 256>>>(w13,  w13h,w13l,H_, 2*H_);
  transpose_split<<<dim3(H_/32,    H_/32), 256>>>(w2,   w2h, w2l, H_, H_);
  convert_split<<<(E_*2*I_*H_)/1024, 256>>>(ws,  wsh,  wsl);
  convert_split<<<(E_*H_*I_)/1024,   256>>>(w2s, w2sh, w2sl);

  // ---- attention branch ----
  rmsnorm_split<<<T_, 256>>>(x, ln_in, xnh, xnl);
  mma_gemm<<<dim3(QKVW_/256, T_/128, 1), 256, MMA_SMEM>>>(xnh, xnl, wqh, wql, qkv, QKVW_, H_, 0);
  rope_split_kernel<<<dim3(T_, NH_ + 2*NKV_), 64>>>(qkv);
  attn_mma<<<dim3(NH_, T_/128), 256, AT_SMEM>>>(ath, atl);
  mma_gemm<<<dim3(H_/256, T_/128, 1), 256, MMA_SMEM>>>(ath, atl, woh, wol, aproj, H_, H_, 0);
  add_kernel<<<(T_*H_)/1024, 256>>>(x, aproj, resat);

  // ---- residual MLP branch ----
  rmsnorm_split<<<T_, 256>>>(resat, ln_res, h2h, h2l);
  mma_gemm<<<dim3(2*H_/256, T_/128, 1), 256, MMA_SMEM>>>(h2h, h2l, w13h, w13l, gu, 2*H_, H_, 0);
  silu_resmlp_kernel<<<(T_*H_)/1024, 256>>>();
  mma_gemm<<<dim3(H_/256, T_/128, 1), 256, MMA_SMEM>>>(hmh, hml, w2h, w2l, mlp, H_, H_, 0);

  // ---- MoE branch ----
  rmsnorm_split<<<T_, 256>>>(x, ln_post, h3h, h3l);
  gate_kernel<<<T_, 256>>>(gw);
  moe_zero_kernel<<<1, 32>>>();
  moe_count_kernel<<<P_/256, 256>>>();
  moe_scan_kernel<<<1, 32>>>();
  moe_scatter_kernel<<<P_/256, 256>>>();
  mma_gemm<<<dim3(2*I_/256, T_/128, E_), 256, MMA_SMEM>>>(h3h, h3l, wsh, wsl, gum, 2*I_, H_, 1);
  silu_moe_kernel<<<(P_*I_)/1024, 256>>>();
  mma_gemm<<<dim3(H_/256, T_/128, E_), 256, MMA_SMEM>>>(hmmh, hmml, w2sh, w2sl, ym, H_, I_, 2);

  // ---- combine ----
  final_kernel<<<T_, 256>>>(out);
}

// round 10
// speedup vs baseline: 3.5422x; 1.3759x over previous
#include <cuda_runtime.h>
#include <cuda_fp16.h>
#include <math.h>

#define T_ 2048
#define H_ 2048
#define NH_ 16
#define NKV_ 4
#define HD_ 128
#define I_ 1024
#define E_ 16
#define TOPK_ 2
#define P_ (T_*TOPK_)
#define QKVW_ 3072

typedef __half fp16;

// ---------------- scratch (device globals; no allocations allowed) ----------------
__device__ float g_qkv[T_*QKVW_];
__device__ float g_aproj[T_*H_];
__device__ float g_resat[T_*H_];
__device__ float g_gu[T_*2*H_];
__device__ float g_mlp[T_*H_];
__device__ float g_gum[P_*2*I_];
__device__ float g_ym[P_*H_];

__device__ fp16 g_xn_h[T_*H_],   g_xn_l[T_*H_];
__device__ fp16 g_attn_h[T_*H_], g_attn_l[T_*H_];
__device__ fp16 g_h2n_h[T_*H_],  g_h2n_l[T_*H_];
__device__ fp16 g_hmid_h[T_*H_], g_hmid_l[T_*H_];
__device__ fp16 g_h3n_h[T_*H_],  g_h3n_l[T_*H_];
__device__ fp16 g_hmm_h[P_*I_],  g_hmm_l[P_*I_];

__device__ fp16 g_q_h[NH_*T_*HD_], g_q_l[NH_*T_*HD_];
__device__ fp16 g_k[NKV_*T_*HD_];
__device__ fp16 g_v[NKV_*T_*HD_];

__device__ fp16 g_wqkvT[QKVW_*H_];
__device__ fp16 g_woT[H_*H_];
__device__ fp16 g_w13T[2*H_*H_];
__device__ fp16 g_w2T[H_*H_];
__device__ fp16 g_ws[E_*2*I_*H_];
__device__ fp16 g_w2s[E_*H_*I_];

__device__ int   g_topi[P_];
__device__ float g_topw[P_];
__device__ int   g_cnt[E_];
__device__ int   g_off[E_];
__device__ int   g_cur[E_];
__device__ int   g_ptok[P_];
__device__ int   g_pslot[P_];

// ---------------- ptx helpers (base compute_103-safe) ----------------
__device__ __forceinline__ unsigned smem_u32(const void* p) {
  unsigned a;
  asm("{ .reg .u64 t; cvta.to.shared.u64 t, %1; cvt.u32.u64 %0, t; }" : "=r"(a) : "l"(p));
  return a;
}
__device__ __forceinline__ void cp16(unsigned dst, const void* src, bool valid) {
  int sz = valid ? 16 : 0;
  asm volatile("cp.async.cg.shared.global [%0], [%1], 16, %2;"
               :: "r"(dst), "l"(src), "r"(sz) : "memory");
}
#define CP_COMMIT() asm volatile("cp.async.commit_group;" ::: "memory")
#define CP_WAIT(n)  asm volatile("cp.async.wait_group %0;" :: "n"(n) : "memory")

__device__ __forceinline__ void ldsm4(unsigned* r, unsigned addr) {
  asm volatile("ldmatrix.sync.aligned.m8n8.x4.shared.b16 {%0,%1,%2,%3}, [%4];"
               : "=r"(r[0]), "=r"(r[1]), "=r"(r[2]), "=r"(r[3]) : "r"(addr));
}
__device__ __forceinline__ void ldsm4t(unsigned* r, unsigned addr) {
  asm volatile("ldmatrix.sync.aligned.m8n8.x4.trans.shared.b16 {%0,%1,%2,%3}, [%4];"
               : "=r"(r[0]), "=r"(r[1]), "=r"(r[2]), "=r"(r[3]) : "r"(addr));
}
__device__ __forceinline__ void mma16816(float* d, const unsigned* a, unsigned b0, unsigned b1) {
  asm volatile("mma.sync.aligned.m16n8k16.row.col.f32.f16.f16.f32 "
               "{%0,%1,%2,%3}, {%4,%5,%6,%7}, {%8,%9}, {%0,%1,%2,%3};"
               : "+f"(d[0]), "+f"(d[1]), "+f"(d[2]), "+f"(d[3])
               : "r"(a[0]), "r"(a[1]), "r"(a[2]), "r"(a[3]), "r"(b0), "r"(b1));
}

// fast 2^y on the FMA pipe (y in [-1e30, 0]); rel err < 3e-6
__device__ __forceinline__ float fexp2(float y) {
  y = fmaxf(y, -120.f);
  float z = y + 12582912.0f;
  int   n = __float_as_int(z) - 0x4B400000;
  float f = y - (z - 12582912.0f);
  float p = 0.0013333558f;
  p = fmaf(p, f, 0.0096181291f);
  p = fmaf(p, f, 0.0555041087f);
  p = fmaf(p, f, 0.2402265069f);
  p = fmaf(p, f, 0.6931471806f);
  p = fmaf(p, f, 1.0f);
  return p * __int_as_float((n + 127) << 23);
}

// ---------------- fp16 split helpers ----------------
__device__ __forceinline__ unsigned pack_h2(float a, float b) {
  __half2 t = __floats2half2_rn(a, b);
  return *(unsigned*)&t;
}
__device__ __forceinline__ void split_store4(float4 v, fp16* ph, fp16* pl) {
  float a[4] = {v.x, v.y, v.z, v.w};
  fp16 h[4], l[4];
  #pragma unroll
  for (int i = 0; i < 4; i++) {
    h[i] = __float2half_rn(a[i]);
    l[i] = __float2half_rn(a[i] - __half2float(h[i]));
  }
  *(uint2*)ph = *(uint2*)h;
  *(uint2*)pl = *(uint2*)l;
}
__device__ __forceinline__ void split_store2(float a, float b, fp16* ph, fp16* pl) {
  unsigned hi = pack_h2(a, b);
  __half2 hb = *(__half2*)&hi;
  unsigned lo = pack_h2(a - __half2float(hb.x), b - __half2float(hb.y));
  *(unsigned*)ph = hi;
  *(unsigned*)pl = lo;
}
__device__ __forceinline__ void split_store1(float a, fp16* ph, fp16* pl) {
  fp16 h = __float2half_rn(a);
  *ph = h;
  *pl = __float2half_rn(a - __half2float(h));
}

// ---------------- weight prep ----------------
__global__ void __launch_bounds__(256) convert_h(const float* __restrict__ in, fp16* __restrict__ o) {
  size_t i = (size_t)blockIdx.x * 256 + threadIdx.x;
  float4 v = ((const float4*)in)[i];
  fp16 h[4] = {__float2half_rn(v.x), __float2half_rn(v.y), __float2half_rn(v.z), __float2half_rn(v.w)};
  *(uint2*)(o + i * 4) = *(uint2*)h;
}

// transpose: in[K][N] fp32 -> o [N][K] fp16. grid (N/32, K/32), 256 thr.
__global__ void __launch_bounds__(256) transpose_h(const float* __restrict__ in, fp16* __restrict__ o,
                                                   int K, int N) {
  __shared__ float t[32][33];
  int k0 = blockIdx.y * 32, n0 = blockIdx.x * 32;
  int tx = threadIdx.x & 31, ty = threadIdx.x >> 5;
  #pragma unroll
  for (int j = 0; j < 4; j++)
    t[ty + 8 * j][tx] = in[(size_t)(k0 + ty + 8 * j) * N + n0 + tx];
  __syncthreads();
  #pragma unroll
  for (int j = 0; j < 4; j++)
    o[(size_t)(n0 + ty + 8 * j) * K + k0 + tx] = __float2half_rn(t[tx][ty + 8 * j]);
}

// ---------------- RMSNorm: one block per token, emits hi/lo fp16 ----------------
__global__ void __launch_bounds__(256) rmsnorm_split(const float* __restrict__ x,
                                                     const float* __restrict__ w,
                                                     fp16* __restrict__ oh, fp16* __restrict__ ol) {
  const int t = blockIdx.x;
  const float4* xr = (const float4*)(x + (size_t)t * H_);
  const float4* wr = (const float4*)w;
  const int i0 = threadIdx.x, i1 = threadIdx.x + 256;
  float4 v0 = xr[i0], v1 = xr[i1];
  float s = v0.x*v0.x+v0.y*v0.y+v0.z*v0.z+v0.w*v0.w
          + v1.x*v1.x+v1.y*v1.y+v1.z*v1.z+v1.w*v1.w;
  #pragma unroll
  for (int off = 16; off; off >>= 1) s += __shfl_xor_sync(0xffffffffu, s, off);
  __shared__ float red[8];
  __shared__ float sinv;
  if ((threadIdx.x & 31) == 0) red[threadIdx.x >> 5] = s;
  __syncthreads();
  if (threadIdx.x == 0) {
    float tt = 0.f;
    #pragma unroll
    for (int k = 0; k < 8; k++) tt += red[k];
    sinv = rsqrtf(tt * (1.f / H_) + 1e-5f);
  }
  __syncthreads();
  float r = sinv;
  float4 w0 = wr[i0], w1 = wr[i1];
  float4 o0, o1;
  o0.x=v0.x*r*w0.x; o0.y=v0.y*r*w0.y; o0.z=v0.z*r*w0.z; o0.w=v0.w*r*w0.w;
  o1.x=v1.x*r*w1.x; o1.y=v1.y*r*w1.y; o1.z=v1.z*r*w1.z; o1.w=v1.w*r*w1.w;
  size_t base = (size_t)t * H_;
  split_store4(o0, oh + base + i0 * 4, ol + base + i0 * 4);
  split_store4(o1, oh + base + i1 * 4, ol + base + i1 * 4);
}

// ---------------- mma.sync fp16 split-A GEMM ----------------
// D[row, n] = sum_k A[row,k]*B[n,k], fp32 out. A hi/lo fp16, B single fp16, K-major.
// CTA tile 128x256, 8 warps (2m x 4n), warp tile 64x64, K-chunk 32, 3-stage cp.async.
// stage: Ah[128x80B] Al[128x80B] B[256x80B] = 40960B.
#define MMA_STG 40960
#define MMA_SMEM (3*MMA_STG + 512)
__global__ void __launch_bounds__(256) mma_gemm(const fp16* __restrict__ Ah, const fp16* __restrict__ Al,
                                                const fp16* __restrict__ B,
                                                float* __restrict__ C, int N, int K, int grouped) {
  extern __shared__ char smem[];
  const int tid = threadIdx.x, wid = tid >> 5, lane = tid & 31;
  const int e = blockIdx.z;
  int count = 0, sbase = 0;
  if (grouped) {
    count = g_cnt[e];
    if ((int)(blockIdx.y << 7) >= count) return;
    sbase = g_off[e];
  }
  const fp16* BE = B + (size_t)e * N * K;
  const int m0 = blockIdx.y << 7, n0 = blockIdx.x << 8;
  unsigned sb = smem_u32(smem);
  int* rowmap = (int*)(smem + 3*MMA_STG);

  if (tid < 128) {
    int gr = m0 + tid;
    if (grouped) {
      if (m0 + tid < count) {
        int slot = sbase + m0 + tid;
        gr = (grouped == 1) ? g_ptok[slot] : slot;
      } else gr = -1;
    }
    rowmap[tid] = gr;
  }
  __syncthreads();

  const int nk = K >> 5;
  auto load_chunk = [&](int c, int st) {
    unsigned base = sb + (unsigned)st * MMA_STG;
    #pragma unroll
    for (int i = 0; i < 4; i++) {              // A hi/lo: 1024 cp16
      int s = tid + (i << 8);
      int mat = s >> 9, r = (s >> 2) & 127, cq = s & 3;
      unsigned dst = base + (unsigned)mat * 10240u + (unsigned)(r * 80 + cq * 16);
      int gr = rowmap[r];
      bool valid = (gr >= 0);
      if (!valid) gr = 0;
      const fp16* src = (mat ? Al : Ah) + (size_t)gr * K + (c << 5) + (cq << 3);
      cp16(dst, src, valid);
    }
    #pragma unroll
    for (int i = 0; i < 4; i++) {              // B: 1024 cp16
      int u = tid + (i << 8);
      int r = (u >> 2) & 255, cq = u & 3;
      unsigned dst = base + 20480u + (unsigned)(r * 80 + cq * 16);
      const fp16* src = BE + (size_t)(n0 + r) * K + (c << 5) + (cq << 3);
      cp16(dst, src, true);
    }
    CP_COMMIT();
  };

  float acc[4][8][4];
  #pragma unroll
  for (int i = 0; i < 4; i++)
    #pragma unroll
    for (int j = 0; j < 8; j++)
      #pragma unroll
      for (int k = 0; k < 4; k++) acc[i][j][k] = 0.f;

  const int wm = (wid >> 2) << 6;           // 0 or 64
  const int wn = (wid & 3) << 6;            // 0,64,128,192
  const int ar  = lane & 15;
  const unsigned aco = (lane & 16) ? 16u : 0u;
  const int bn  = (lane & 7) + ((lane & 16) ? 8 : 0);
  const unsigned bko = (lane & 8) ? 16u : 0u;

  load_chunk(0, 0);
  if (nk > 1) load_chunk(1, 1);
  for (int c = 0; c < nk; c++) {
    const int st = c - (c / 3) * 3;
    if (c + 1 < nk) CP_WAIT(1); else CP_WAIT(0);
    __syncthreads();
    if (c + 2 < nk) load_chunk(c + 2, (c + 2) - ((c + 2) / 3) * 3);
    const unsigned stb = sb + (unsigned)st * MMA_STG;
    #pragma unroll
    for (int ks = 0; ks < 2; ks++) {
      const unsigned kb = (unsigned)(ks << 5);
      unsigned ahf[4][4], alf[4][4];
      #pragma unroll
      for (int mi = 0; mi < 4; mi++) {
        unsigned rowA = (unsigned)((wm + mi * 16 + ar) * 80);
        ldsm4(ahf[mi], stb +          rowA + kb + aco);
        ldsm4(alf[mi], stb + 10240u + rowA + kb + aco);
      }
      #pragma unroll
      for (int nb = 0; nb < 4; nb++) {
        unsigned rowB = (unsigned)((wn + nb * 16 + bn) * 80);
        unsigned bhf[4];
        ldsm4(bhf, stb + 20480u + rowB + kb + bko);
        #pragma unroll
        for (int mi = 0; mi < 4; mi++) {
          #pragma unroll
          for (int half = 0; half < 2; half++) {
            float* d = acc[mi][nb * 2 + half];
            mma16816(d, ahf[mi], bhf[half * 2], bhf[half * 2 + 1]);
            mma16816(d, alf[mi], bhf[half * 2], bhf[half * 2 + 1]);
          }
        }
      }
    }
    __syncthreads();
  }

  #pragma unroll
  for (int mi = 0; mi < 4; mi++) {
    const int lr0 = wm + mi * 16 + (lane >> 2);
    const int gr0 = m0 + lr0;
    const bool s0 = !grouped || (gr0 < count);
    const bool s1 = !grouped || (gr0 + 8 < count);
    const size_t row0 = (size_t)((grouped ? sbase : 0) + gr0);
    #pragma unroll
    for (int nt = 0; nt < 8; nt++) {
      const int col = n0 + wn + nt * 8 + ((lane & 3) << 1);
      float* d = acc[mi][nt];
      if (s0) *(float2*)(C + row0 * N + col)       = make_float2(d[0], d[1]);
      if (s1) *(float2*)(C + (row0 + 8) * N + col) = make_float2(d[2], d[3]);
    }
  }
}

// ---------------- RoPE + split into per-head fp16 layouts ----------------
// q -> hi/lo, k -> single fp16 (rotated), v -> single fp16
__global__ void rope_split_kernel(const float* __restrict__ qkv) {
  const int t = blockIdx.x, hh = blockIdx.y, i = threadIdx.x;
  if (hh < NH_ + NKV_) {
    const float* b;
    float fr = powf(10000.f, -(float)(2*i) * (1.f/HD_));
    float ang = (float)t * fr;
    float sn, cs; sincosf(ang, &sn, &cs);
    if (hh < NH_) {
      b = qkv + (size_t)t*QKVW_ + hh*HD_;
      size_t o = ((size_t)hh*T_ + t) * HD_;
      float x1 = b[i], x2 = b[i+64];
      split_store1(x1*cs - x2*sn, g_q_h + o + i,      g_q_l + o + i);
      split_store1(x2*cs + x1*sn, g_q_h + o + i + 64, g_q_l + o + i + 64);
    } else {
      int k = hh - NH_;
      b = qkv + (size_t)t*QKVW_ + NH_*HD_ + k*HD_;
      size_t o = ((size_t)k*T_ + t) * HD_;
      float x1 = b[i], x2 = b[i+64];
      g_k[o + i]      = __float2half_rn(x1*cs - x2*sn);
      g_k[o + i + 64] = __float2half_rn(x2*cs + x1*sn);
    }
  } else {
    int v = hh - NH_ - NKV_;
    const float* b = qkv + (size_t)t*QKVW_ + (NH_+NKV_)*HD_ + v*HD_;
    size_t o = ((size_t)v*T_ + t) * HD_;
    g_v[o + i]      = __float2half_rn(b[i]);
    g_v[o + i + 64] = __float2half_rn(b[i+64]);
  }
}

// ---------------- mma.sync flash attention (fp16, split Q / split P) ----------------
#define AT_RS  272
#define AT_QSZ (128*AT_RS)
#define AT_TSZ (64*AT_RS)
#define AT_SMEM (2*AT_QSZ + 2*2*AT_TSZ)   // 139264
__global__ void __launch_bounds__(256) attn_mma(fp16* __restrict__ outh, fp16* __restrict__ outl) {
  extern __shared__ char smc[];
  const int h = blockIdx.x;
  const int q0 = ((int)gridDim.y - 1 - (int)blockIdx.y) << 7;   // heavy tiles first
  const int kvh = h >> 2;
  const int tid = threadIdx.x, wid = tid >> 5, lane = tid & 31;
  const unsigned sb = smem_u32(smc);
  const unsigned Ql_o = AT_QSZ, KV_o = 2*AT_QSZ;

  // Q tile hi/lo: 4096 cp16
  #pragma unroll
  for (int i = 0; i < 16; i++) {
    int s = tid + (i << 8);
    int mat = s >> 11, r = (s >> 4) & 127, cq = s & 15;
    unsigned dst = sb + (mat ? Ql_o : 0u) + (unsigned)(r * AT_RS + cq * 16);
    const fp16* src = (mat ? g_q_l : g_q_h) + (((size_t)h*T_ + q0 + r) << 7) + cq*8;
    cp16(dst, src, true);
  }
  CP_COMMIT();

  auto load_kv = [&](int c, int st) {
    unsigned base = sb + KV_o + (unsigned)st * (2*AT_TSZ);
    #pragma unroll
    for (int i = 0; i < 8; i++) {
      int s = tid + (i << 8);
      int mat = s >> 10, r = (s >> 4) & 63, cq = s & 15;
      unsigned dst = base + (unsigned)mat * AT_TSZ + (unsigned)(r * AT_RS + cq * 16);
      const fp16* ap = (mat == 0) ? g_k : g_v;
      cp16(dst, ap + (((size_t)kvh*T_ + c*64 + r) << 7) + cq*8, true);
    }
    CP_COMMIT();
  };

  const int wr0 = wid << 4;
  const int rlo = q0 + wr0 + (lane >> 2);
  float m0 = -1e30f, m1 = -1e30f, l0 = 0.f, l1 = 0.f;
  float o[16][4];
  #pragma unroll
  for (int i = 0; i < 16; i++)
    #pragma unroll
    for (int j = 0; j < 4; j++) o[i][j] = 0.f;

  const int ntl = (q0 >> 6) + 2;
  load_kv(0, 0);

  const int ar  = lane & 15;
  const int aco = (lane >> 4) << 4;
  const int bnr = (lane & 7) + ((lane & 16) ? 8 : 0);
  const int bko = (lane & 8) ? 16 : 0;
  const float sc = 0.12751744f;                    // (1/sqrt(128)) * log2(e)

  for (int c = 0; c < ntl; c++) {
    const int st = c & 1;
    if (c + 1 < ntl) { load_kv(c + 1, st ^ 1); CP_WAIT(1); }
    else CP_WAIT(0);
    __syncthreads();
    const int s0 = c << 6;
    const bool active = (s0 <= q0 + wr0 + 15);
    if (active) {
      const unsigned kvb = sb + KV_o + (unsigned)st * (2*AT_TSZ);
      float s8[8][4];
      #pragma unroll
      for (int i = 0; i < 8; i++)
        #pragma unroll
        for (int j = 0; j < 4; j++) s8[i][j] = 0.f;
      #pragma unroll
      for (int kk = 0; kk < 8; kk++) {
        const unsigned qoff = (unsigned)((wr0 + ar) * AT_RS + kk * 32 + aco);
        unsigned ah[4], al[4];
        ldsm4(ah, sb + qoff);
        ldsm4(al, sb + Ql_o + qoff);
        #pragma unroll
        for (int ntp = 0; ntp < 4; ntp++) {
          const unsigned koff = (unsigned)((bnr + ntp * 16) * AT_RS + kk * 32 + bko);
          unsigned bh[4];
          ldsm4(bh, kvb + koff);
          #pragma unroll
          for (int hf = 0; hf < 2; hf++) {
            float* d = s8[ntp * 2 + hf];
            mma16816(d, ah, bh[hf*2], bh[hf*2+1]);
            mma16816(d, al, bh[hf*2], bh[hf*2+1]);
          }
        }
      }
      #pragma unroll
      for (int nt = 0; nt < 8; nt++)
        #pragma unroll
        for (int j = 0; j < 4; j++) s8[nt][j] *= sc;
      if (s0 + 63 > q0 + wr0) {
        const int cb = s0 + ((lane & 3) << 1);
        #pragma unroll
        for (int nt = 0; nt < 8; nt++) {
          #pragma unroll
          for (int j = 0; j < 2; j++) {
            int col = cb + nt * 8 + j;
            if (col > rlo)     s8[nt][j]     = -1e30f;
            if (col > rlo + 8) s8[nt][j + 2] = -1e30f;
          }
        }
      }
      float tm0 = -1e30f, tm1 = -1e30f;
      #pragma unroll
      for (int nt = 0; nt < 8; nt++) {
        tm0 = fmaxf(tm0, fmaxf(s8[nt][0], s8[nt][1]));
        tm1 = fmaxf(tm1, fmaxf(s8[nt][2], s8[nt][3]));
      }
      tm0 = fmaxf(tm0, __shfl_xor_sync(0xffffffffu, tm0, 1));
      tm0 = fmaxf(tm0, __shfl_xor_sync(0xffffffffu, tm0, 2));
      tm1 = fmaxf(tm1, __shfl_xor_sync(0xffffffffu, tm1, 1));
      tm1 = fmaxf(tm1, __shfl_xor_sync(0xffffffffu, tm1, 2));
      const float mn0 = fmaxf(m0, tm0), mn1 = fmaxf(m1, tm1);
      const float aa0 = fexp2(m0 - mn0), aa1 = fexp2(m1 - mn1);
      m0 = mn0; m1 = mn1;
      float ts0 = 0.f, ts1 = 0.f;
      unsigned pH[4][4], pL[4][4];
      #pragma unroll
      for (int kc = 0; kc < 4; kc++) {
        float e00 = fexp2(s8[2*kc][0]   - m0), e01 = fexp2(s8[2*kc][1]   - m0);
        float e02 = fexp2(s8[2*kc][2]   - m1), e03 = fexp2(s8[2*kc][3]   - m1);
        float e10 = fexp2(s8[2*kc+1][0] - m0), e11 = fexp2(s8[2*kc+1][1] - m0);
        float e12 = fexp2(s8[2*kc+1][2] - m1), e13 = fexp2(s8[2*kc+1][3] - m1);
        ts0 += e00 + e01 + e10 + e11;
        ts1 += e02 + e03 + e12 + e13;
        pH[kc][0] = pack_h2(e00, e01);
        pH[kc][1] = pack_h2(e02, e03);
        pH[kc][2] = pack_h2(e10, e11);
        pH[kc][3] = pack_h2(e12, e13);
        __half2 h0 = *(__half2*)&pH[kc][0];
        __half2 h1 = *(__half2*)&pH[kc][1];
        __half2 h2 = *(__half2*)&pH[kc][2];
        __half2 h3 = *(__half2*)&pH[kc][3];
        pL[kc][0] = pack_h2(e00 - __half2float(h0.x), e01 - __half2float(h0.y));
        pL[kc][1] = pack_h2(e02 - __half2float(h1.x), e03 - __half2float(h1.y));
        pL[kc][2] = pack_h2(e10 - __half2float(h2.x), e11 - __half2float(h2.y));
        pL[kc][3] = pack_h2(e12 - __half2float(h3.x), e13 - __half2float(h3.y));
      }
      ts0 += __shfl_xor_sync(0xffffffffu, ts0, 1);
      ts0 += __shfl_xor_sync(0xffffffffu, ts0, 2);
      ts1 += __shfl_xor_sync(0xffffffffu, ts1, 1);
      ts1 += __shfl_xor_sync(0xffffffffu, ts1, 2);
      l0 = l0 * aa0 + ts0;
      l1 = l1 * aa1 + ts1;
      #pragma unroll
      for (int nt = 0; nt < 16; nt++) {
        o[nt][0] *= aa0; o[nt][1] *= aa0;
        o[nt][2] *= aa1; o[nt][3] *= aa1;
      }
      #pragma unroll
      for (int kc = 0; kc < 4; kc++) {
        #pragma unroll
        for (int ntp = 0; ntp < 8; ntp++) {
          const unsigned voff = (unsigned)((kc * 16 + ar) * AT_RS + ntp * 32 + aco);
          unsigned vh[4];
          ldsm4t(vh, kvb + AT_TSZ + voff);
          #pragma unroll
          for (int hf = 0; hf < 2; hf++) {
            float* d = o[ntp * 2 + hf];
            mma16816(d, pH[kc], vh[hf*2], vh[hf*2+1]);
            mma16816(d, pL[kc], vh[hf*2], vh[hf*2+1]);
          }
        }
      }
    }
    __syncthreads();
  }

  const float inv0 = 1.f / l0, inv1 = 1.f / l1;
  #pragma unroll
  for (int nt = 0; nt < 16; nt++) {
    const int col = h * HD_ + nt * 8 + ((lane & 3) << 1);
    size_t b0 = (size_t)rlo * H_ + col;
    size_t b1 = (size_t)(rlo + 8) * H_ + col;
    split_store2(o[nt][0] * inv0, o[nt][1] * inv0, outh + b0, outl + b0);
    split_store2(o[nt][2] * inv1, o[nt][3] * inv1, outh + b1, outl + b1);
  }
}

// ---------------- elementwise ----------------
__global__ void add_kernel(const float* __restrict__ a, const float* __restrict__ b,
                           float* __restrict__ c) {
  int i = blockIdx.x*256 + threadIdx.x;
  float4 va = ((const float4*)a)[i], vb = ((const float4*)b)[i];
  ((float4*)c)[i] = make_float4(va.x+vb.x, va.y+vb.y, va.z+vb.z, va.w+vb.w);
}

__device__ __forceinline__ float siluf(float g){ return g / (1.f + expf(-g)); }

__global__ void silu_resmlp_kernel() {
  int idx = blockIdx.x*256 + threadIdx.x;
  int t = idx >> 9;
  int jq = idx & 511;
  const float4* gp = (const float4*)(g_gu + (size_t)t*2*H_);
  float4 g4 = gp[jq], u4 = gp[jq + 512];
  float4 o = make_float4(siluf(g4.x)*u4.x, siluf(g4.y)*u4.y, siluf(g4.z)*u4.z, siluf(g4.w)*u4.w);
  size_t b = (size_t)t*H_ + jq*4;
  split_store4(o, g_hmid_h + b, g_hmid_l + b);
}

__global__ void silu_moe_kernel() {
  int idx = blockIdx.x*256 + threadIdx.x;
  int p = idx >> 8;
  int jq = idx & 255;
  const float4* gp = (const float4*)(g_gum + (size_t)p*2*I_);
  float4 g4 = gp[jq], u4 = gp[jq + 256];
  float4 o = make_float4(siluf(g4.x)*u4.x, siluf(g4.y)*u4.y, siluf(g4.z)*u4.z, siluf(g4.w)*u4.w);
  size_t b = (size_t)p*I_ + jq*4;
  split_store4(o, g_hmm_h + b, g_hmm_l + b);
}

// ---------------- gating + routing ----------------
__global__ void __launch_bounds__(256) gate_kernel(const float* __restrict__ gw) {
  const int t = blockIdx.x;
  __shared__ float part[256];
  const int tid = threadIdx.x;
  const int e = tid & 15, c = tid >> 4;
  const fp16* xh = g_h3n_h + (size_t)t*H_;
  const fp16* xl = g_h3n_l + (size_t)t*H_;
  float s = 0.f;
  for (int h = c*128; h < c*128+128; h++)
    s += (__half2float(xh[h]) + __half2float(xl[h])) * gw[h*E_ + e];
  part[tid] = s;
  __syncthreads();
  if (tid == 0) {
    float lg[16];
    for (int ee=0; ee<16; ee++){ float v=0.f; for (int cc=0; cc<16; cc++) v += part[cc*16+ee]; lg[ee]=v; }
    int i1 = 0;
    for (int ee=1; ee<16; ee++) if (lg[ee] > lg[i1]) i1 = ee;
    int i2 = (i1==0) ? 1 : 0;
    for (int ee=0; ee<16; ee++) if (ee!=i1 && lg[ee] > lg[i2]) i2 = ee;
    float mx = lg[i1];
    float p1 = expf(lg[i1]-mx), p2 = expf(lg[i2]-mx);
    float d = p1 + p2;
    g_topi[t*2]=i1; g_topi[t*2+1]=i2;
    g_topw[t*2]=p1/d; g_topw[t*2+1]=p2/d;
  }
}

__global__ void moe_zero_kernel(){ if (threadIdx.x < E_){ g_cnt[threadIdx.x]=0; g_cur[threadIdx.x]=0; } }
__global__ void moe_count_kernel(){ int i = blockIdx.x*256+threadIdx.x; if (i < P_) atomicAdd(&g_cnt[g_topi[i]], 1); }
__global__ void moe_scan_kernel(){ if (threadIdx.x==0){ int o=0; for (int e=0;e<E_;e++){ g_off[e]=o; o+=g_cnt[e]; } } }
__global__ void moe_scatter_kernel(){
  int i = blockIdx.x*256+threadIdx.x;
  if (i < P_) {
    int e = g_topi[i];
    int pos = g_off[e] + atomicAdd(&g_cur[e], 1);
    g_ptok[pos] = i >> 1;
    g_pslot[i]  = pos;
  }
}

// ---------------- final combine ----------------
__global__ void final_kernel(float* __restrict__ out) {
  const int t = blockIdx.x;
  const int p0 = g_pslot[t*2], p1 = g_pslot[t*2+1];
  const float w0 = g_topw[t*2], w1 = g_topw[t*2+1];
  const float4* ra = (const float4*)(g_resat + (size_t)t*H_);
  const float4* ml = (const float4*)(g_mlp   + (size_t)t*H_);
  const float4* y0 = (const float4*)(g_ym    + (size_t)p0*H_);
  const float4* y1 = (const float4*)(g_ym    + (size_t)p1*H_);
  float4* op = (float4*)(out + (size_t)t*H_);
  for (int i = threadIdx.x; i < 512; i += 256) {
    float4 A=ra[i], B=ml[i], C=y0[i], D=y1[i];
    op[i] = make_float4(A.x+B.x+w0*C.x+w1*D.x, A.y+B.y+w0*C.y+w1*D.y,
                        A.z+B.z+w0*C.z+w1*D.z, A.w+B.w+w0*C.w+w1*D.w);
  }
}

// ---------------- host ----------------
extern "C" void kernel_launch(void* const* d_in, const int* in_sizes, int n_in,
                              void* d_out, int out_size) {
  (void)in_sizes; (void)n_in; (void)out_size;
  const float* x      = (const float*)d_in[0];
  const float* ln_in  = (const float*)d_in[1];
  const float* ln_post= (const float*)d_in[2];
  const float* ln_res = (const float*)d_in[3];
  const float* wqkv   = (const float*)d_in[4];
  const float* wo     = (const float*)d_in[5];
  const float* w13    = (const float*)d_in[6];
  const float* w2     = (const float*)d_in[7];
  const float* gw     = (const float*)d_in[8];
  const float* ws     = (const float*)d_in[9];
  const float* w2s    = (const float*)d_in[10];
  float* out = (float*)d_out;

  float *qkv,*aproj,*resat,*gu,*mlp,*gum,*ym;
  cudaGetSymbolAddress((void**)&qkv,  g_qkv);
  cudaGetSymbolAddress((void**)&aproj,g_aproj);
  cudaGetSymbolAddress((void**)&resat,g_resat);
  cudaGetSymbolAddress((void**)&gu,   g_gu);
  cudaGetSymbolAddress((void**)&mlp,  g_mlp);
  cudaGetSymbolAddress((void**)&gum,  g_gum);
  cudaGetSymbolAddress((void**)&ym,   g_ym);

  fp16 *xnh,*xnl,*ath,*atl,*h2h,*h2l,*hmh,*hml,*h3h,*h3l,*hmmh,*hmml;
  cudaGetSymbolAddress((void**)&xnh, g_xn_h);   cudaGetSymbolAddress((void**)&xnl, g_xn_l);
  cudaGetSymbolAddress((void**)&ath, g_attn_h); cudaGetSymbolAddress((void**)&atl, g_attn_l);
  cudaGetSymbolAddress((void**)&h2h, g_h2n_h);  cudaGetSymbolAddress((void**)&h2l, g_h2n_l);
  cudaGetSymbolAddress((void**)&hmh, g_hmid_h); cudaGetSymbolAddress((void**)&hml, g_hmid_l);
  cudaGetSymbolAddress((void**)&h3h, g_h3n_h);  cudaGetSymbolAddress((void**)&h3l, g_h3n_l);
  cudaGetSymbolAddress((void**)&hmmh,g_hmm_h);  cudaGetSymbolAddress((void**)&hmml,g_hmm_l);

  fp16 *wq,*wo16,*w1316,*w216,*ws16,*w2s16;
  cudaGetSymbolAddress((void**)&wq,    g_wqkvT);
  cudaGetSymbolAddress((void**)&wo16,  g_woT);
  cudaGetSymbolAddress((void**)&w1316, g_w13T);
  cudaGetSymbolAddress((void**)&w216,  g_w2T);
  cudaGetSymbolAddress((void**)&ws16,  g_ws);
  cudaGetSymbolAddress((void**)&w2s16, g_w2s);

  cudaFuncSetAttribute(mma_gemm, cudaFuncAttributeMaxDynamicSharedMemorySize, MMA_SMEM);
  cudaFuncSetAttribute(attn_mma, cudaFuncAttributeMaxDynamicSharedMemorySize, AT_SMEM);

  // ---- weight prep ----
  transpose_h<<<dim3(QKVW_/32, H_/32), 256>>>(wqkv, wq,    H_, QKVW_);
  transpose_h<<<dim3(H_/32,    H_/32), 256>>>(wo,   wo16,  H_, H_);
  transpose_h<<<dim3(2*H_/32,  H_/32), 256>>>(w13,  w1316, H_, 2*H_);
  transpose_h<<<dim3(H_/32,    H_/32), 256>>>(w2,   w216,  H_, H_);
  convert_h<<<(E_*2*I_*H_)/1024, 256>>>(ws,  ws16);
  convert_h<<<(E_*H_*I_)/1024,   256>>>(w2s, w2s16);

  // ---- attention branch ----
  rmsnorm_split<<<T_, 256>>>(x, ln_in, xnh, xnl);
  mma_gemm<<<dim3(QKVW_/256, T_/128, 1), 256, MMA_SMEM>>>(xnh, xnl, wq, qkv, QKVW_, H_, 0);
  rope_split_kernel<<<dim3(T_, NH_ + 2*NKV_), 64>>>(qkv);
  attn_mma<<<dim3(NH_, T_/128), 256, AT_SMEM>>>(ath, atl);
  mma_gemm<<<dim3(H_/256, T_/128, 1), 256, MMA_SMEM>>>(ath, atl, wo16, aproj, H_, H_, 0);
  add_kernel<<<(T_*H_)/1024, 256>>>(x, aproj, resat);

  // ---- residual MLP branch ----
  rmsnorm_split<<<T_, 256>>>(resat, ln_res, h2h, h2l);
  mma_gemm<<<dim3(2*H_/256, T_/128, 1), 256, MMA_SMEM>>>(h2h, h2l, w1316, gu, 2*H_, H_, 0);
  silu_resmlp_kernel<<<(T_*H_)/1024, 256>>>();
  mma_gemm<<<dim3(H_/256, T_/128, 1), 256, MMA_SMEM>>>(hmh, hml, w216, mlp, H_, H_, 0);

  // ---- MoE branch ----
  rmsnorm_split<<<T_, 256>>>(x, ln_post, h3h, h3l);
  gate_kernel<<<T_, 256>>>(gw);
  moe_zero_kernel<<<1, 32>>>();
  moe_count_kernel<<<P_/256, 256>>>();
  moe_scan_kernel<<<1, 32>>>();
  moe_scatter_kernel<<<P_/256, 256>>>();
  mma_gemm<<<dim3(2*I_/256, T_/128, E_), 256, MMA_SMEM>>>(h3h, h3l, ws16, gum, 2*I_, H_, 1);
  silu_moe_kernel<<<(P_*I_)/1024, 256>>>();
  mma_gemm<<<dim3(H_/256, T_/128, E_), 256, MMA_SMEM>>>(hmmh, hmml, w2s16, ym, H_, I_, 2);

  // ---- combine ----
  final_kernel<<<T_, 256>>>(out);
}

// round 11
// speedup vs baseline: 5.0746x; 1.4326x over previous
#include <cuda_runtime.h>
#include <cuda_fp16.h>
#include <math.h>

#define T_ 2048
#define H_ 2048
#define NH_ 16
#define NKV_ 4
#define HD_ 128
#define I_ 1024
#define E_ 16
#define TOPK_ 2
#define P_ (T_*TOPK_)
#define QKVW_ 3072

typedef __half fp16;

// ---------------- scratch (device globals; no allocations allowed) ----------------
__device__ float g_qkv[T_*QKVW_];
__device__ float g_aproj[T_*H_];
__device__ float g_resat[T_*H_];
__device__ float g_gu[T_*2*H_];
__device__ float g_mlp[T_*H_];
__device__ float g_gum[P_*2*I_];
__device__ float g_ym[P_*H_];

__device__ fp16 g_xn[T_*H_];
__device__ fp16 g_attn[T_*H_];
__device__ fp16 g_h2n[T_*H_];
__device__ fp16 g_hmid[T_*H_];
__device__ fp16 g_h3n[T_*H_];
__device__ fp16 g_hmm[P_*I_];

__device__ fp16 g_q[NH_*T_*HD_];
__device__ fp16 g_k[NKV_*T_*HD_];
__device__ fp16 g_v[NKV_*T_*HD_];

__device__ fp16 g_wqkvT[QKVW_*H_];
__device__ fp16 g_woT[H_*H_];
__device__ fp16 g_w13T[2*H_*H_];
__device__ fp16 g_w2T[H_*H_];
__device__ fp16 g_ws[E_*2*I_*H_];
__device__ fp16 g_w2s[E_*H_*I_];

__device__ int   g_topi[P_];
__device__ float g_topw[P_];
__device__ int   g_cnt[E_];
__device__ int   g_off[E_];
__device__ int   g_cur[E_];
__device__ int   g_ptok[P_];
__device__ int   g_pslot[P_];

// ---------------- ptx helpers (base compute_103-safe) ----------------
__device__ __forceinline__ unsigned smem_u32(const void* p) {
  unsigned a;
  asm("{ .reg .u64 t; cvta.to.shared.u64 t, %1; cvt.u32.u64 %0, t; }" : "=r"(a) : "l"(p));
  return a;
}
__device__ __forceinline__ void cp16(unsigned dst, const void* src, bool valid) {
  int sz = valid ? 16 : 0;
  asm volatile("cp.async.cg.shared.global [%0], [%1], 16, %2;"
               :: "r"(dst), "l"(src), "r"(sz) : "memory");
}
#define CP_COMMIT() asm volatile("cp.async.commit_group;" ::: "memory")
#define CP_WAIT(n)  asm volatile("cp.async.wait_group %0;" :: "n"(n) : "memory")

__device__ __forceinline__ void ldsm4(unsigned* r, unsigned addr) {
  asm volatile("ldmatrix.sync.aligned.m8n8.x4.shared.b16 {%0,%1,%2,%3}, [%4];"
               : "=r"(r[0]), "=r"(r[1]), "=r"(r[2]), "=r"(r[3]) : "r"(addr));
}
__device__ __forceinline__ void ldsm4t(unsigned* r, unsigned addr) {
  asm volatile("ldmatrix.sync.aligned.m8n8.x4.trans.shared.b16 {%0,%1,%2,%3}, [%4];"
               : "=r"(r[0]), "=r"(r[1]), "=r"(r[2]), "=r"(r[3]) : "r"(addr));
}
__device__ __forceinline__ void mma16816(float* d, const unsigned* a, unsigned b0, unsigned b1) {
  asm volatile("mma.sync.aligned.m16n8k16.row.col.f32.f16.f16.f32 "
               "{%0,%1,%2,%3}, {%4,%5,%6,%7}, {%8,%9}, {%0,%1,%2,%3};"
               : "+f"(d[0]), "+f"(d[1]), "+f"(d[2]), "+f"(d[3])
               : "r"(a[0]), "r"(a[1]), "r"(a[2]), "r"(a[3]), "r"(b0), "r"(b1));
}

// fast 2^y on the FMA pipe (y in [-1e30, 0]); rel err < 3e-6
__device__ __forceinline__ float fexp2(float y) {
  y = fmaxf(y, -120.f);
  float z = y + 12582912.0f;
  int   n = __float_as_int(z) - 0x4B400000;
  float f = y - (z - 12582912.0f);
  float p = 0.0013333558f;
  p = fmaf(p, f, 0.0096181291f);
  p = fmaf(p, f, 0.0555041087f);
  p = fmaf(p, f, 0.2402265069f);
  p = fmaf(p, f, 0.6931471806f);
  p = fmaf(p, f, 1.0f);
  return p * __int_as_float((n + 127) << 23);
}

__device__ __forceinline__ unsigned pack_h2(float a, float b) {
  __half2 t = __floats2half2_rn(a, b);
  return *(unsigned*)&t;
}
__device__ __forceinline__ void store_h4(float4 v, fp16* p) {
  fp16 h[4] = {__float2half_rn(v.x), __float2half_rn(v.y), __float2half_rn(v.z), __float2half_rn(v.w)};
  *(uint2*)p = *(uint2*)h;
}

// ---------------- weight prep ----------------
__global__ void __launch_bounds__(256) convert_h(const float* __restrict__ in, fp16* __restrict__ o) {
  size_t i = (size_t)blockIdx.x * 256 + threadIdx.x;
  float4 v = ((const float4*)in)[i];
  store_h4(v, o + i * 4);
}

// transpose: in[K][N] fp32 -> o [N][K] fp16. grid (N/32, K/32), 256 thr.
__global__ void __launch_bounds__(256) transpose_h(const float* __restrict__ in, fp16* __restrict__ o,
                                                   int K, int N) {
  __shared__ float t[32][33];
  int k0 = blockIdx.y * 32, n0 = blockIdx.x * 32;
  int tx = threadIdx.x & 31, ty = threadIdx.x >> 5;
  #pragma unroll
  for (int j = 0; j < 4; j++)
    t[ty + 8 * j][tx] = in[(size_t)(k0 + ty + 8 * j) * N + n0 + tx];
  __syncthreads();
  #pragma unroll
  for (int j = 0; j < 4; j++)
    o[(size_t)(n0 + ty + 8 * j) * K + k0 + tx] = __float2half_rn(t[tx][ty + 8 * j]);
}

// ---------------- RMSNorm: one block per token, emits fp16 ----------------
__global__ void __launch_bounds__(256) rmsnorm_h(const float* __restrict__ x,
                                                 const float* __restrict__ w,
                                                 fp16* __restrict__ o) {
  const int t = blockIdx.x;
  const float4* xr = (const float4*)(x + (size_t)t * H_);
  const float4* wr = (const float4*)w;
  const int i0 = threadIdx.x, i1 = threadIdx.x + 256;
  float4 v0 = xr[i0], v1 = xr[i1];
  float s = v0.x*v0.x+v0.y*v0.y+v0.z*v0.z+v0.w*v0.w
          + v1.x*v1.x+v1.y*v1.y+v1.z*v1.z+v1.w*v1.w;
  #pragma unroll
  for (int off = 16; off; off >>= 1) s += __shfl_xor_sync(0xffffffffu, s, off);
  __shared__ float red[8];
  __shared__ float sinv;
  if ((threadIdx.x & 31) == 0) red[threadIdx.x >> 5] = s;
  __syncthreads();
  if (threadIdx.x == 0) {
    float tt = 0.f;
    #pragma unroll
    for (int k = 0; k < 8; k++) tt += red[k];
    sinv = rsqrtf(tt * (1.f / H_) + 1e-5f);
  }
  __syncthreads();
  float r = sinv;
  float4 w0 = wr[i0], w1 = wr[i1];
  float4 o0, o1;
  o0.x=v0.x*r*w0.x; o0.y=v0.y*r*w0.y; o0.z=v0.z*r*w0.z; o0.w=v0.w*r*w0.w;
  o1.x=v1.x*r*w1.x; o1.y=v1.y*r*w1.y; o1.z=v1.z*r*w1.z; o1.w=v1.w*r*w1.w;
  size_t base = (size_t)t * H_;
  store_h4(o0, o + base + i0 * 4);
  store_h4(o1, o + base + i1 * 4);
}

// ---------------- mma.sync fp16 GEMM ----------------
// D[row, n] = sum_k A[row,k]*B[n,k], fp32 out. A,B fp16 K-major.
// CTA tile 128x256, 8 warps (2m x 4n), warp tile 64x64, K-chunk 32, 3-stage cp.async.
// stage: A[128x80B] + B[256x80B] = 30720B.
#define MMA_STG 30720
#define MMA_SMEM (3*MMA_STG + 512)
__global__ void __launch_bounds__(256) mma_gemm(const fp16* __restrict__ A,
                                                const fp16* __restrict__ B,
                                                float* __restrict__ C, int N, int K, int grouped) {
  extern __shared__ char smem[];
  const int tid = threadIdx.x, wid = tid >> 5, lane = tid & 31;
  const int e = blockIdx.z;
  int count = 0, sbase = 0;
  if (grouped) {
    count = g_cnt[e];
    if ((int)(blockIdx.y << 7) >= count) return;
    sbase = g_off[e];
  }
  const fp16* BE = B + (size_t)e * N * K;
  const int m0 = blockIdx.y << 7, n0 = blockIdx.x << 8;
  unsigned sb = smem_u32(smem);
  int* rowmap = (int*)(smem + 3*MMA_STG);

  if (tid < 128) {
    int gr = m0 + tid;
    if (grouped) {
      if (m0 + tid < count) {
        int slot = sbase + m0 + tid;
        gr = (grouped == 1) ? g_ptok[slot] : slot;
      } else gr = -1;
    }
    rowmap[tid] = gr;
  }
  __syncthreads();

  const int nk = K >> 5;
  auto load_chunk = [&](int c, int st) {
    unsigned base = sb + (unsigned)st * MMA_STG;
    #pragma unroll
    for (int i = 0; i < 2; i++) {              // A: 512 cp16
      int s = tid + (i << 8);
      int r = (s >> 2) & 127, cq = s & 3;
      unsigned dst = base + (unsigned)(r * 80 + cq * 16);
      int gr = rowmap[r];
      bool valid = (gr >= 0);
      if (!valid) gr = 0;
      const fp16* src = A + (size_t)gr * K + (c << 5) + (cq << 3);
      cp16(dst, src, valid);
    }
    #pragma unroll
    for (int i = 0; i < 4; i++) {              // B: 1024 cp16
      int u = tid + (i << 8);
      int r = (u >> 2) & 255, cq = u & 3;
      unsigned dst = base + 10240u + (unsigned)(r * 80 + cq * 16);
      const fp16* src = BE + (size_t)(n0 + r) * K + (c << 5) + (cq << 3);
      cp16(dst, src, true);
    }
    CP_COMMIT();
  };

  float acc[4][8][4];
  #pragma unroll
  for (int i = 0; i < 4; i++)
    #pragma unroll
    for (int j = 0; j < 8; j++)
      #pragma unroll
      for (int k = 0; k < 4; k++) acc[i][j][k] = 0.f;

  const int wm = (wid >> 2) << 6;           // 0 or 64
  const int wn = (wid & 3) << 6;            // 0,64,128,192
  const int ar  = lane & 15;
  const unsigned aco = (lane & 16) ? 16u : 0u;
  const int bn  = (lane & 7) + ((lane & 16) ? 8 : 0);
  const unsigned bko = (lane & 8) ? 16u : 0u;

  load_chunk(0, 0);
  if (nk > 1) load_chunk(1, 1);
  for (int c = 0; c < nk; c++) {
    const int st = c - (c / 3) * 3;
    if (c + 1 < nk) CP_WAIT(1); else CP_WAIT(0);
    __syncthreads();
    if (c + 2 < nk) load_chunk(c + 2, (c + 2) - ((c + 2) / 3) * 3);
    const unsigned stb = sb + (unsigned)st * MMA_STG;
    #pragma unroll
    for (int ks = 0; ks < 2; ks++) {
      const unsigned kb = (unsigned)(ks << 5);
      unsigned ahf[4][4];
      #pragma unroll
      for (int mi = 0; mi < 4; mi++) {
        unsigned rowA = (unsigned)((wm + mi * 16 + ar) * 80);
        ldsm4(ahf[mi], stb + rowA + kb + aco);
      }
      #pragma unroll
      for (int nb = 0; nb < 4; nb++) {
        unsigned rowB = (unsigned)((wn + nb * 16 + bn) * 80);
        unsigned bhf[4];
        ldsm4(bhf, stb + 10240u + rowB + kb + bko);
        #pragma unroll
        for (int mi = 0; mi < 4; mi++) {
          #pragma unroll
          for (int half = 0; half < 2; half++) {
            mma16816(acc[mi][nb * 2 + half], ahf[mi], bhf[half * 2], bhf[half * 2 + 1]);
          }
        }
      }
    }
    __syncthreads();
  }

  #pragma unroll
  for (int mi = 0; mi < 4; mi++) {
    const int lr0 = wm + mi * 16 + (lane >> 2);
    const int gr0 = m0 + lr0;
    const bool s0 = !grouped || (gr0 < count);
    const bool s1 = !grouped || (gr0 + 8 < count);
    const size_t row0 = (size_t)((grouped ? sbase : 0) + gr0);
    #pragma unroll
    for (int nt = 0; nt < 8; nt++) {
      const int col = n0 + wn + nt * 8 + ((lane & 3) << 1);
      float* d = acc[mi][nt];
      if (s0) *(float2*)(C + row0 * N + col)       = make_float2(d[0], d[1]);
      if (s1) *(float2*)(C + (row0 + 8) * N + col) = make_float2(d[2], d[3]);
    }
  }
}

// ---------------- RoPE + pack into per-head fp16 layouts ----------------
__global__ void rope_split_kernel(const float* __restrict__ qkv) {
  const int t = blockIdx.x, hh = blockIdx.y, i = threadIdx.x;
  if (hh < NH_ + NKV_) {
    const float* b;
    fp16* d;
    if (hh < NH_) {
      b = qkv + (size_t)t*QKVW_ + hh*HD_;
      d = g_q + ((size_t)hh*T_ + t) * HD_;
    } else {
      int k = hh - NH_;
      b = qkv + (size_t)t*QKVW_ + NH_*HD_ + k*HD_;
      d = g_k + ((size_t)k*T_ + t) * HD_;
    }
    float fr = powf(10000.f, -(float)(2*i) * (1.f/HD_));
    float ang = (float)t * fr;
    float sn, cs; sincosf(ang, &sn, &cs);
    float x1 = b[i], x2 = b[i+64];
    d[i]      = __float2half_rn(x1*cs - x2*sn);
    d[i + 64] = __float2half_rn(x2*cs + x1*sn);
  } else {
    int v = hh - NH_ - NKV_;
    const float* b = qkv + (size_t)t*QKVW_ + (NH_+NKV_)*HD_ + v*HD_;
    size_t o = ((size_t)v*T_ + t) * HD_;
    g_v[o + i]      = __float2half_rn(b[i]);
    g_v[o + i + 64] = __float2half_rn(b[i+64]);
  }
}

// ---------------- mma.sync flash attention (single fp16) ----------------
#define AT_RS  272
#define AT_QSZ (128*AT_RS)
#define AT_TSZ (64*AT_RS)
#define AT_SMEM (AT_QSZ + 2*2*AT_TSZ)   // 104448
__global__ void __launch_bounds__(256) attn_mma(fp16* __restrict__ out) {
  extern __shared__ char smc[];
  const int h = blockIdx.x;
  const int q0 = ((int)gridDim.y - 1 - (int)blockIdx.y) << 7;   // heavy tiles first
  const int kvh = h >> 2;
  const int tid = threadIdx.x, wid = tid >> 5, lane = tid & 31;
  const unsigned sb = smem_u32(smc);
  const unsigned KV_o = AT_QSZ;

  // Q tile: 2048 cp16
  #pragma unroll
  for (int i = 0; i < 8; i++) {
    int s = tid + (i << 8);
    int r = (s >> 4) & 127, cq = s & 15;
    unsigned dst = sb + (unsigned)(r * AT_RS + cq * 16);
    const fp16* src = g_q + (((size_t)h*T_ + q0 + r) << 7) + cq*8;
    cp16(dst, src, true);
  }
  CP_COMMIT();

  auto load_kv = [&](int c, int st) {
    unsigned base = sb + KV_o + (unsigned)st * (2*AT_TSZ);
    #pragma unroll
    for (int i = 0; i < 8; i++) {
      int s = tid + (i << 8);
      int mat = s >> 10, r = (s >> 4) & 63, cq = s & 15;
      unsigned dst = base + (unsigned)mat * AT_TSZ + (unsigned)(r * AT_RS + cq * 16);
      const fp16* ap = (mat == 0) ? g_k : g_v;
      cp16(dst, ap + (((size_t)kvh*T_ + c*64 + r) << 7) + cq*8, true);
    }
    CP_COMMIT();
  };

  const int wr0 = wid << 4;
  const int rlo = q0 + wr0 + (lane >> 2);
  float m0 = -1e30f, m1 = -1e30f, l0 = 0.f, l1 = 0.f;
  float o[16][4];
  #pragma unroll
  for (int i = 0; i < 16; i++)
    #pragma unroll
    for (int j = 0; j < 4; j++) o[i][j] = 0.f;

  const int ntl = (q0 >> 6) + 2;
  load_kv(0, 0);

  const int ar  = lane & 15;
  const int aco = (lane >> 4) << 4;
  const int bnr = (lane & 7) + ((lane & 16) ? 8 : 0);
  const int bko = (lane & 8) ? 16 : 0;
  const float sc = 0.12751744f;                    // (1/sqrt(128)) * log2(e)

  for (int c = 0; c < ntl; c++) {
    const int st = c & 1;
    if (c + 1 < ntl) { load_kv(c + 1, st ^ 1); CP_WAIT(1); }
    else CP_WAIT(0);
    __syncthreads();
    const int s0 = c << 6;
    const bool active = (s0 <= q0 + wr0 + 15);
    if (active) {
      const unsigned kvb = sb + KV_o + (unsigned)st * (2*AT_TSZ);
      float s8[8][4];
      #pragma unroll
      for (int i = 0; i < 8; i++)
        #pragma unroll
        for (int j = 0; j < 4; j++) s8[i][j] = 0.f;
      #pragma unroll
      for (int kk = 0; kk < 8; kk++) {
        const unsigned qoff = (unsigned)((wr0 + ar) * AT_RS + kk * 32 + aco);
        unsigned ah[4];
        ldsm4(ah, sb + qoff);
        #pragma unroll
        for (int ntp = 0; ntp < 4; ntp++) {
          const unsigned koff = (unsigned)((bnr + ntp * 16) * AT_RS + kk * 32 + bko);
          unsigned bh[4];
          ldsm4(bh, kvb + koff);
          #pragma unroll
          for (int hf = 0; hf < 2; hf++)
            mma16816(s8[ntp * 2 + hf], ah, bh[hf*2], bh[hf*2+1]);
        }
      }
      #pragma unroll
      for (int nt = 0; nt < 8; nt++)
        #pragma unroll
        for (int j = 0; j < 4; j++) s8[nt][j] *= sc;
      if (s0 + 63 > q0 + wr0) {
        const int cb = s0 + ((lane & 3) << 1);
        #pragma unroll
        for (int nt = 0; nt < 8; nt++) {
          #pragma unroll
          for (int j = 0; j < 2; j++) {
            int col = cb + nt * 8 + j;
            if (col > rlo)     s8[nt][j]     = -1e30f;
            if (col > rlo + 8) s8[nt][j + 2] = -1e30f;
          }
        }
      }
      float tm0 = -1e30f, tm1 = -1e30f;
      #pragma unroll
      for (int nt = 0; nt < 8; nt++) {
        tm0 = fmaxf(tm0, fmaxf(s8[nt][0], s8[nt][1]));
        tm1 = fmaxf(tm1, fmaxf(s8[nt][2], s8[nt][3]));
      }
      tm0 = fmaxf(tm0, __shfl_xor_sync(0xffffffffu, tm0, 1));
      tm0 = fmaxf(tm0, __shfl_xor_sync(0xffffffffu, tm0, 2));
      tm1 = fmaxf(tm1, __shfl_xor_sync(0xffffffffu, tm1, 1));
      tm1 = fmaxf(tm1, __shfl_xor_sync(0xffffffffu, tm1, 2));
      const float mn0 = fmaxf(m0, tm0), mn1 = fmaxf(m1, tm1);
      const float aa0 = fexp2(m0 - mn0), aa1 = fexp2(m1 - mn1);
      m0 = mn0; m1 = mn1;
      float ts0 = 0.f, ts1 = 0.f;
      unsigned pH[4][4];
      #pragma unroll
      for (int kc = 0; kc < 4; kc++) {
        float e00 = fexp2(s8[2*kc][0]   - m0), e01 = fexp2(s8[2*kc][1]   - m0);
        float e02 = fexp2(s8[2*kc][2]   - m1), e03 = fexp2(s8[2*kc][3]   - m1);
        float e10 = fexp2(s8[2*kc+1][0] - m0), e11 = fexp2(s8[2*kc+1][1] - m0);
        float e12 = fexp2(s8[2*kc+1][2] - m1), e13 = fexp2(s8[2*kc+1][3] - m1);
        ts0 += e00 + e01 + e10 + e11;
        ts1 += e02 + e03 + e12 + e13;
        pH[kc][0] = pack_h2(e00, e01);
        pH[kc][1] = pack_h2(e02, e03);
        pH[kc][2] = pack_h2(e10, e11);
        pH[kc][3] = pack_h2(e12, e13);
      }
      ts0 += __shfl_xor_sync(0xffffffffu, ts0, 1);
      ts0 += __shfl_xor_sync(0xffffffffu, ts0, 2);
      ts1 += __shfl_xor_sync(0xffffffffu, ts1, 1);
      ts1 += __shfl_xor_sync(0xffffffffu, ts1, 2);
      l0 = l0 * aa0 + ts0;
      l1 = l1 * aa1 + ts1;
      #pragma unroll
      for (int nt = 0; nt < 16; nt++) {
        o[nt][0] *= aa0; o[nt][1] *= aa0;
        o[nt][2] *= aa1; o[nt][3] *= aa1;
      }
      #pragma unroll
      for (int kc = 0; kc < 4; kc++) {
        #pragma unroll
        for (int ntp = 0; ntp < 8; ntp++) {
          const unsigned voff = (unsigned)((kc * 16 + ar) * AT_RS + ntp * 32 + aco);
          unsigned vh[4];
          ldsm4t(vh, kvb + AT_TSZ + voff);
          #pragma unroll
          for (int hf = 0; hf < 2; hf++)
            mma16816(o[ntp * 2 + hf], pH[kc], vh[hf*2], vh[hf*2+1]);
        }
      }
    }
    __syncthreads();
  }

  const float inv0 = 1.f / l0, inv1 = 1.f / l1;
  #pragma unroll
  for (int nt = 0; nt < 16; nt++) {
    const int col = h * HD_ + nt * 8 + ((lane & 3) << 1);
    size_t b0 = (size_t)rlo * H_ + col;
    size_t b1 = (size_t)(rlo + 8) * H_ + col;
    *(unsigned*)(out + b0) = pack_h2(o[nt][0] * inv0, o[nt][1] * inv0);
    *(unsigned*)(out + b1) = pack_h2(o[nt][2] * inv1, o[nt][3] * inv1);
  }
}

// ---------------- elementwise ----------------
__global__ void add_kernel(const float* __restrict__ a, const float* __restrict__ b,
                           float* __restrict__ c) {
  int i = blockIdx.x*256 + threadIdx.x;
  float4 va = ((const float4*)a)[i], vb = ((const float4*)b)[i];
  ((float4*)c)[i] = make_float4(va.x+vb.x, va.y+vb.y, va.z+vb.z, va.w+vb.w);
}

__device__ __forceinline__ float siluf(float g){ return g / (1.f + expf(-g)); }

__global__ void silu_resmlp_kernel() {
  int idx = blockIdx.x*256 + threadIdx.x;
  int t = idx >> 9;
  int jq = idx & 511;
  const float4* gp = (const float4*)(g_gu + (size_t)t*2*H_);
  float4 g4 = gp[jq], u4 = gp[jq + 512];
  float4 o = make_float4(siluf(g4.x)*u4.x, siluf(g4.y)*u4.y, siluf(g4.z)*u4.z, siluf(g4.w)*u4.w);
  store_h4(o, g_hmid + (size_t)t*H_ + jq*4);
}

__global__ void silu_moe_kernel() {
  int idx = blockIdx.x*256 + threadIdx.x;
  int p = idx >> 8;
  int jq = idx & 255;
  const float4* gp = (const float4*)(g_gum + (size_t)p*2*I_);
  float4 g4 = gp[jq], u4 = gp[jq + 256];
  float4 o = make_float4(siluf(g4.x)*u4.x, siluf(g4.y)*u4.y, siluf(g4.z)*u4.z, siluf(g4.w)*u4.w);
  store_h4(o, g_hmm + (size_t)p*I_ + jq*4);
}

// ---------------- gating + routing ----------------
__global__ void __launch_bounds__(256) gate_kernel(const float* __restrict__ gw) {
  const int t = blockIdx.x;
  __shared__ float part[256];
  const int tid = threadIdx.x;
  const int e = tid & 15, c = tid >> 4;
  const fp16* xh = g_h3n + (size_t)t*H_;
  float s = 0.f;
  for (int h = c*128; h < c*128+128; h++)
    s += __half2float(xh[h]) * gw[h*E_ + e];
  part[tid] = s;
  __syncthreads();
  if (tid == 0) {
    float lg[16];
    for (int ee=0; ee<16; ee++){ float v=0.f; for (int cc=0; cc<16; cc++) v += part[cc*16+ee]; lg[ee]=v; }
    int i1 = 0;
    for (int ee=1; ee<16; ee++) if (lg[ee] > lg[i1]) i1 = ee;
    int i2 = (i1==0) ? 1 : 0;
    for (int ee=0; ee<16; ee++) if (ee!=i1 && lg[ee] > lg[i2]) i2 = ee;
    float mx = lg[i1];
    float p1 = expf(lg[i1]-mx), p2 = expf(lg[i2]-mx);
    float d = p1 + p2;
    g_topi[t*2]=i1; g_topi[t*2+1]=i2;
    g_topw[t*2]=p1/d; g_topw[t*2+1]=p2/d;
  }
}

__global__ void moe_zero_kernel(){ if (threadIdx.x < E_){ g_cnt[threadIdx.x]=0; g_cur[threadIdx.x]=0; } }
__global__ void moe_count_kernel(){ int i = blockIdx.x*256+threadIdx.x; if (i < P_) atomicAdd(&g_cnt[g_topi[i]], 1); }
__global__ void moe_scan_kernel(){ if (threadIdx.x==0){ int o=0; for (int e=0;e<E_;e++){ g_off[e]=o; o+=g_cnt[e]; } } }
__global__ void moe_scatter_kernel(){
  int i = blockIdx.x*256+threadIdx.x;
  if (i < P_) {
    int e = g_topi[i];
    int pos = g_off[e] + atomicAdd(&g_cur[e], 1);
    g_ptok[pos] = i >> 1;
    g_pslot[i]  = pos;
  }
}

// ---------------- final combine ----------------
__global__ void final_kernel(float* __restrict__ out) {
  const int t = blockIdx.x;
  const int p0 = g_pslot[t*2], p1 = g_pslot[t*2+1];
  const float w0 = g_topw[t*2], w1 = g_topw[t*2+1];
  const float4* ra = (const float4*)(g_resat + (size_t)t*H_);
  const float4* ml = (const float4*)(g_mlp   + (size_t)t*H_);
  const float4* y0 = (const float4*)(g_ym    + (size_t)p0*H_);
  const float4* y1 = (const float4*)(g_ym    + (size_t)p1*H_);
  float4* op = (float4*)(out + (size_t)t*H_);
  for (int i = threadIdx.x; i < 512; i += 256) {
    float4 A=ra[i], B=ml[i], C=y0[i], D=y1[i];
    op[i] = make_float4(A.x+B.x+w0*C.x+w1*D.x, A.y+B.y+w0*C.y+w1*D.y,
                        A.z+B.z+w0*C.z+w1*D.z, A.w+B.w+w0*C.w+w1*D.w);
  }
}

// ---------------- host ----------------
extern "C" void kernel_launch(void* const* d_in, const int* in_sizes, int n_in,
                              void* d_out, int out_size) {
  (void)in_sizes; (void)n_in; (void)out_size;
  const float* x      = (const float*)d_in[0];
  const float* ln_in  = (const float*)d_in[1];
  const float* ln_post= (const float*)d_in[2];
  const float* ln_res = (const float*)d_in[3];
  const float* wqkv   = (const float*)d_in[4];
  const float* wo     = (const float*)d_in[5];
  const float* w13    = (const float*)d_in[6];
  const float* w2     = (const float*)d_in[7];
  const float* gw     = (const float*)d_in[8];
  const float* ws     = (const float*)d_in[9];
  const float* w2s    = (const float*)d_in[10];
  float* out = (float*)d_out;

  float *qkv,*aproj,*resat,*gu,*mlp,*gum,*ym;
  cudaGetSymbolAddress((void**)&qkv,  g_qkv);
  cudaGetSymbolAddress((void**)&aproj,g_aproj);
  cudaGetSymbolAddress((void**)&resat,g_resat);
  cudaGetSymbolAddress((void**)&gu,   g_gu);
  cudaGetSymbolAddress((void**)&mlp,  g_mlp);
  cudaGetSymbolAddress((void**)&gum,  g_gum);
  cudaGetSymbolAddress((void**)&ym,   g_ym);

  fp16 *xn,*attn,*h2n,*hmid,*h3n,*hmm;
  cudaGetSymbolAddress((void**)&xn,   g_xn);
  cudaGetSymbolAddress((void**)&attn, g_attn);
  cudaGetSymbolAddress((void**)&h2n,  g_h2n);
  cudaGetSymbolAddress((void**)&hmid, g_hmid);
  cudaGetSymbolAddress((void**)&h3n,  g_h3n);
  cudaGetSymbolAddress((void**)&hmm,  g_hmm);

  fp16 *wq,*wo16,*w1316,*w216,*ws16,*w2s16;
  cudaGetSymbolAddress((void**)&wq,    g_wqkvT);
  cudaGetSymbolAddress((void**)&wo16,  g_woT);
  cudaGetSymbolAddress((void**)&w1316, g_w13T);
  cudaGetSymbolAddress((void**)&w216,  g_w2T);
  cudaGetSymbolAddress((void**)&ws16,  g_ws);
  cudaGetSymbolAddress((void**)&w2s16, g_w2s);

  cudaFuncSetAttribute(mma_gemm, cudaFuncAttributeMaxDynamicSharedMemorySize, MMA_SMEM);
  cudaFuncSetAttribute(attn_mma, cudaFuncAttributeMaxDynamicSharedMemorySize, AT_SMEM);

  // ---- weight prep ----
  transpose_h<<<dim3(QKVW_/32, H_/32), 256>>>(wqkv, wq,    H_, QKVW_);
  transpose_h<<<dim3(H_/32,    H_/32), 256>>>(wo,   wo16,  H_, H_);
  transpose_h<<<dim3(2*H_/32,  H_/32), 256>>>(w13,  w1316, H_, 2*H_);
  transpose_h<<<dim3(H_/32,    H_/32), 256>>>(w2,   w216,  H_, H_);
  convert_h<<<(E_*2*I_*H_)/1024, 256>>>(ws,  ws16);
  convert_h<<<(E_*H_*I_)/1024,   256>>>(w2s, w2s16);

  // ---- attention branch ----
  rmsnorm_h<<<T_, 256>>>(x, ln_in, xn);
  mma_gemm<<<dim3(QKVW_/256, T_/128, 1), 256, MMA_SMEM>>>(xn, wq, qkv, QKVW_, H_, 0);
  rope_split_kernel<<<dim3(T_, NH_ + 2*NKV_), 64>>>(qkv);
  attn_mma<<<dim3(NH_, T_/128), 256, AT_SMEM>>>(attn);
  mma_gemm<<<dim3(H_/256, T_/128, 1), 256, MMA_SMEM>>>(attn, wo16, aproj, H_, H_, 0);
  add_kernel<<<(T_*H_)/1024, 256>>>(x, aproj, resat);

  // ---- residual MLP branch ----
  rmsnorm_h<<<T_, 256>>>(resat, ln_res, h2n);
  mma_gemm<<<dim3(2*H_/256, T_/128, 1), 256, MMA_SMEM>>>(h2n, w1316, gu, 2*H_, H_, 0);
  silu_resmlp_kernel<<<(T_*H_)/1024, 256>>>();
  mma_gemm<<<dim3(H_/256, T_/128, 1), 256, MMA_SMEM>>>(hmid, w216, mlp, H_, H_, 0);

  // ---- MoE branch ----
  rmsnorm_h<<<T_, 256>>>(x, ln_post, h3n);
  gate_kernel<<<T_, 256>>>(gw);
  moe_zero_kernel<<<1, 32>>>();
  moe_count_kernel<<<P_/256, 256>>>();
  moe_scan_kernel<<<1, 32>>>();
  moe_scatter_kernel<<<P_/256, 256>>>();
  mma_gemm<<<dim3(2*I_/256, T_/128, E_), 256, MMA_SMEM>>>(h3n, ws16, gum, 2*I_, H_, 1);
  silu_moe_kernel<<<(P_*I_)/1024, 256>>>();
  mma_gemm<<<dim3(H_/256, T_/128, E_), 256, MMA_SMEM>>>(hmm, w2s16, ym, H_, I_, 2);

  // ---- combine ----
  final_kernel<<<T_, 256>>>(out);
}

// round 12
// speedup vs baseline: 6.3570x; 1.2527x over previous
#include <cuda_runtime.h>
#include <cuda_fp16.h>
#include <math.h>

#define T_ 2048
#define H_ 2048
#define NH_ 16
#define NKV_ 4
#define HD_ 128
#define I_ 1024
#define E_ 16
#define TOPK_ 2
#define P_ (T_*TOPK_)
#define QKVW_ 3072

typedef __half fp16;

// ---------------- scratch (device globals; no allocations allowed) ----------------
__device__ float g_qkv[T_*QKVW_];
__device__ float g_resat[T_*H_];
__device__ float g_mlp[T_*H_];
__device__ float g_ym[P_*H_];

__device__ fp16 g_xn[T_*H_];
__device__ fp16 g_attn[T_*H_];
__device__ fp16 g_h2n[T_*H_];
__device__ fp16 g_hmid[T_*H_];
__device__ fp16 g_h3n[T_*H_];
__device__ fp16 g_hmm[P_*I_];

__device__ fp16 g_q[NH_*T_*HD_];
__device__ fp16 g_k[NKV_*T_*HD_];
__device__ fp16 g_v[NKV_*T_*HD_];

__device__ fp16 g_wqkvT[QKVW_*H_];
__device__ fp16 g_woT[H_*H_];
__device__ fp16 g_w13T[2*H_*H_];     // gate/up interleaved rows
__device__ fp16 g_w2T[H_*H_];
__device__ fp16 g_ws[E_*2*I_*H_];    // gate/up interleaved rows per expert
__device__ fp16 g_w2s[E_*H_*I_];

__device__ int   g_topi[P_];
__device__ float g_topw[P_];
__device__ int   g_cnt[E_];
__device__ int   g_off[E_];
__device__ int   g_cur[E_];
__device__ int   g_ptok[P_];
__device__ int   g_pslot[P_];

// ---------------- ptx helpers (base compute_103-safe) ----------------
__device__ __forceinline__ unsigned smem_u32(const void* p) {
  unsigned a;
  asm("{ .reg .u64 t; cvta.to.shared.u64 t, %1; cvt.u32.u64 %0, t; }" : "=r"(a) : "l"(p));
  return a;
}
__device__ __forceinline__ void cp16(unsigned dst, const void* src, bool valid) {
  int sz = valid ? 16 : 0;
  asm volatile("cp.async.cg.shared.global [%0], [%1], 16, %2;"
               :: "r"(dst), "l"(src), "r"(sz) : "memory");
}
#define CP_COMMIT() asm volatile("cp.async.commit_group;" ::: "memory")
#define CP_WAIT(n)  asm volatile("cp.async.wait_group %0;" :: "n"(n) : "memory")

__device__ __forceinline__ void ldsm4(unsigned* r, unsigned addr) {
  asm volatile("ldmatrix.sync.aligned.m8n8.x4.shared.b16 {%0,%1,%2,%3}, [%4];"
               : "=r"(r[0]), "=r"(r[1]), "=r"(r[2]), "=r"(r[3]) : "r"(addr));
}
__device__ __forceinline__ void ldsm4t(unsigned* r, unsigned addr) {
  asm volatile("ldmatrix.sync.aligned.m8n8.x4.trans.shared.b16 {%0,%1,%2,%3}, [%4];"
               : "=r"(r[0]), "=r"(r[1]), "=r"(r[2]), "=r"(r[3]) : "r"(addr));
}
__device__ __forceinline__ void mma16816(float* d, const unsigned* a, unsigned b0, unsigned b1) {
  asm volatile("mma.sync.aligned.m16n8k16.row.col.f32.f16.f16.f32 "
               "{%0,%1,%2,%3}, {%4,%5,%6,%7}, {%8,%9}, {%0,%1,%2,%3};"
               : "+f"(d[0]), "+f"(d[1]), "+f"(d[2]), "+f"(d[3])
               : "r"(a[0]), "r"(a[1]), "r"(a[2]), "r"(a[3]), "r"(b0), "r"(b1));
}

// fast 2^y on the FMA pipe (y in [-1e30, 0]); rel err < 3e-6
__device__ __forceinline__ float fexp2(float y) {
  y = fmaxf(y, -120.f);
  float z = y + 12582912.0f;
  int   n = __float_as_int(z) - 0x4B400000;
  float f = y - (z - 12582912.0f);
  float p = 0.0013333558f;
  p = fmaf(p, f, 0.0096181291f);
  p = fmaf(p, f, 0.0555041087f);
  p = fmaf(p, f, 0.2402265069f);
  p = fmaf(p, f, 0.6931471806f);
  p = fmaf(p, f, 1.0f);
  return p * __int_as_float((n + 127) << 23);
}

__device__ __forceinline__ unsigned pack_h2(float a, float b) {
  __half2 t = __floats2half2_rn(a, b);
  return *(unsigned*)&t;
}
__device__ __forceinline__ void store_h4(float4 v, fp16* p) {
  fp16 h[4] = {__float2half_rn(v.x), __float2half_rn(v.y), __float2half_rn(v.z), __float2half_rn(v.w)};
  *(uint2*)p = *(uint2*)h;
}
__device__ __forceinline__ float siluf(float g){ return g / (1.f + __expf(-g)); }

// ---------------- weight prep ----------------
// ws (E, 2I, H): interleave gate/up rows per expert; fp32 -> fp16; 8 elems/thread.
__global__ void __launch_bounds__(256) convert_ws_int(const float* __restrict__ in, fp16* __restrict__ o) {
  size_t idx = (size_t)blockIdx.x * 256 + threadIdx.x;
  size_t r = idx >> 8;                       // H_/8 = 256 chunks per row
  int h0 = (int)(idx & 255) << 3;
  int e = (int)(r >> 11);                    // 2I = 2048 rows per expert
  int k = (int)(r & 2047);
  int srcr = e * 2 * I_ + ((k & 1) ? I_ + (k >> 1) : (k >> 1));
  const float4* s = (const float4*)(in + (size_t)srcr * H_ + h0);
  float4 a = s[0], b = s[1];
  fp16 hb[8] = {__float2half_rn(a.x), __float2half_rn(a.y), __float2half_rn(a.z), __float2half_rn(a.w),
                __float2half_rn(b.x), __float2half_rn(b.y), __float2half_rn(b.z), __float2half_rn(b.w)};
  *(uint4*)(o + r * H_ + h0) = *(uint4*)hb;
}

// plain fp32 -> fp16, 8 elems/thread
__global__ void __launch_bounds__(256) convert_h8(const float* __restrict__ in, fp16* __restrict__ o) {
  size_t i = ((size_t)blockIdx.x * 256 + threadIdx.x) << 3;
  const float4* s = (const float4*)(in + i);
  float4 a = s[0], b = s[1];
  fp16 hb[8] = {__float2half_rn(a.x), __float2half_rn(a.y), __float2half_rn(a.z), __float2half_rn(a.w),
                __float2half_rn(b.x), __float2half_rn(b.y), __float2half_rn(b.z), __float2half_rn(b.w)};
  *(uint4*)(o + i) = *(uint4*)hb;
}

// transpose: in[K][N] fp32 -> o [N][K] fp16; il=1 interleaves gate/up dest rows.
__global__ void __launch_bounds__(256) transpose_h(const float* __restrict__ in, fp16* __restrict__ o,
                                                   int K, int N, int il) {
  __shared__ float t[32][33];
  int k0 = blockIdx.y * 32, n0 = blockIdx.x * 32;
  int tx = threadIdx.x & 31, ty = threadIdx.x >> 5;
  #pragma unroll
  for (int j = 0; j < 4; j++)
    t[ty + 8 * j][tx] = in[(size_t)(k0 + ty + 8 * j) * N + n0 + tx];
  __syncthreads();
  int half = N >> 1;
  #pragma unroll
  for (int j = 0; j < 4; j++) {
    int n = n0 + ty + 8 * j;
    int dr = il ? ((n < half) ? 2 * n : 2 * (n - half) + 1) : n;
    o[(size_t)dr * K + k0 + tx] = __float2half_rn(t[tx][ty + 8 * j]);
  }
}

// ---------------- RMSNorm: one block per token, emits fp16 ----------------
__global__ void __launch_bounds__(256) rmsnorm_h(const float* __restrict__ x,
                                                 const float* __restrict__ w,
                                                 fp16* __restrict__ o) {
  const int t = blockIdx.x;
  const float4* xr = (const float4*)(x + (size_t)t * H_);
  const float4* wr = (const float4*)w;
  const int i0 = threadIdx.x, i1 = threadIdx.x + 256;
  float4 v0 = xr[i0], v1 = xr[i1];
  float s = v0.x*v0.x+v0.y*v0.y+v0.z*v0.z+v0.w*v0.w
          + v1.x*v1.x+v1.y*v1.y+v1.z*v1.z+v1.w*v1.w;
  #pragma unroll
  for (int off = 16; off; off >>= 1) s += __shfl_xor_sync(0xffffffffu, s, off);
  __shared__ float red[8];
  __shared__ float sinv;
  if ((threadIdx.x & 31) == 0) red[threadIdx.x >> 5] = s;
  __syncthreads();
  if (threadIdx.x == 0) {
    float tt = 0.f;
    #pragma unroll
    for (int k = 0; k < 8; k++) tt += red[k];
    sinv = rsqrtf(tt * (1.f / H_) + 1e-5f);
  }
  __syncthreads();
  float r = sinv;
  float4 w0 = wr[i0], w1 = wr[i1];
  float4 o0, o1;
  o0.x=v0.x*r*w0.x; o0.y=v0.y*r*w0.y; o0.z=v0.z*r*w0.z; o0.w=v0.w*r*w0.w;
  o1.x=v1.x*r*w1.x; o1.y=v1.y*r*w1.y; o1.z=v1.z*r*w1.z; o1.w=v1.w*r*w1.w;
  size_t base = (size_t)t * H_;
  store_h4(o0, o + base + i0 * 4);
  store_h4(o1, o + base + i1 * 4);
}

// ---------------- mma.sync fp16 GEMM with fused epilogues ----------------
// D[row, n] = sum_k A[row,k]*B[n,k]. CTA tile 128x256, 8 warps (2m x 4n), K-chunk 32, 3 stages.
// mode 0: fp32 store to C. mode 1: gate/up interleaved cols -> silu(g)*u fp16 to Ch (Nout=N/2).
// mode 2: C = Xres + acc (fp32, dense only).
#define MMA_STG 30720
#define MMA_SMEM (3*MMA_STG + 512)
__global__ void __launch_bounds__(256) mma_gemm(const fp16* __restrict__ A,
                                                const fp16* __restrict__ B,
                                                float* __restrict__ C,
                                                fp16* __restrict__ Ch,
                                                const float* __restrict__ Xres,
                                                int N, int K, int grouped, int mode) {
  extern __shared__ char smem[];
  const int tid = threadIdx.x, wid = tid >> 5, lane = tid & 31;
  const int e = blockIdx.z;
  int count = 0, sbase = 0;
  if (grouped) {
    count = g_cnt[e];
    if ((int)(blockIdx.y << 7) >= count) return;
    sbase = g_off[e];
  }
  const fp16* BE = B + (size_t)e * N * K;
  const int m0 = blockIdx.y << 7, n0 = blockIdx.x << 8;
  unsigned sb = smem_u32(smem);
  int* rowmap = (int*)(smem + 3*MMA_STG);

  if (tid < 128) {
    int gr = m0 + tid;
    if (grouped) {
      if (m0 + tid < count) {
        int slot = sbase + m0 + tid;
        gr = (grouped == 1) ? g_ptok[slot] : slot;
      } else gr = -1;
    }
    rowmap[tid] = gr;
  }
  __syncthreads();

  const int nk = K >> 5;
  auto load_chunk = [&](int c, int st) {
    unsigned base = sb + (unsigned)st * MMA_STG;
    #pragma unroll
    for (int i = 0; i < 2; i++) {              // A: 512 cp16
      int s = tid + (i << 8);
      int r = (s >> 2) & 127, cq = s & 3;
      unsigned dst = base + (unsigned)(r * 80 + cq * 16);
      int gr = rowmap[r];
      bool valid = (gr >= 0);
      if (!valid) gr = 0;
      const fp16* src = A + (size_t)gr * K + (c << 5) + (cq << 3);
      cp16(dst, src, valid);
    }
    #pragma unroll
    for (int i = 0; i < 4; i++) {              // B: 1024 cp16
      int u = tid + (i << 8);
      int r = (u >> 2) & 255, cq = u & 3;
      unsigned dst = base + 10240u + (unsigned)(r * 80 + cq * 16);
      const fp16* src = BE + (size_t)(n0 + r) * K + (c << 5) + (cq << 3);
      cp16(dst, src, true);
    }
    CP_COMMIT();
  };

  float acc[4][8][4];
  #pragma unroll
  for (int i = 0; i < 4; i++)
    #pragma unroll
    for (int j = 0; j < 8; j++)
      #pragma unroll
      for (int k = 0; k < 4; k++) acc[i][j][k] = 0.f;

  const int wm = (wid >> 2) << 6;
  const int wn = (wid & 3) << 6;
  const int ar  = lane & 15;
  const unsigned aco = (lane & 16) ? 16u : 0u;
  const int bn  = (lane & 7) + ((lane & 16) ? 8 : 0);
  const unsigned bko = (lane & 8) ? 16u : 0u;

  load_chunk(0, 0);
  if (nk > 1) load_chunk(1, 1);
  for (int c = 0; c < nk; c++) {
    const int st = c - (c / 3) * 3;
    if (c + 1 < nk) CP_WAIT(1); else CP_WAIT(0);
    __syncthreads();
    if (c + 2 < nk) load_chunk(c + 2, (c + 2) - ((c + 2) / 3) * 3);
    const unsigned stb = sb + (unsigned)st * MMA_STG;
    #pragma unroll
    for (int ks = 0; ks < 2; ks++) {
      const unsigned kb = (unsigned)(ks << 5);
      unsigned ahf[4][4];
      #pragma unroll
      for (int mi = 0; mi < 4; mi++) {
        unsigned rowA = (unsigned)((wm + mi * 16 + ar) * 80);
        ldsm4(ahf[mi], stb + rowA + kb + aco);
      }
      #pragma unroll
      for (int nb = 0; nb < 4; nb++) {
        unsigned rowB = (unsigned)((wn + nb * 16 + bn) * 80);
        unsigned bhf[4];
        ldsm4(bhf, stb + 10240u + rowB + kb + bko);
        #pragma unroll
        for (int mi = 0; mi < 4; mi++) {
          #pragma unroll
          for (int half = 0; half < 2; half++) {
            mma16816(acc[mi][nb * 2 + half], ahf[mi], bhf[half * 2], bhf[half * 2 + 1]);
          }
        }
      }
    }
    __syncthreads();
  }

  #pragma unroll
  for (int mi = 0; mi < 4; mi++) {
    const int lr0 = wm + mi * 16 + (lane >> 2);
    const int gr0 = m0 + lr0;
    const bool st0 = !grouped || (gr0 < count);
    const bool st1 = !grouped || (gr0 + 8 < count);
    const size_t row0 = (size_t)((grouped ? sbase : 0) + gr0);
    if (mode == 1) {
      const int Nout = N >> 1;
      #pragma unroll
      for (int nt = 0; nt < 8; nt++) {
        const int col = n0 + wn + nt * 8 + ((lane & 3) << 1);
        const int j = col >> 1;
        float* d = acc[mi][nt];
        if (st0) Ch[row0 * Nout + j]       = __float2half_rn(siluf(d[0]) * d[1]);
        if (st1) Ch[(row0 + 8) * Nout + j] = __float2half_rn(siluf(d[2]) * d[3]);
      }
    } else if (mode == 2) {
      #pragma unroll
      for (int nt = 0; nt < 8; nt++) {
        const int col = n0 + wn + nt * 8 + ((lane & 3) << 1);
        float* d = acc[mi][nt];
        float2 r0 = *(const float2*)(Xres + row0 * N + col);
        float2 r1 = *(const float2*)(Xres + (row0 + 8) * N + col);
        *(float2*)(C + row0 * N + col)       = make_float2(r0.x + d[0], r0.y + d[1]);
        *(float2*)(C + (row0 + 8) * N + col) = make_float2(r1.x + d[2], r1.y + d[3]);
      }
    } else {
      #pragma unroll
      for (int nt = 0; nt < 8; nt++) {
        const int col = n0 + wn + nt * 8 + ((lane & 3) << 1);
        float* d = acc[mi][nt];
        if (st0) *(float2*)(C + row0 * N + col)       = make_float2(d[0], d[1]);
        if (st1) *(float2*)(C + (row0 + 8) * N + col) = make_float2(d[2], d[3]);
      }
    }
  }
}

// ---------------- RoPE + pack into per-head fp16 layouts ----------------
__global__ void rope_split_kernel(const float* __restrict__ qkv) {
  const int t = blockIdx.x, hh = blockIdx.y, i = threadIdx.x;
  if (hh < NH_ + NKV_) {
    const float* b;
    fp16* d;
    if (hh < NH_) {
      b = qkv + (size_t)t*QKVW_ + hh*HD_;
      d = g_q + ((size_t)hh*T_ + t) * HD_;
    } else {
      int k = hh - NH_;
      b = qkv + (size_t)t*QKVW_ + NH_*HD_ + k*HD_;
      d = g_k + ((size_t)k*T_ + t) * HD_;
    }
    float fr = powf(10000.f, -(float)(2*i) * (1.f/HD_));
    float ang = (float)t * fr;
    float sn, cs; sincosf(ang, &sn, &cs);
    float x1 = b[i], x2 = b[i+64];
    d[i]      = __float2half_rn(x1*cs - x2*sn);
    d[i + 64] = __float2half_rn(x2*cs + x1*sn);
  } else {
    int v = hh - NH_ - NKV_;
    const float* b = qkv + (size_t)t*QKVW_ + (NH_+NKV_)*HD_ + v*HD_;
    size_t o = ((size_t)v*T_ + t) * HD_;
    g_v[o + i]      = __float2half_rn(b[i]);
    g_v[o + i + 64] = __float2half_rn(b[i+64]);
  }
}

// ---------------- mma.sync flash attention (single fp16) ----------------
#define AT_RS  272
#define AT_QSZ (128*AT_RS)
#define AT_TSZ (64*AT_RS)
#define AT_SMEM (AT_QSZ + 2*2*AT_TSZ)   // 104448
__global__ void __launch_bounds__(256) attn_mma(fp16* __restrict__ out) {
  extern __shared__ char smc[];
  const int h = blockIdx.x;
  const int q0 = ((int)gridDim.y - 1 - (int)blockIdx.y) << 7;   // heavy tiles first
  const int kvh = h >> 2;
  const int tid = threadIdx.x, wid = tid >> 5, lane = tid & 31;
  const unsigned sb = smem_u32(smc);
  const unsigned KV_o = AT_QSZ;

  #pragma unroll
  for (int i = 0; i < 8; i++) {
    int s = tid + (i << 8);
    int r = (s >> 4) & 127, cq = s & 15;
    unsigned dst = sb + (unsigned)(r * AT_RS + cq * 16);
    const fp16* src = g_q + (((size_t)h*T_ + q0 + r) << 7) + cq*8;
    cp16(dst, src, true);
  }
  CP_COMMIT();

  auto load_kv = [&](int c, int st) {
    unsigned base = sb + KV_o + (unsigned)st * (2*AT_TSZ);
    #pragma unroll
    for (int i = 0; i < 8; i++) {
      int s = tid + (i << 8);
      int mat = s >> 10, r = (s >> 4) & 63, cq = s & 15;
      unsigned dst = base + (unsigned)mat * AT_TSZ + (unsigned)(r * AT_RS + cq * 16);
      const fp16* ap = (mat == 0) ? g_k : g_v;
      cp16(dst, ap + (((size_t)kvh*T_ + c*64 + r) << 7) + cq*8, true);
    }
    CP_COMMIT();
  };

  const int wr0 = wid << 4;
  const int rlo = q0 + wr0 + (lane >> 2);
  float m0 = -1e30f, m1 = -1e30f, l0 = 0.f, l1 = 0.f;
  float o[16][4];
  #pragma unroll
  for (int i = 0; i < 16; i++)
    #pragma unroll
    for (int j = 0; j < 4; j++) o[i][j] = 0.f;

  const int ntl = (q0 >> 6) + 2;
  load_kv(0, 0);

  const int ar  = lane & 15;
  const int aco = (lane >> 4) << 4;
  const int bnr = (lane & 7) + ((lane & 16) ? 8 : 0);
  const int bko = (lane & 8) ? 16 : 0;
  const float sc = 0.12751744f;                    // (1/sqrt(128)) * log2(e)

  for (int c = 0; c < ntl; c++) {
    const int st = c & 1;
    if (c + 1 < ntl) { load_kv(c + 1, st ^ 1); CP_WAIT(1); }
    else CP_WAIT(0);
    __syncthreads();
    const int s0 = c << 6;
    const bool active = (s0 <= q0 + wr0 + 15);
    if (active) {
      const unsigned kvb = sb + KV_o + (unsigned)st * (2*AT_TSZ);
      float s8[8][4];
      #pragma unroll
      for (int i = 0; i < 8; i++)
        #pragma unroll
        for (int j = 0; j < 4; j++) s8[i][j] = 0.f;
      #pragma unroll
      for (int kk = 0; kk < 8; kk++) {
        const unsigned qoff = (unsigned)((wr0 + ar) * AT_RS + kk * 32 + aco);
        unsigned ah[4];
        ldsm4(ah, sb + qoff);
        #pragma unroll
        for (int ntp = 0; ntp < 4; ntp++) {
          const unsigned koff = (unsigned)((bnr + ntp * 16) * AT_RS + kk * 32 + bko);
          unsigned bh[4];
          ldsm4(bh, kvb + koff);
          #pragma unroll
          for (int hf = 0; hf < 2; hf++)
            mma16816(s8[ntp * 2 + hf], ah, bh[hf*2], bh[hf*2+1]);
        }
      }
      #pragma unroll
      for (int nt = 0; nt < 8; nt++)
        #pragma unroll
        for (int j = 0; j < 4; j++) s8[nt][j] *= sc;
      if (s0 + 63 > q0 + wr0) {
        const int cb = s0 + ((lane & 3) << 1);
        #pragma unroll
        for (int nt = 0; nt < 8; nt++) {
          #pragma unroll
          for (int j = 0; j < 2; j++) {
            int col = cb + nt * 8 + j;
            if (col > rlo)     s8[nt][j]     = -1e30f;
            if (col > rlo + 8) s8[nt][j + 2] = -1e30f;
          }
        }
      }
      float tm0 = -1e30f, tm1 = -1e30f;
      #pragma unroll
      for (int nt = 0; nt < 8; nt++) {
        tm0 = fmaxf(tm0, fmaxf(s8[nt][0], s8[nt][1]));
        tm1 = fmaxf(tm1, fmaxf(s8[nt][2], s8[nt][3]));
      }
      tm0 = fmaxf(tm0, __shfl_xor_sync(0xffffffffu, tm0, 1));
      tm0 = fmaxf(tm0, __shfl_xor_sync(0xffffffffu, tm0, 2));
      tm1 = fmaxf(tm1, __shfl_xor_sync(0xffffffffu, tm1, 1));
      tm1 = fmaxf(tm1, __shfl_xor_sync(0xffffffffu, tm1, 2));
      const float mn0 = fmaxf(m0, tm0), mn1 = fmaxf(m1, tm1);
      const float aa0 = fexp2(m0 - mn0), aa1 = fexp2(m1 - mn1);
      m0 = mn0; m1 = mn1;
      float ts0 = 0.f, ts1 = 0.f;
      unsigned pH[4][4];
      #pragma unroll
      for (int kc = 0; kc < 4; kc++) {
        float e00 = fexp2(s8[2*kc][0]   - m0), e01 = fexp2(s8[2*kc][1]   - m0);
        float e02 = fexp2(s8[2*kc][2]   - m1), e03 = fexp2(s8[2*kc][3]   - m1);
        float e10 = fexp2(s8[2*kc+1][0] - m0), e11 = fexp2(s8[2*kc+1][1] - m0);
        float e12 = fexp2(s8[2*kc+1][2] - m1), e13 = fexp2(s8[2*kc+1][3] - m1);
        ts0 += e00 + e01 + e10 + e11;
        ts1 += e02 + e03 + e12 + e13;
        pH[kc][0] = pack_h2(e00, e01);
        pH[kc][1] = pack_h2(e02, e03);
        pH[kc][2] = pack_h2(e10, e11);
        pH[kc][3] = pack_h2(e12, e13);
      }
      ts0 += __shfl_xor_sync(0xffffffffu, ts0, 1);
      ts0 += __shfl_xor_sync(0xffffffffu, ts0, 2);
      ts1 += __shfl_xor_sync(0xffffffffu, ts1, 1);
      ts1 += __shfl_xor_sync(0xffffffffu, ts1, 2);
      l0 = l0 * aa0 + ts0;
      l1 = l1 * aa1 + ts1;
      #pragma unroll
      for (int nt = 0; nt < 16; nt++) {
        o[nt][0] *= aa0; o[nt][1] *= aa0;
        o[nt][2] *= aa1; o[nt][3] *= aa1;
      }
      #pragma unroll
      for (int kc = 0; kc < 4; kc++) {
        #pragma unroll
        for (int ntp = 0; ntp < 8; ntp++) {
          const unsigned voff = (unsigned)((kc * 16 + ar) * AT_RS + ntp * 32 + aco);
          unsigned vh[4];
          ldsm4t(vh, kvb + AT_TSZ + voff);
          #pragma unroll
          for (int hf = 0; hf < 2; hf++)
            mma16816(o[ntp * 2 + hf], pH[kc], vh[hf*2], vh[hf*2+1]);
        }
      }
    }
    __syncthreads();
  }

  const float inv0 = 1.f / l0, inv1 = 1.f / l1;
  #pragma unroll
  for (int nt = 0; nt < 16; nt++) {
    const int col = h * HD_ + nt * 8 + ((lane & 3) << 1);
    size_t b0 = (size_t)rlo * H_ + col;
    size_t b1 = (size_t)(rlo + 8) * H_ + col;
    *(unsigned*)(out + b0) = pack_h2(o[nt][0] * inv0, o[nt][1] * inv0);
    *(unsigned*)(out + b1) = pack_h2(o[nt][2] * inv1, o[nt][3] * inv1);
  }
}

// ---------------- gating + routing ----------------
__global__ void __launch_bounds__(256) gate_kernel(const float* __restrict__ gw) {
  const int t = blockIdx.x;
  __shared__ float part[256];
  const int tid = threadIdx.x;
  const int e = tid & 15, c = tid >> 4;
  const fp16* xh = g_h3n + (size_t)t*H_;
  float s = 0.f;
  for (int h = c*128; h < c*128+128; h++)
    s += __half2float(xh[h]) * gw[h*E_ + e];
  part[tid] = s;
  __syncthreads();
  if (tid == 0) {
    float lg[16];
    for (int ee=0; ee<16; ee++){ float v=0.f; for (int cc=0; cc<16; cc++) v += part[cc*16+ee]; lg[ee]=v; }
    int i1 = 0;
    for (int ee=1; ee<16; ee++) if (lg[ee] > lg[i1]) i1 = ee;
    int i2 = (i1==0) ? 1 : 0;
    for (int ee=0; ee<16; ee++) if (ee!=i1 && lg[ee] > lg[i2]) i2 = ee;
    float mx = lg[i1];
    float p1 = expf(lg[i1]-mx), p2 = expf(lg[i2]-mx);
    float d = p1 + p2;
    g_topi[t*2]=i1; g_topi[t*2+1]=i2;
    g_topw[t*2]=p1/d; g_topw[t*2+1]=p2/d;
  }
}

__global__ void moe_zero_kernel(){ if (threadIdx.x < E_){ g_cnt[threadIdx.x]=0; g_cur[threadIdx.x]=0; } }
__global__ void moe_count_kernel(){ int i = blockIdx.x*256+threadIdx.x; if (i < P_) atomicAdd(&g_cnt[g_topi[i]], 1); }
__global__ void moe_scan_kernel(){ if (threadIdx.x==0){ int o=0; for (int e=0;e<E_;e++){ g_off[e]=o; o+=g_cnt[e]; } } }
__global__ void moe_scatter_kernel(){
  int i = blockIdx.x*256+threadIdx.x;
  if (i < P_) {
    int e = g_topi[i];
    int pos = g_off[e] + atomicAdd(&g_cur[e], 1);
    g_ptok[pos] = i >> 1;
    g_pslot[i]  = pos;
  }
}

// ---------------- final combine ----------------
__global__ void final_kernel(float* __restrict__ out) {
  const int t = blockIdx.x;
  const int p0 = g_pslot[t*2], p1 = g_pslot[t*2+1];
  const float w0 = g_topw[t*2], w1 = g_topw[t*2+1];
  const float4* ra = (const float4*)(g_resat + (size_t)t*H_);
  const float4* ml = (const float4*)(g_mlp   + (size_t)t*H_);
  const float4* y0 = (const float4*)(g_ym    + (size_t)p0*H_);
  const float4* y1 = (const float4*)(g_ym    + (size_t)p1*H_);
  float4* op = (float4*)(out + (size_t)t*H_);
  for (int i = threadIdx.x; i < 512; i += 256) {
    float4 A=ra[i], B=ml[i], C=y0[i], D=y1[i];
    op[i] = make_float4(A.x+B.x+w0*C.x+w1*D.x, A.y+B.y+w0*C.y+w1*D.y,
                        A.z+B.z+w0*C.z+w1*D.z, A.w+B.w+w0*C.w+w1*D.w);
  }
}

// ---------------- host ----------------
extern "C" void kernel_launch(void* const* d_in, const int* in_sizes, int n_in,
                              void* d_out, int out_size) {
  (void)in_sizes; (void)n_in; (void)out_size;
  const float* x      = (const float*)d_in[0];
  const float* ln_in  = (const float*)d_in[1];
  const float* ln_post= (const float*)d_in[2];
  const float* ln_res = (const float*)d_in[3];
  const float* wqkv   = (const float*)d_in[4];
  const float* wo     = (const float*)d_in[5];
  const float* w13    = (const float*)d_in[6];
  const float* w2     = (const float*)d_in[7];
  const float* gw     = (const float*)d_in[8];
  const float* ws     = (const float*)d_in[9];
  const float* w2s    = (const float*)d_in[10];
  float* out = (float*)d_out;

  float *qkv,*resat,*mlp,*ym;
  cudaGetSymbolAddress((void**)&qkv,  g_qkv);
  cudaGetSymbolAddress((void**)&resat,g_resat);
  cudaGetSymbolAddress((void**)&mlp,  g_mlp);
  cudaGetSymbolAddress((void**)&ym,   g_ym);

  fp16 *xn,*attn,*h2n,*hmid,*h3n,*hmm;
  cudaGetSymbolAddress((void**)&xn,   g_xn);
  cudaGetSymbolAddress((void**)&attn, g_attn);
  cudaGetSymbolAddress((void**)&h2n,  g_h2n);
  cudaGetSymbolAddress((void**)&hmid, g_hmid);
  cudaGetSymbolAddress((void**)&h3n,  g_h3n);
  cudaGetSymbolAddress((void**)&hmm,  g_hmm);

  fp16 *wq,*wo16,*w1316,*w216,*ws16,*w2s16;
  cudaGetSymbolAddress((void**)&wq,    g_wqkvT);
  cudaGetSymbolAddress((void**)&wo16,  g_woT);
  cudaGetSymbolAddress((void**)&w1316, g_w13T);
  cudaGetSymbolAddress((void**)&w216,  g_w2T);
  cudaGetSymbolAddress((void**)&ws16,  g_ws);
  cudaGetSymbolAddress((void**)&w2s16, g_w2s);

  cudaFuncSetAttribute(mma_gemm, cudaFuncAttributeMaxDynamicSharedMemorySize, MMA_SMEM);
  cudaFuncSetAttribute(attn_mma, cudaFuncAttributeMaxDynamicSharedMemorySize, AT_SMEM);

  // fork a side stream for the MoE branch (host objects only; created on the
  // 2 host invocations — capture replays never rerun this code). Leaked on purpose.
  cudaStream_t s1;
  cudaStreamCreateWithFlags(&s1, cudaStreamNonBlocking);
  cudaEvent_t evFork, evW, evJoin;
  cudaEventCreateWithFlags(&evFork, cudaEventDisableTiming);
  cudaEventCreateWithFlags(&evW,    cudaEventDisableTiming);
  cudaEventCreateWithFlags(&evJoin, cudaEventDisableTiming);

  cudaEventRecord(evFork, 0);
  cudaStreamWaitEvent(s1, evFork, 0);

  // ---- side stream: small transposes, MoE weight prep + whole MoE branch ----
  transpose_h<<<dim3(H_/32,   H_/32), 256, 0, s1>>>(wo,  wo16,  H_, H_, 0);
  transpose_h<<<dim3(2*H_/32, H_/32), 256, 0, s1>>>(w13, w1316, H_, 2*H_, 1);
  transpose_h<<<dim3(H_/32,   H_/32), 256, 0, s1>>>(w2,  w216,  H_, H_, 0);
  cudaEventRecord(evW, s1);
  convert_ws_int<<<(E_*2*I_*H_)/2048, 256, 0, s1>>>(ws, ws16);
  convert_h8<<<(E_*H_*I_)/2048, 256, 0, s1>>>(w2s, w2s16);
  rmsnorm_h<<<T_, 256, 0, s1>>>(x, ln_post, h3n);
  gate_kernel<<<T_, 256, 0, s1>>>(gw);
  moe_zero_kernel<<<1, 32, 0, s1>>>();
  moe_count_kernel<<<P_/256, 256, 0, s1>>>();
  moe_scan_kernel<<<1, 32, 0, s1>>>();
  moe_scatter_kernel<<<P_/256, 256, 0, s1>>>();
  mma_gemm<<<dim3(2*I_/256, T_/128, E_), 256, MMA_SMEM, s1>>>(h3n, ws16, nullptr, hmm, nullptr, 2*I_, H_, 1, 1);
  mma_gemm<<<dim3(H_/256, T_/128, E_), 256, MMA_SMEM, s1>>>(hmm, w2s16, ym, nullptr, nullptr, H_, I_, 2, 0);
  cudaEventRecord(evJoin, s1);

  // ---- main stream: attention chain + residual MLP ----
  transpose_h<<<dim3(QKVW_/32, H_/32), 256>>>(wqkv, wq, H_, QKVW_, 0);
  rmsnorm_h<<<T_, 256>>>(x, ln_in, xn);
  mma_gemm<<<dim3(QKVW_/256, T_/128, 1), 256, MMA_SMEM>>>(xn, wq, qkv, nullptr, nullptr, QKVW_, H_, 0, 0);
  rope_split_kernel<<<dim3(T_, NH_ + 2*NKV_), 64>>>(qkv);
  attn_mma<<<dim3(NH_, T_/128), 256, AT_SMEM>>>(attn);
  cudaStreamWaitEvent(0, evW, 0);
  mma_gemm<<<dim3(H_/256, T_/128, 1), 256, MMA_SMEM>>>(attn, wo16, resat, nullptr, x, H_, H_, 0, 2);
  rmsnorm_h<<<T_, 256>>>(resat, ln_res, h2n);
  mma_gemm<<<dim3(2*H_/256, T_/128, 1), 256, MMA_SMEM>>>(h2n, w1316, nullptr, hmid, nullptr, 2*H_, H_, 0, 1);
  mma_gemm<<<dim3(H_/256, T_/128, 1), 256, MMA_SMEM>>>(hmid, w216, mlp, nullptr, nullptr, H_, H_, 0, 0);

  // ---- join + combine ----
  cudaStreamWaitEvent(0, evJoin, 0);
  final_kernel<<<T_, 256>>>(out);
}

// round 13
// speedup vs baseline: 7.4130x; 1.1661x over previous
#include <cuda_runtime.h>
#include <cuda_fp16.h>
#include <math.h>

#define T_ 2048
#define H_ 2048
#define NH_ 16
#define NKV_ 4
#define HD_ 128
#define I_ 1024
#define E_ 16
#define TOPK_ 2
#define P_ (T_*TOPK_)
#define QKVW_ 3072

typedef __half fp16;

// ---------------- scratch (device globals; no allocations allowed) ----------------
__device__ float g_resat[T_*H_];
__device__ float g_mlp[T_*H_];
__device__ float g_ym[P_*H_];

__device__ fp16 g_qkvh[T_*QKVW_];
__device__ fp16 g_xn[T_*H_];
__device__ fp16 g_attn[T_*H_];
__device__ fp16 g_h2n[T_*H_];
__device__ fp16 g_hmid[T_*H_];
__device__ fp16 g_h3n[T_*H_];
__device__ fp16 g_hmm[P_*I_];

__device__ fp16 g_q[NH_*T_*HD_];
__device__ fp16 g_k[NKV_*T_*HD_];
__device__ fp16 g_v[NKV_*T_*HD_];

__device__ fp16 g_wqkvT[QKVW_*H_];
__device__ fp16 g_woT[H_*H_];
__device__ fp16 g_w13T[2*H_*H_];     // gate/up interleaved rows
__device__ fp16 g_w2T[H_*H_];
__device__ fp16 g_ws[E_*2*I_*H_];    // gate/up interleaved rows per expert
__device__ fp16 g_w2s[E_*H_*I_];

__device__ int   g_topi[P_];
__device__ float g_topw[P_];
__device__ int   g_cnt[E_];
__device__ int   g_off[E_];
__device__ int   g_cur[E_];
__device__ int   g_ptok[P_];
__device__ int   g_pslot[P_];

// ---------------- ptx helpers (base compute_103-safe) ----------------
__device__ __forceinline__ unsigned smem_u32(const void* p) {
  unsigned a;
  asm("{ .reg .u64 t; cvta.to.shared.u64 t, %1; cvt.u32.u64 %0, t; }" : "=r"(a) : "l"(p));
  return a;
}
__device__ __forceinline__ void cp16(unsigned dst, const void* src, bool valid) {
  int sz = valid ? 16 : 0;
  asm volatile("cp.async.cg.shared.global [%0], [%1], 16, %2;"
               :: "r"(dst), "l"(src), "r"(sz) : "memory");
}
#define CP_COMMIT() asm volatile("cp.async.commit_group;" ::: "memory")
#define CP_WAIT(n)  asm volatile("cp.async.wait_group %0;" :: "n"(n) : "memory")

__device__ __forceinline__ void ldsm4(unsigned* r, unsigned addr) {
  asm volatile("ldmatrix.sync.aligned.m8n8.x4.shared.b16 {%0,%1,%2,%3}, [%4];"
               : "=r"(r[0]), "=r"(r[1]), "=r"(r[2]), "=r"(r[3]) : "r"(addr));
}
__device__ __forceinline__ void ldsm4t(unsigned* r, unsigned addr) {
  asm volatile("ldmatrix.sync.aligned.m8n8.x4.trans.shared.b16 {%0,%1,%2,%3}, [%4];"
               : "=r"(r[0]), "=r"(r[1]), "=r"(r[2]), "=r"(r[3]) : "r"(addr));
}
__device__ __forceinline__ void mma16816(float* d, const unsigned* a, unsigned b0, unsigned b1) {
  asm volatile("mma.sync.aligned.m16n8k16.row.col.f32.f16.f16.f32 "
               "{%0,%1,%2,%3}, {%4,%5,%6,%7}, {%8,%9}, {%0,%1,%2,%3};"
               : "+f"(d[0]), "+f"(d[1]), "+f"(d[2]), "+f"(d[3])
               : "r"(a[0]), "r"(a[1]), "r"(a[2]), "r"(a[3]), "r"(b0), "r"(b1));
}

// fast 2^y on the FMA pipe (y in [-1e30, 0]); rel err < 3e-6
__device__ __forceinline__ float fexp2(float y) {
  y = fmaxf(y, -120.f);
  float z = y + 12582912.0f;
  int   n = __float_as_int(z) - 0x4B400000;
  float f = y - (z - 12582912.0f);
  float p = 0.0013333558f;
  p = fmaf(p, f, 0.0096181291f);
  p = fmaf(p, f, 0.0555041087f);
  p = fmaf(p, f, 0.2402265069f);
  p = fmaf(p, f, 0.6931471806f);
  p = fmaf(p, f, 1.0f);
  return p * __int_as_float((n + 127) << 23);
}

__device__ __forceinline__ unsigned pack_h2(float a, float b) {
  __half2 t = __floats2half2_rn(a, b);
  return *(unsigned*)&t;
}
__device__ __forceinline__ void store_h4(float4 v, fp16* p) {
  fp16 h[4] = {__float2half_rn(v.x), __float2half_rn(v.y), __float2half_rn(v.z), __float2half_rn(v.w)};
  *(uint2*)p = *(uint2*)h;
}
__device__ __forceinline__ float siluf(float g){ return g / (1.f + __expf(-g)); }

// ---------------- weight prep ----------------
__global__ void __launch_bounds__(256) convert_ws_int(const float* __restrict__ in, fp16* __restrict__ o) {
  size_t idx = (size_t)blockIdx.x * 256 + threadIdx.x;
  size_t r = idx >> 8;
  int h0 = (int)(idx & 255) << 3;
  int e = (int)(r >> 11);
  int k = (int)(r & 2047);
  int srcr = e * 2 * I_ + ((k & 1) ? I_ + (k >> 1) : (k >> 1));
  const float4* s = (const float4*)(in + (size_t)srcr * H_ + h0);
  float4 a = s[0], b = s[1];
  fp16 hb[8] = {__float2half_rn(a.x), __float2half_rn(a.y), __float2half_rn(a.z), __float2half_rn(a.w),
                __float2half_rn(b.x), __float2half_rn(b.y), __float2half_rn(b.z), __float2half_rn(b.w)};
  *(uint4*)(o + r * H_ + h0) = *(uint4*)hb;
}

__global__ void __launch_bounds__(256) convert_h8(const float* __restrict__ in, fp16* __restrict__ o) {
  size_t i = ((size_t)blockIdx.x * 256 + threadIdx.x) << 3;
  const float4* s = (const float4*)(in + i);
  float4 a = s[0], b = s[1];
  fp16 hb[8] = {__float2half_rn(a.x), __float2half_rn(a.y), __float2half_rn(a.z), __float2half_rn(a.w),
                __float2half_rn(b.x), __float2half_rn(b.y), __float2half_rn(b.z), __float2half_rn(b.w)};
  *(uint4*)(o + i) = *(uint4*)hb;
}

// transpose: in[K][N] fp32 -> o [N][K] fp16; il=1 interleaves gate/up dest rows.
__global__ void __launch_bounds__(256) transpose_h(const float* __restrict__ in, fp16* __restrict__ o,
                                                   int K, int N, int il) {
  __shared__ float t[32][33];
  int k0 = blockIdx.y * 32, n0 = blockIdx.x * 32;
  int tx = threadIdx.x & 31, ty = threadIdx.x >> 5;
  #pragma unroll
  for (int j = 0; j < 4; j++)
    t[ty + 8 * j][tx] = in[(size_t)(k0 + ty + 8 * j) * N + n0 + tx];
  __syncthreads();
  int half = N >> 1;
  #pragma unroll
  for (int j = 0; j < 4; j++) {
    int n = n0 + ty + 8 * j;
    int dr = il ? ((n < half) ? 2 * n : 2 * (n - half) + 1) : n;
    o[(size_t)dr * K + k0 + tx] = __float2half_rn(t[tx][ty + 8 * j]);
  }
}

// ---------------- RMSNorm: one block per token, emits fp16 ----------------
__global__ void __launch_bounds__(256) rmsnorm_h(const float* __restrict__ x,
                                                 const float* __restrict__ w,
                                                 fp16* __restrict__ o) {
  const int t = blockIdx.x;
  const float4* xr = (const float4*)(x + (size_t)t * H_);
  const float4* wr = (const float4*)w;
  const int i0 = threadIdx.x, i1 = threadIdx.x + 256;
  float4 v0 = xr[i0], v1 = xr[i1];
  float s = v0.x*v0.x+v0.y*v0.y+v0.z*v0.z+v0.w*v0.w
          + v1.x*v1.x+v1.y*v1.y+v1.z*v1.z+v1.w*v1.w;
  #pragma unroll
  for (int off = 16; off; off >>= 1) s += __shfl_xor_sync(0xffffffffu, s, off);
  __shared__ float red[8];
  __shared__ float sinv;
  if ((threadIdx.x & 31) == 0) red[threadIdx.x >> 5] = s;
  __syncthreads();
  if (threadIdx.x == 0) {
    float tt = 0.f;
    #pragma unroll
    for (int k = 0; k < 8; k++) tt += red[k];
    sinv = rsqrtf(tt * (1.f / H_) + 1e-5f);
  }
  __syncthreads();
  float r = sinv;
  float4 w0 = wr[i0], w1 = wr[i1];
  float4 o0, o1;
  o0.x=v0.x*r*w0.x; o0.y=v0.y*r*w0.y; o0.z=v0.z*r*w0.z; o0.w=v0.w*r*w0.w;
  o1.x=v1.x*r*w1.x; o1.y=v1.y*r*w1.y; o1.z=v1.z*r*w1.z; o1.w=v1.w*r*w1.w;
  size_t base = (size_t)t * H_;
  store_h4(o0, o + base + i0 * 4);
  store_h4(o1, o + base + i1 * 4);
}

// ---------------- mma.sync fp16 GEMM with fused epilogues ----------------
// CTA tile 128x128, 8 warps (2m x 4n), warp tile 64x32, K-chunk 32, 3-stage cp.async.
// 2 CTAs/SM (stage 20KB x3 = 61440B + rowmap).
// mode 0: fp32 to C. mode 1: gate/up interleaved -> silu(g)*u fp16 to Ch (Nout=N/2).
// mode 2: C = Xres + acc (fp32, dense). mode 3: fp16 to Ch.
#define MMA_STG 20480
#define MMA_SMEM (3*MMA_STG + 512)
__global__ void __launch_bounds__(256, 2) mma_gemm(const fp16* __restrict__ A,
                                                   const fp16* __restrict__ B,
                                                   float* __restrict__ C,
                                                   fp16* __restrict__ Ch,
                                                   const float* __restrict__ Xres,
                                                   int N, int K, int grouped, int mode) {
  extern __shared__ char smem[];
  const int tid = threadIdx.x, wid = tid >> 5, lane = tid & 31;
  const int e = blockIdx.z;
  int count = 0, sbase = 0;
  if (grouped) {
    count = g_cnt[e];
    if ((int)(blockIdx.y << 7) >= count) return;
    sbase = g_off[e];
  }
  const fp16* BE = B + (size_t)e * N * K;
  const int m0 = blockIdx.y << 7, n0 = blockIdx.x << 7;
  unsigned sb = smem_u32(smem);
  int* rowmap = (int*)(smem + 3*MMA_STG);

  if (tid < 128) {
    int gr = m0 + tid;
    if (grouped) {
      if (m0 + tid < count) {
        int slot = sbase + m0 + tid;
        gr = (grouped == 1) ? g_ptok[slot] : slot;
      } else gr = -1;
    }
    rowmap[tid] = gr;
  }
  __syncthreads();

  const int nk = K >> 5;
  auto load_chunk = [&](int c, int st) {
    unsigned base = sb + (unsigned)st * MMA_STG;
    #pragma unroll
    for (int i = 0; i < 4; i++) {              // A+B: 1024 cp16
      int s = tid + (i << 8);
      int mat = s >> 9, r = (s >> 2) & 127, cq = s & 3;
      unsigned dst = base + (unsigned)mat * 10240u + (unsigned)(r * 80 + cq * 16);
      const fp16* src;
      bool valid = true;
      if (mat == 0) {
        int gr = rowmap[r];
        valid = (gr >= 0);
        if (!valid) gr = 0;
        src = A + (size_t)gr * K + (c << 5) + (cq << 3);
      } else {
        src = BE + (size_t)(n0 + r) * K + (c << 5) + (cq << 3);
      }
      cp16(dst, src, valid);
    }
    CP_COMMIT();
  };

  float acc[4][4][4];
  #pragma unroll
  for (int i = 0; i < 4; i++)
    #pragma unroll
    for (int j = 0; j < 4; j++)
      #pragma unroll
      for (int k = 0; k < 4; k++) acc[i][j][k] = 0.f;

  const int wm = (wid >> 2) << 6;           // 0 or 64
  const int wn = (wid & 3) << 5;            // 0,32,64,96
  const int ar  = lane & 15;
  const unsigned aco = (lane & 16) ? 16u : 0u;
  const int bn  = (lane & 7) + ((lane & 16) ? 8 : 0);
  const unsigned bko = (lane & 8) ? 16u : 0u;

  load_chunk(0, 0);
  if (nk > 1) load_chunk(1, 1);
  for (int c = 0; c < nk; c++) {
    const int st = c - (c / 3) * 3;
    if (c + 1 < nk) CP_WAIT(1); else CP_WAIT(0);
    __syncthreads();
    if (c + 2 < nk) load_chunk(c + 2, (c + 2) - ((c + 2) / 3) * 3);
    const unsigned stb = sb + (unsigned)st * MMA_STG;
    #pragma unroll
    for (int ks = 0; ks < 2; ks++) {
      const unsigned kb = (unsigned)(ks << 5);
      unsigned ahf[4][4];
      #pragma unroll
      for (int mi = 0; mi < 4; mi++) {
        unsigned rowA = (unsigned)((wm + mi * 16 + ar) * 80);
        ldsm4(ahf[mi], stb + rowA + kb + aco);
      }
      #pragma unroll
      for (int nb = 0; nb < 2; nb++) {
        unsigned rowB = (unsigned)((wn + nb * 16 + bn) * 80);
        unsigned bhf[4];
        ldsm4(bhf, stb + 10240u + rowB + kb + bko);
        #pragma unroll
        for (int mi = 0; mi < 4; mi++) {
          #pragma unroll
          for (int half = 0; half < 2; half++) {
            mma16816(acc[mi][nb * 2 + half], ahf[mi], bhf[half * 2], bhf[half * 2 + 1]);
          }
        }
      }
    }
    __syncthreads();
  }

  #pragma unroll
  for (int mi = 0; mi < 4; mi++) {
    const int lr0 = wm + mi * 16 + (lane >> 2);
    const int gr0 = m0 + lr0;
    const bool st0 = !grouped || (gr0 < count);
    const bool st1 = !grouped || (gr0 + 8 < count);
    const size_t row0 = (size_t)((grouped ? sbase : 0) + gr0);
    if (mode == 1) {
      const int Nout = N >> 1;
      #pragma unroll
      for (int nt = 0; nt < 4; nt++) {
        const int col = n0 + wn + nt * 8 + ((lane & 3) << 1);
        const int j = col >> 1;
        float* d = acc[mi][nt];
        if (st0) Ch[row0 * Nout + j]       = __float2half_rn(siluf(d[0]) * d[1]);
        if (st1) Ch[(row0 + 8) * Nout + j] = __float2half_rn(siluf(d[2]) * d[3]);
      }
    } else if (mode == 2) {
      #pragma unroll
      for (int nt = 0; nt < 4; nt++) {
        const int col = n0 + wn + nt * 8 + ((lane & 3) << 1);
        float* d = acc[mi][nt];
        float2 r0 = *(const float2*)(Xres + row0 * N + col);
        float2 r1 = *(const float2*)(Xres + (row0 + 8) * N + col);
        *(float2*)(C + row0 * N + col)       = make_float2(r0.x + d[0], r0.y + d[1]);
        *(float2*)(C + (row0 + 8) * N + col) = make_float2(r1.x + d[2], r1.y + d[3]);
      }
    } else if (mode == 3) {
      #pragma unroll
      for (int nt = 0; nt < 4; nt++) {
        const int col = n0 + wn + nt * 8 + ((lane & 3) << 1);
        float* d = acc[mi][nt];
        if (st0) *(unsigned*)(Ch + row0 * N + col)       = pack_h2(d[0], d[1]);
        if (st1) *(unsigned*)(Ch + (row0 + 8) * N + col) = pack_h2(d[2], d[3]);
      }
    } else {
      #pragma unroll
      for (int nt = 0; nt < 4; nt++) {
        const int col = n0 + wn + nt * 8 + ((lane & 3) << 1);
        float* d = acc[mi][nt];
        if (st0) *(float2*)(C + row0 * N + col)       = make_float2(d[0], d[1]);
        if (st1) *(float2*)(C + (row0 + 8) * N + col) = make_float2(d[2], d[3]);
      }
    }
  }
}

// ---------------- RoPE + pack into per-head fp16 layouts (fp16 input) ----------------
__global__ void rope_split_kernel(const fp16* __restrict__ qkv) {
  const int t = blockIdx.x, hh = blockIdx.y, i = threadIdx.x;
  if (hh < NH_ + NKV_) {
    const fp16* b;
    fp16* d;
    if (hh < NH_) {
      b = qkv + (size_t)t*QKVW_ + hh*HD_;
      d = g_q + ((size_t)hh*T_ + t) * HD_;
    } else {
      int k = hh - NH_;
      b = qkv + (size_t)t*QKVW_ + NH_*HD_ + k*HD_;
      d = g_k + ((size_t)k*T_ + t) * HD_;
    }
    float fr = powf(10000.f, -(float)(2*i) * (1.f/HD_));
    float ang = (float)t * fr;
    float sn, cs; sincosf(ang, &sn, &cs);
    float x1 = __half2float(b[i]), x2 = __half2float(b[i+64]);
    d[i]      = __float2half_rn(x1*cs - x2*sn);
    d[i + 64] = __float2half_rn(x2*cs + x1*sn);
  } else {
    int v = hh - NH_ - NKV_;
    const fp16* b = qkv + (size_t)t*QKVW_ + (NH_+NKV_)*HD_ + v*HD_;
    size_t o = ((size_t)v*T_ + t) * HD_;
    g_v[o + i]      = b[i];
    g_v[o + i + 64] = b[i+64];
  }
}

// ---------------- mma.sync flash attention (single fp16) ----------------
#define AT_RS  272
#define AT_QSZ (128*AT_RS)
#define AT_TSZ (64*AT_RS)
#define AT_SMEM (AT_QSZ + 2*2*AT_TSZ)   // 104448
__global__ void __launch_bounds__(256) attn_mma(fp16* __restrict__ out) {
  extern __shared__ char smc[];
  const int h = blockIdx.x;
  const int q0 = ((int)gridDim.y - 1 - (int)blockIdx.y) << 7;   // heavy tiles first
  const int kvh = h >> 2;
  const int tid = threadIdx.x, wid = tid >> 5, lane = tid & 31;
  const unsigned sb = smem_u32(smc);
  const unsigned KV_o = AT_QSZ;

  #pragma unroll
  for (int i = 0; i < 8; i++) {
    int s = tid + (i << 8);
    int r = (s >> 4) & 127, cq = s & 15;
    unsigned dst = sb + (unsigned)(r * AT_RS + cq * 16);
    const fp16* src = g_q + (((size_t)h*T_ + q0 + r) << 7) + cq*8;
    cp16(dst, src, true);
  }
  CP_COMMIT();

  auto load_kv = [&](int c, int st) {
    unsigned base = sb + KV_o + (unsigned)st * (2*AT_TSZ);
    #pragma unroll
    for (int i = 0; i < 8; i++) {
      int s = tid + (i << 8);
      int mat = s >> 10, r = (s >> 4) & 63, cq = s & 15;
      unsigned dst = base + (unsigned)mat * AT_TSZ + (unsigned)(r * AT_RS + cq * 16);
      const fp16* ap = (mat == 0) ? g_k : g_v;
      cp16(dst, ap + (((size_t)kvh*T_ + c*64 + r) << 7) + cq*8, true);
    }
    CP_COMMIT();
  };

  const int wr0 = wid << 4;
  const int rlo = q0 + wr0 + (lane >> 2);
  float m0 = -1e30f, m1 = -1e30f, l0 = 0.f, l1 = 0.f;
  float o[16][4];
  #pragma unroll
  for (int i = 0; i < 16; i++)
    #pragma unroll
    for (int j = 0; j < 4; j++) o[i][j] = 0.f;

  const int ntl = (q0 >> 6) + 2;
  load_kv(0, 0);

  const int ar  = lane & 15;
  const int aco = (lane >> 4) << 4;
  const int bnr = (lane & 7) + ((lane & 16) ? 8 : 0);
  const int bko = (lane & 8) ? 16 : 0;
  const float sc = 0.12751744f;                    // (1/sqrt(128)) * log2(e)

  for (int c = 0; c < ntl; c++) {
    const int st = c & 1;
    if (c + 1 < ntl) { load_kv(c + 1, st ^ 1); CP_WAIT(1); }
    else CP_WAIT(0);
    __syncthreads();
    const int s0 = c << 6;
    const bool active = (s0 <= q0 + wr0 + 15);
    if (active) {
      const unsigned kvb = sb + KV_o + (unsigned)st * (2*AT_TSZ);
      float s8[8][4];
      #pragma unroll
      for (int i = 0; i < 8; i++)
        #pragma unroll
        for (int j = 0; j < 4; j++) s8[i][j] = 0.f;
      #pragma unroll
      for (int kk = 0; kk < 8; kk++) {
        const unsigned qoff = (unsigned)((wr0 + ar) * AT_RS + kk * 32 + aco);
        unsigned ah[4];
        ldsm4(ah, sb + qoff);
        #pragma unroll
        for (int ntp = 0; ntp < 4; ntp++) {
          const unsigned koff = (unsigned)((bnr + ntp * 16) * AT_RS + kk * 32 + bko);
          unsigned bh[4];
          ldsm4(bh, kvb + koff);
          #pragma unroll
          for (int hf = 0; hf < 2; hf++)
            mma16816(s8[ntp * 2 + hf], ah, bh[hf*2], bh[hf*2+1]);
        }
      }
      #pragma unroll
      for (int nt = 0; nt < 8; nt++)
        #pragma unroll
        for (int j = 0; j < 4; j++) s8[nt][j] *= sc;
      if (s0 + 63 > q0 + wr0) {
        const int cb = s0 + ((lane & 3) << 1);
        #pragma unroll
        for (int nt = 0; nt < 8; nt++) {
          #pragma unroll
          for (int j = 0; j < 2; j++) {
            int col = cb + nt * 8 + j;
            if (col > rlo)     s8[nt][j]     = -1e30f;
            if (col > rlo + 8) s8[nt][j + 2] = -1e30f;
          }
        }
      }
      float tm0 = -1e30f, tm1 = -1e30f;
      #pragma unroll
      for (int nt = 0; nt < 8; nt++) {
        tm0 = fmaxf(tm0, fmaxf(s8[nt][0], s8[nt][1]));
        tm1 = fmaxf(tm1, fmaxf(s8[nt][2], s8[nt][3]));
      }
      tm0 = fmaxf(tm0, __shfl_xor_sync(0xffffffffu, tm0, 1));
      tm0 = fmaxf(tm0, __shfl_xor_sync(0xffffffffu, tm0, 2));
      tm1 = fmaxf(tm1, __shfl_xor_sync(0xffffffffu, tm1, 1));
      tm1 = fmaxf(tm1, __shfl_xor_sync(0xffffffffu, tm1, 2));
      const float mn0 = fmaxf(m0, tm0), mn1 = fmaxf(m1, tm1);
      const float aa0 = fexp2(m0 - mn0), aa1 = fexp2(m1 - mn1);
      m0 = mn0; m1 = mn1;
      float ts0 = 0.f, ts1 = 0.f;
      unsigned pH[4][4];
      #pragma unroll
      for (int kc = 0; kc < 4; kc++) {
        float e00 = fexp2(s8[2*kc][0]   - m0), e01 = fexp2(s8[2*kc][1]   - m0);
        float e02 = fexp2(s8[2*kc][2]   - m1), e03 = fexp2(s8[2*kc][3]   - m1);
        float e10 = fexp2(s8[2*kc+1][0] - m0), e11 = fexp2(s8[2*kc+1][1] - m0);
        float e12 = fexp2(s8[2*kc+1][2] - m1), e13 = fexp2(s8[2*kc+1][3] - m1);
        ts0 += e00 + e01 + e10 + e11;
        ts1 += e02 + e03 + e12 + e13;
        pH[kc][0] = pack_h2(e00, e01);
        pH[kc][1] = pack_h2(e02, e03);
        pH[kc][2] = pack_h2(e10, e11);
        pH[kc][3] = pack_h2(e12, e13);
      }
      ts0 += __shfl_xor_sync(0xffffffffu, ts0, 1);
      ts0 += __shfl_xor_sync(0xffffffffu, ts0, 2);
      ts1 += __shfl_xor_sync(0xffffffffu, ts1, 1);
      ts1 += __shfl_xor_sync(0xffffffffu, ts1, 2);
      l0 = l0 * aa0 + ts0;
      l1 = l1 * aa1 + ts1;
      #pragma unroll
      for (int nt = 0; nt < 16; nt++) {
        o[nt][0] *= aa0; o[nt][1] *= aa0;
        o[nt][2] *= aa1; o[nt][3] *= aa1;
      }
      #pragma unroll
      for (int kc = 0; kc < 4; kc++) {
        #pragma unroll
        for (int ntp = 0; ntp < 8; ntp++) {
          const unsigned voff = (unsigned)((kc * 16 + ar) * AT_RS + ntp * 32 + aco);
          unsigned vh[4];
          ldsm4t(vh, kvb + AT_TSZ + voff);
          #pragma unroll
          for (int hf = 0; hf < 2; hf++)
            mma16816(o[ntp * 2 + hf], pH[kc], vh[hf*2], vh[hf*2+1]);
        }
      }
    }
    __syncthreads();
  }

  const float inv0 = 1.f / l0, inv1 = 1.f / l1;
  #pragma unroll
  for (int nt = 0; nt < 16; nt++) {
    const int col = h * HD_ + nt * 8 + ((lane & 3) << 1);
    size_t b0 = (size_t)rlo * H_ + col;
    size_t b1 = (size_t)(rlo + 8) * H_ + col;
    *(unsigned*)(out + b0) = pack_h2(o[nt][0] * inv0, o[nt][1] * inv0);
    *(unsigned*)(out + b1) = pack_h2(o[nt][2] * inv1, o[nt][3] * inv1);
  }
}

// ---------------- gating + routing ----------------
__global__ void __launch_bounds__(256) gate_kernel(const float* __restrict__ gw) {
  const int t = blockIdx.x;
  __shared__ float part[256];
  const int tid = threadIdx.x;
  const int e = tid & 15, c = tid >> 4;
  const fp16* xh = g_h3n + (size_t)t*H_;
  float s = 0.f;
  for (int h = c*128; h < c*128+128; h++)
    s += __half2float(xh[h]) * gw[h*E_ + e];
  part[tid] = s;
  __syncthreads();
  if (tid == 0) {
    float lg[16];
    for (int ee=0; ee<16; ee++){ float v=0.f; for (int cc=0; cc<16; cc++) v += part[cc*16+ee]; lg[ee]=v; }
    int i1 = 0;
    for (int ee=1; ee<16; ee++) if (lg[ee] > lg[i1]) i1 = ee;
    int i2 = (i1==0) ? 1 : 0;
    for (int ee=0; ee<16; ee++) if (ee!=i1 && lg[ee] > lg[i2]) i2 = ee;
    float mx = lg[i1];
    float p1 = expf(lg[i1]-mx), p2 = expf(lg[i2]-mx);
    float d = p1 + p2;
    g_topi[t*2]=i1; g_topi[t*2+1]=i2;
    g_topw[t*2]=p1/d; g_topw[t*2+1]=p2/d;
  }
}

__global__ void moe_zero_kernel(){ if (threadIdx.x < E_){ g_cnt[threadIdx.x]=0; g_cur[threadIdx.x]=0; } }
__global__ void moe_count_kernel(){ int i = blockIdx.x*256+threadIdx.x; if (i < P_) atomicAdd(&g_cnt[g_topi[i]], 1); }
__global__ void moe_scan_kernel(){ if (threadIdx.x==0){ int o=0; for (int e=0;e<E_;e++){ g_off[e]=o; o+=g_cnt[e]; } } }
__global__ void moe_scatter_kernel(){
  int i = blockIdx.x*256+threadIdx.x;
  if (i < P_) {
    int e = g_topi[i];
    int pos = g_off[e] + atomicAdd(&g_cur[e], 1);
    g_ptok[pos] = i >> 1;
    g_pslot[i]  = pos;
  }
}

// ---------------- final combine ----------------
__global__ void final_kernel(float* __restrict__ out) {
  const int t = blockIdx.x;
  const int p0 = g_pslot[t*2], p1 = g_pslot[t*2+1];
  const float w0 = g_topw[t*2], w1 = g_topw[t*2+1];
  const float4* ra = (const float4*)(g_resat + (size_t)t*H_);
  const float4* ml = (const float4*)(g_mlp   + (size_t)t*H_);
  const float4* y0 = (const float4*)(g_ym    + (size_t)p0*H_);
  const float4* y1 = (const float4*)(g_ym    + (size_t)p1*H_);
  float4* op = (float4*)(out + (size_t)t*H_);
  for (int i = threadIdx.x; i < 512; i += 256) {
    float4 A=ra[i], B=ml[i], C=y0[i], D=y1[i];
    op[i] = make_float4(A.x+B.x+w0*C.x+w1*D.x, A.y+B.y+w0*C.y+w1*D.y,
                        A.z+B.z+w0*C.z+w1*D.z, A.w+B.w+w0*C.w+w1*D.w);
  }
}

// ---------------- host ----------------
extern "C" void kernel_launch(void* const* d_in, const int* in_sizes, int n_in,
                              void* d_out, int out_size) {
  (void)in_sizes; (void)n_in; (void)out_size;
  const float* x      = (const float*)d_in[0];
  const float* ln_in  = (const float*)d_in[1];
  const float* ln_post= (const float*)d_in[2];
  const float* ln_res = (const float*)d_in[3];
  const float* wqkv   = (const float*)d_in[4];
  const float* wo     = (const float*)d_in[5];
  const float* w13    = (const float*)d_in[6];
  const float* w2     = (const float*)d_in[7];
  const float* gw     = (const float*)d_in[8];
  const float* ws     = (const float*)d_in[9];
  const float* w2s    = (const float*)d_in[10];
  float* out = (float*)d_out;

  float *resat,*mlp,*ym;
  cudaGetSymbolAddress((void**)&resat,g_resat);
  cudaGetSymbolAddress((void**)&mlp,  g_mlp);
  cudaGetSymbolAddress((void**)&ym,   g_ym);

  fp16 *qkvh,*xn,*attn,*h2n,*hmid,*h3n,*hmm;
  cudaGetSymbolAddress((void**)&qkvh, g_qkvh);
  cudaGetSymbolAddress((void**)&xn,   g_xn);
  cudaGetSymbolAddress((void**)&attn, g_attn);
  cudaGetSymbolAddress((void**)&h2n,  g_h2n);
  cudaGetSymbolAddress((void**)&hmid, g_hmid);
  cudaGetSymbolAddress((void**)&h3n,  g_h3n);
  cudaGetSymbolAddress((void**)&hmm,  g_hmm);

  fp16 *wq,*wo16,*w1316,*w216,*ws16,*w2s16;
  cudaGetSymbolAddress((void**)&wq,    g_wqkvT);
  cudaGetSymbolAddress((void**)&wo16,  g_woT);
  cudaGetSymbolAddress((void**)&w1316, g_w13T);
  cudaGetSymbolAddress((void**)&w216,  g_w2T);
  cudaGetSymbolAddress((void**)&ws16,  g_ws);
  cudaGetSymbolAddress((void**)&w2s16, g_w2s);

  cudaFuncSetAttribute(mma_gemm, cudaFuncAttributeMaxDynamicSharedMemorySize, MMA_SMEM);
  cudaFuncSetAttribute(attn_mma, cudaFuncAttributeMaxDynamicSharedMemorySize, AT_SMEM);

  // fork a side stream (host objects only; created once per host invocation).
  cudaStream_t s1;
  cudaStreamCreateWithFlags(&s1, cudaStreamNonBlocking);
  cudaEvent_t evFork, evWq, evW, evJoin;
  cudaEventCreateWithFlags(&evFork, cudaEventDisableTiming);
  cudaEventCreateWithFlags(&evWq,   cudaEventDisableTiming);
  cudaEventCreateWithFlags(&evW,    cudaEventDisableTiming);
  cudaEventCreateWithFlags(&evJoin, cudaEventDisableTiming);

  cudaEventRecord(evFork, 0);
  cudaStreamWaitEvent(s1, evFork, 0);

  // ---- side stream: wqkv transpose first (main waits on it), then the rest ----
  transpose_h<<<dim3(QKVW_/32, H_/32), 256, 0, s1>>>(wqkv, wq, H_, QKVW_, 0);
  cudaEventRecord(evWq, s1);
  transpose_h<<<dim3(H_/32,   H_/32), 256, 0, s1>>>(wo,  wo16,  H_, H_, 0);
  transpose_h<<<dim3(2*H_/32, H_/32), 256, 0, s1>>>(w13, w1316, H_, 2*H_, 1);
  transpose_h<<<dim3(H_/32,   H_/32), 256, 0, s1>>>(w2,  w216,  H_, H_, 0);
  cudaEventRecord(evW, s1);
  convert_ws_int<<<(E_*2*I_*H_)/2048, 256, 0, s1>>>(ws, ws16);
  convert_h8<<<(E_*H_*I_)/2048, 256, 0, s1>>>(w2s, w2s16);
  rmsnorm_h<<<T_, 256, 0, s1>>>(x, ln_post, h3n);
  gate_kernel<<<T_, 256, 0, s1>>>(gw);
  moe_zero_kernel<<<1, 32, 0, s1>>>();
  moe_count_kernel<<<P_/256, 256, 0, s1>>>();
  moe_scan_kernel<<<1, 32, 0, s1>>>();
  moe_scatter_kernel<<<P_/256, 256, 0, s1>>>();
  mma_gemm<<<dim3(2*I_/128, T_/128, E_), 256, MMA_SMEM, s1>>>(h3n, ws16, nullptr, hmm, nullptr, 2*I_, H_, 1, 1);
  mma_gemm<<<dim3(H_/128, T_/128, E_), 256, MMA_SMEM, s1>>>(hmm, w2s16, ym, nullptr, nullptr, H_, I_, 2, 0);
  cudaEventRecord(evJoin, s1);

  // ---- main stream: attention chain + residual MLP ----
  rmsnorm_h<<<T_, 256>>>(x, ln_in, xn);
  cudaStreamWaitEvent(0, evWq, 0);
  mma_gemm<<<dim3(QKVW_/128, T_/128, 1), 256, MMA_SMEM>>>(xn, wq, nullptr, qkvh, nullptr, QKVW_, H_, 0, 3);
  rope_split_kernel<<<dim3(T_, NH_ + 2*NKV_), 64>>>(qkvh);
  attn_mma<<<dim3(NH_, T_/128), 256, AT_SMEM>>>(attn);
  cudaStreamWaitEvent(0, evW, 0);
  mma_gemm<<<dim3(H_/128, T_/128, 1), 256, MMA_SMEM>>>(attn, wo16, resat, nullptr, x, H_, H_, 0, 2);
  rmsnorm_h<<<T_, 256>>>(resat, ln_res, h2n);
  mma_gemm<<<dim3(2*H_/128, T_/128, 1), 256, MMA_SMEM>>>(h2n, w1316, nullptr, hmid, nullptr, 2*H_, H_, 0, 1);
  mma_gemm<<<dim3(H_/128, T_/128, 1), 256, MMA_SMEM>>>(hmid, w216, mlp, nullptr, nullptr, H_, H_, 0, 0);

  // ---- join + combine ----
  cudaStreamWaitEvent(0, evJoin, 0);
  final_kernel<<<T_, 256>>>(out);
}

// round 14
// speedup vs baseline: 7.7518x; 1.0457x over previous
#include <cuda_runtime.h>
#include <cuda_fp16.h>
#include <math.h>

#define T_ 2048
#define H_ 2048
#define NH_ 16
#define NKV_ 4
#define HD_ 128
#define I_ 1024
#define E_ 16
#define TOPK_ 2
#define P_ (T_*TOPK_)
#define QKVW_ 3072

typedef __half fp16;

// ---------------- scratch (device globals; no allocations allowed) ----------------
__device__ float g_resat[T_*H_];
__device__ float g_mlp[T_*H_];

__device__ fp16 g_qkvh[T_*QKVW_];
__device__ fp16 g_xn[T_*H_];
__device__ fp16 g_attn[T_*H_];
__device__ fp16 g_h2n[T_*H_];
__device__ fp16 g_hmid[T_*H_];
__device__ fp16 g_h3n[T_*H_];
__device__ fp16 g_hmm[P_*I_];
__device__ fp16 g_ymh[P_*H_];

__device__ fp16 g_q[NH_*T_*HD_];
__device__ fp16 g_k[NKV_*T_*HD_];
__device__ fp16 g_v[NKV_*T_*HD_];

__device__ fp16 g_wqkvT[QKVW_*H_];
__device__ fp16 g_woT[H_*H_];
__device__ fp16 g_w13T[2*H_*H_];     // gate/up interleaved rows
__device__ fp16 g_w2T[H_*H_];
__device__ fp16 g_ws[E_*2*I_*H_];    // gate/up interleaved rows per expert
__device__ fp16 g_w2s[E_*H_*I_];

__device__ int   g_topi[P_];
__device__ float g_topw[P_];
__device__ float g_wslot[P_];
__device__ int   g_cnt[E_];
__device__ int   g_off[E_];
__device__ int   g_cur[E_];
__device__ int   g_ptok[P_];
__device__ int   g_pslot[P_];

// ---------------- ptx helpers (base compute_103-safe) ----------------
__device__ __forceinline__ unsigned smem_u32(const void* p) {
  unsigned a;
  asm("{ .reg .u64 t; cvta.to.shared.u64 t, %1; cvt.u32.u64 %0, t; }" : "=r"(a) : "l"(p));
  return a;
}
__device__ __forceinline__ void cp16(unsigned dst, const void* src, bool valid) {
  int sz = valid ? 16 : 0;
  asm volatile("cp.async.cg.shared.global [%0], [%1], 16, %2;"
               :: "r"(dst), "l"(src), "r"(sz) : "memory");
}
#define CP_COMMIT() asm volatile("cp.async.commit_group;" ::: "memory")
#define CP_WAIT(n)  asm volatile("cp.async.wait_group %0;" :: "n"(n) : "memory")

__device__ __forceinline__ void ldsm4(unsigned* r, unsigned addr) {
  asm volatile("ldmatrix.sync.aligned.m8n8.x4.shared.b16 {%0,%1,%2,%3}, [%4];"
               : "=r"(r[0]), "=r"(r[1]), "=r"(r[2]), "=r"(r[3]) : "r"(addr));
}
__device__ __forceinline__ void ldsm4t(unsigned* r, unsigned addr) {
  asm volatile("ldmatrix.sync.aligned.m8n8.x4.trans.shared.b16 {%0,%1,%2,%3}, [%4];"
               : "=r"(r[0]), "=r"(r[1]), "=r"(r[2]), "=r"(r[3]) : "r"(addr));
}
__device__ __forceinline__ void mma16816(float* d, const unsigned* a, unsigned b0, unsigned b1) {
  asm volatile("mma.sync.aligned.m16n8k16.row.col.f32.f16.f16.f32 "
               "{%0,%1,%2,%3}, {%4,%5,%6,%7}, {%8,%9}, {%0,%1,%2,%3};"
               : "+f"(d[0]), "+f"(d[1]), "+f"(d[2]), "+f"(d[3])
               : "r"(a[0]), "r"(a[1]), "r"(a[2]), "r"(a[3]), "r"(b0), "r"(b1));
}

// fast 2^y on the FMA pipe (y in [-1e30, 0]); rel err < 3e-6
__device__ __forceinline__ float fexp2(float y) {
  y = fmaxf(y, -120.f);
  float z = y + 12582912.0f;
  int   n = __float_as_int(z) - 0x4B400000;
  float f = y - (z - 12582912.0f);
  float p = 0.0013333558f;
  p = fmaf(p, f, 0.0096181291f);
  p = fmaf(p, f, 0.0555041087f);
  p = fmaf(p, f, 0.2402265069f);
  p = fmaf(p, f, 0.6931471806f);
  p = fmaf(p, f, 1.0f);
  return p * __int_as_float((n + 127) << 23);
}

__device__ __forceinline__ unsigned pack_h2(float a, float b) {
  __half2 t = __floats2half2_rn(a, b);
  return *(unsigned*)&t;
}
__device__ __forceinline__ void store_h4(float4 v, fp16* p) {
  fp16 h[4] = {__float2half_rn(v.x), __float2half_rn(v.y), __float2half_rn(v.z), __float2half_rn(v.w)};
  *(uint2*)p = *(uint2*)h;
}
__device__ __forceinline__ float siluf(float g){ return g / (1.f + __expf(-g)); }

// ---------------- weight prep ----------------
__global__ void __launch_bounds__(256) convert_ws_int(const float* __restrict__ in, fp16* __restrict__ o) {
  size_t idx = (size_t)blockIdx.x * 256 + threadIdx.x;
  size_t r = idx >> 8;
  int h0 = (int)(idx & 255) << 3;
  int e = (int)(r >> 11);
  int k = (int)(r & 2047);
  int srcr = e * 2 * I_ + ((k & 1) ? I_ + (k >> 1) : (k >> 1));
  const float4* s = (const float4*)(in + (size_t)srcr * H_ + h0);
  float4 a = s[0], b = s[1];
  fp16 hb[8] = {__float2half_rn(a.x), __float2half_rn(a.y), __float2half_rn(a.z), __float2half_rn(a.w),
                __float2half_rn(b.x), __float2half_rn(b.y), __float2half_rn(b.z), __float2half_rn(b.w)};
  *(uint4*)(o + r * H_ + h0) = *(uint4*)hb;
}

__global__ void __launch_bounds__(256) convert_h8(const float* __restrict__ in, fp16* __restrict__ o) {
  size_t i = ((size_t)blockIdx.x * 256 + threadIdx.x) << 3;
  const float4* s = (const float4*)(in + i);
  float4 a = s[0], b = s[1];
  fp16 hb[8] = {__float2half_rn(a.x), __float2half_rn(a.y), __float2half_rn(a.z), __float2half_rn(a.w),
                __float2half_rn(b.x), __float2half_rn(b.y), __float2half_rn(b.z), __float2half_rn(b.w)};
  *(uint4*)(o + i) = *(uint4*)hb;
}

// transpose: in[K][N] fp32 -> o [N][K] fp16; il=1 interleaves gate/up dest rows.
__global__ void __launch_bounds__(256) transpose_h(const float* __restrict__ in, fp16* __restrict__ o,
                                                   int K, int N, int il) {
  __shared__ float t[32][33];
  int k0 = blockIdx.y * 32, n0 = blockIdx.x * 32;
  int tx = threadIdx.x & 31, ty = threadIdx.x >> 5;
  #pragma unroll
  for (int j = 0; j < 4; j++)
    t[ty + 8 * j][tx] = in[(size_t)(k0 + ty + 8 * j) * N + n0 + tx];
  __syncthreads();
  int half = N >> 1;
  #pragma unroll
  for (int j = 0; j < 4; j++) {
    int n = n0 + ty + 8 * j;
    int dr = il ? ((n < half) ? 2 * n : 2 * (n - half) + 1) : n;
    o[(size_t)dr * K + k0 + tx] = __float2half_rn(t[tx][ty + 8 * j]);
  }
}

// ---------------- RMSNorm: one block per token, emits fp16 ----------------
__global__ void __launch_bounds__(256) rmsnorm_h(const float* __restrict__ x,
                                                 const float* __restrict__ w,
                                                 fp16* __restrict__ o) {
  const int t = blockIdx.x;
  const float4* xr = (const float4*)(x + (size_t)t * H_);
  const float4* wr = (const float4*)w;
  const int i0 = threadIdx.x, i1 = threadIdx.x + 256;
  float4 v0 = xr[i0], v1 = xr[i1];
  float s = v0.x*v0.x+v0.y*v0.y+v0.z*v0.z+v0.w*v0.w
          + v1.x*v1.x+v1.y*v1.y+v1.z*v1.z+v1.w*v1.w;
  #pragma unroll
  for (int off = 16; off; off >>= 1) s += __shfl_xor_sync(0xffffffffu, s, off);
  __shared__ float red[8];
  __shared__ float sinv;
  if ((threadIdx.x & 31) == 0) red[threadIdx.x >> 5] = s;
  __syncthreads();
  if (threadIdx.x == 0) {
    float tt = 0.f;
    #pragma unroll
    for (int k = 0; k < 8; k++) tt += red[k];
    sinv = rsqrtf(tt * (1.f / H_) + 1e-5f);
  }
  __syncthreads();
  float r = sinv;
  float4 w0 = wr[i0], w1 = wr[i1];
  float4 o0, o1;
  o0.x=v0.x*r*w0.x; o0.y=v0.y*r*w0.y; o0.z=v0.z*r*w0.z; o0.w=v0.w*r*w0.w;
  o1.x=v1.x*r*w1.x; o1.y=v1.y*r*w1.y; o1.z=v1.z*r*w1.z; o1.w=v1.w*r*w1.w;
  size_t base = (size_t)t * H_;
  store_h4(o0, o + base + i0 * 4);
  store_h4(o1, o + base + i1 * 4);
}

// ---------------- mma.sync fp16 GEMM with fused epilogues ----------------
// CTA tile 128x128, 8 warps (2m x 4n), warp tile 64x32, K-chunk 64, 2-stage cp.async.
// 2 CTAs/SM (stage 36864B x2 + rowmap).
// mode 0: fp32 to C. mode 1: gate/up interleaved -> silu(g)*u fp16 to Ch (Nout=N/2).
// mode 2: C = Xres + acc (fp32, dense). mode 3: fp16 to Ch.
// mode 4: fp16 to Ch scaled by g_wslot[row] (grouped=2 MoE down-proj).
#define MMA_STG 36864
#define MMA_SMEM (2*MMA_STG + 512)
__global__ void __launch_bounds__(256, 2) mma_gemm(const fp16* __restrict__ A,
                                                   const fp16* __restrict__ B,
                                                   float* __restrict__ C,
                                                   fp16* __restrict__ Ch,
                                                   const float* __restrict__ Xres,
                                                   int N, int K, int grouped, int mode) {
  extern __shared__ char smem[];
  const int tid = threadIdx.x, wid = tid >> 5, lane = tid & 31;
  const int e = blockIdx.z;
  int count = 0, sbase = 0;
  if (grouped) {
    count = g_cnt[e];
    if ((int)(blockIdx.y << 7) >= count) return;
    sbase = g_off[e];
  }
  const fp16* BE = B + (size_t)e * N * K;
  const int m0 = blockIdx.y << 7, n0 = blockIdx.x << 7;
  unsigned sb = smem_u32(smem);
  int* rowmap = (int*)(smem + 2*MMA_STG);

  if (tid < 128) {
    int gr = m0 + tid;
    if (grouped) {
      if (m0 + tid < count) {
        int slot = sbase + m0 + tid;
        gr = (grouped == 1) ? g_ptok[slot] : slot;
      } else gr = -1;
    }
    rowmap[tid] = gr;
  }
  __syncthreads();

  const int nk = K >> 6;
  auto load_chunk = [&](int c, int st) {
    unsigned base = sb + (unsigned)st * MMA_STG;
    #pragma unroll
    for (int i = 0; i < 8; i++) {              // A+B: 2048 cp16
      int s = tid + (i << 8);
      int mat = s >> 10, r = (s >> 3) & 127, cq = s & 7;
      unsigned dst = base + (unsigned)mat * 18432u + (unsigned)(r * 144 + cq * 16);
      const fp16* src;
      bool valid = true;
      if (mat == 0) {
        int gr = rowmap[r];
        valid = (gr >= 0);
        if (!valid) gr = 0;
        src = A + (size_t)gr * K + (c << 6) + (cq << 3);
      } else {
        src = BE + (size_t)(n0 + r) * K + (c << 6) + (cq << 3);
      }
      cp16(dst, src, valid);
    }
    CP_COMMIT();
  };

  float acc[4][4][4];
  #pragma unroll
  for (int i = 0; i < 4; i++)
    #pragma unroll
    for (int j = 0; j < 4; j++)
      #pragma unroll
      for (int k = 0; k < 4; k++) acc[i][j][k] = 0.f;

  const int wm = (wid >> 2) << 6;           // 0 or 64
  const int wn = (wid & 3) << 5;            // 0,32,64,96
  const int ar  = lane & 15;
  const unsigned aco = (lane & 16) ? 16u : 0u;
  const int bn  = (lane & 7) + ((lane & 16) ? 8 : 0);
  const unsigned bko = (lane & 8) ? 16u : 0u;

  load_chunk(0, 0);
  for (int c = 0; c < nk; c++) {
    const int st = c & 1;
    if (c + 1 < nk) { load_chunk(c + 1, st ^ 1); CP_WAIT(1); }
    else CP_WAIT(0);
    __syncthreads();
    const unsigned stb = sb + (unsigned)st * MMA_STG;
    #pragma unroll
    for (int ks = 0; ks < 4; ks++) {
      const unsigned kb = (unsigned)(ks << 5);
      unsigned ahf[4][4];
      #pragma unroll
      for (int mi = 0; mi < 4; mi++) {
        unsigned rowA = (unsigned)((wm + mi * 16 + ar) * 144);
        ldsm4(ahf[mi], stb + rowA + kb + aco);
      }
      #pragma unroll
      for (int nb = 0; nb < 2; nb++) {
        unsigned rowB = (unsigned)((wn + nb * 16 + bn) * 144);
        unsigned bhf[4];
        ldsm4(bhf, stb + 18432u + rowB + kb + bko);
        #pragma unroll
        for (int mi = 0; mi < 4; mi++) {
          #pragma unroll
          for (int half = 0; half < 2; half++) {
            mma16816(acc[mi][nb * 2 + half], ahf[mi], bhf[half * 2], bhf[half * 2 + 1]);
          }
        }
      }
    }
    __syncthreads();
  }

  #pragma unroll
  for (int mi = 0; mi < 4; mi++) {
    const int lr0 = wm + mi * 16 + (lane >> 2);
    const int gr0 = m0 + lr0;
    const bool st0 = !grouped || (gr0 < count);
    const bool st1 = !grouped || (gr0 + 8 < count);
    const size_t row0 = (size_t)((grouped ? sbase : 0) + gr0);
    if (mode == 1) {
      const int Nout = N >> 1;
      #pragma unroll
      for (int nt = 0; nt < 4; nt++) {
        const int col = n0 + wn + nt * 8 + ((lane & 3) << 1);
        const int j = col >> 1;
        float* d = acc[mi][nt];
        if (st0) Ch[row0 * Nout + j]       = __float2half_rn(siluf(d[0]) * d[1]);
        if (st1) Ch[(row0 + 8) * Nout + j] = __float2half_rn(siluf(d[2]) * d[3]);
      }
    } else if (mode == 2) {
      #pragma unroll
      for (int nt = 0; nt < 4; nt++) {
        const int col = n0 + wn + nt * 8 + ((lane & 3) << 1);
        float* d = acc[mi][nt];
        float2 r0 = *(const float2*)(Xres + row0 * N + col);
        float2 r1 = *(const float2*)(Xres + (row0 + 8) * N + col);
        *(float2*)(C + row0 * N + col)       = make_float2(r0.x + d[0], r0.y + d[1]);
        *(float2*)(C + (row0 + 8) * N + col) = make_float2(r1.x + d[2], r1.y + d[3]);
      }
    } else if (mode == 3) {
      #pragma unroll
      for (int nt = 0; nt < 4; nt++) {
        const int col = n0 + wn + nt * 8 + ((lane & 3) << 1);
        float* d = acc[mi][nt];
        if (st0) *(unsigned*)(Ch + row0 * N + col)       = pack_h2(d[0], d[1]);
        if (st1) *(unsigned*)(Ch + (row0 + 8) * N + col) = pack_h2(d[2], d[3]);
      }
    } else if (mode == 4) {
      const float w0s = st0 ? g_wslot[row0]     : 0.f;
      const float w1s = st1 ? g_wslot[row0 + 8] : 0.f;
      #pragma unroll
      for (int nt = 0; nt < 4; nt++) {
        const int col = n0 + wn + nt * 8 + ((lane & 3) << 1);
        float* d = acc[mi][nt];
        if (st0) *(unsigned*)(Ch + row0 * N + col)       = pack_h2(d[0] * w0s, d[1] * w0s);
        if (st1) *(unsigned*)(Ch + (row0 + 8) * N + col) = pack_h2(d[2] * w1s, d[3] * w1s);
      }
    } else {
      #pragma unroll
      for (int nt = 0; nt < 4; nt++) {
        const int col = n0 + wn + nt * 8 + ((lane & 3) << 1);
        float* d = acc[mi][nt];
        if (st0) *(float2*)(C + row0 * N + col)       = make_float2(d[0], d[1]);
        if (st1) *(float2*)(C + (row0 + 8) * N + col) = make_float2(d[2], d[3]);
      }
    }
  }
}

// ---------------- RoPE + pack into per-head fp16 layouts (fp16 input) ----------------
__global__ void rope_split_kernel(const fp16* __restrict__ qkv) {
  const int t = blockIdx.x, hh = blockIdx.y, i = threadIdx.x;
  if (hh < NH_ + NKV_) {
    const fp16* b;
    fp16* d;
    if (hh < NH_) {
      b = qkv + (size_t)t*QKVW_ + hh*HD_;
      d = g_q + ((size_t)hh*T_ + t) * HD_;
    } else {
      int k = hh - NH_;
      b = qkv + (size_t)t*QKVW_ + NH_*HD_ + k*HD_;
      d = g_k + ((size_t)k*T_ + t) * HD_;
    }
    float fr = powf(10000.f, -(float)(2*i) * (1.f/HD_));
    float ang = (float)t * fr;
    float sn, cs; sincosf(ang, &sn, &cs);
    float x1 = __half2float(b[i]), x2 = __half2float(b[i+64]);
    d[i]      = __float2half_rn(x1*cs - x2*sn);
    d[i + 64] = __float2half_rn(x2*cs + x1*sn);
  } else {
    int v = hh - NH_ - NKV_;
    const fp16* b = qkv + (size_t)t*QKVW_ + (NH_+NKV_)*HD_ + v*HD_;
    size_t o = ((size_t)v*T_ + t) * HD_;
    g_v[o + i]      = b[i];
    g_v[o + i + 64] = b[i+64];
  }
}

// ---------------- mma.sync flash attention (single fp16) ----------------
#define AT_RS  272
#define AT_QSZ (128*AT_RS)
#define AT_TSZ (64*AT_RS)
#define AT_SMEM (AT_QSZ + 2*2*AT_TSZ)   // 104448
__global__ void __launch_bounds__(256) attn_mma(fp16* __restrict__ out) {
  extern __shared__ char smc[];
  const int h = blockIdx.x;
  const int q0 = ((int)gridDim.y - 1 - (int)blockIdx.y) << 7;   // heavy tiles first
  const int kvh = h >> 2;
  const int tid = threadIdx.x, wid = tid >> 5, lane = tid & 31;
  const unsigned sb = smem_u32(smc);
  const unsigned KV_o = AT_QSZ;

  #pragma unroll
  for (int i = 0; i < 8; i++) {
    int s = tid + (i << 8);
    int r = (s >> 4) & 127, cq = s & 15;
    unsigned dst = sb + (unsigned)(r * AT_RS + cq * 16);
    const fp16* src = g_q + (((size_t)h*T_ + q0 + r) << 7) + cq*8;
    cp16(dst, src, true);
  }
  CP_COMMIT();

  auto load_kv = [&](int c, int st) {
    unsigned base = sb + KV_o + (unsigned)st * (2*AT_TSZ);
    #pragma unroll
    for (int i = 0; i < 8; i++) {
      int s = tid + (i << 8);
      int mat = s >> 10, r = (s >> 4) & 63, cq = s & 15;
      unsigned dst = base + (unsigned)mat * AT_TSZ + (unsigned)(r * AT_RS + cq * 16);
      const fp16* ap = (mat == 0) ? g_k : g_v;
      cp16(dst, ap + (((size_t)kvh*T_ + c*64 + r) << 7) + cq*8, true);
    }
    CP_COMMIT();
  };

  const int wr0 = wid << 4;
  const int rlo = q0 + wr0 + (lane >> 2);
  float m0 = -1e30f, m1 = -1e30f, l0 = 0.f, l1 = 0.f;
  float o[16][4];
  #pragma unroll
  for (int i = 0; i < 16; i++)
    #pragma unroll
    for (int j = 0; j < 4; j++) o[i][j] = 0.f;

  const int ntl = (q0 >> 6) + 2;
  load_kv(0, 0);

  const int ar  = lane & 15;
  const int aco = (lane >> 4) << 4;
  const int bnr = (lane & 7) + ((lane & 16) ? 8 : 0);
  const int bko = (lane & 8) ? 16 : 0;
  const float sc = 0.12751744f;                    // (1/sqrt(128)) * log2(e)

  for (int c = 0; c < ntl; c++) {
    const int st = c & 1;
    if (c + 1 < ntl) { load_kv(c + 1, st ^ 1); CP_WAIT(1); }
    else CP_WAIT(0);
    __syncthreads();
    const int s0 = c << 6;
    const bool active = (s0 <= q0 + wr0 + 15);
    if (active) {
      const unsigned kvb = sb + KV_o + (unsigned)st * (2*AT_TSZ);
      float s8[8][4];
      #pragma unroll
      for (int i = 0; i < 8; i++)
        #pragma unroll
        for (int j = 0; j < 4; j++) s8[i][j] = 0.f;
      #pragma unroll
      for (int kk = 0; kk < 8; kk++) {
        const unsigned qoff = (unsigned)((wr0 + ar) * AT_RS + kk * 32 + aco);
        unsigned ah[4];
        ldsm4(ah, sb + qoff);
        #pragma unroll
        for (int ntp = 0; ntp < 4; ntp++) {
          const unsigned koff = (unsigned)((bnr + ntp * 16) * AT_RS + kk * 32 + bko);
          unsigned bh[4];
          ldsm4(bh, kvb + koff);
          #pragma unroll
          for (int hf = 0; hf < 2; hf++)
            mma16816(s8[ntp * 2 + hf], ah, bh[hf*2], bh[hf*2+1]);
        }
      }
      #pragma unroll
      for (int nt = 0; nt < 8; nt++)
        #pragma unroll
        for (int j = 0; j < 4; j++) s8[nt][j] *= sc;
      if (s0 + 63 > q0 + wr0) {
        const int cb = s0 + ((lane & 3) << 1);
        #pragma unroll
        for (int nt = 0; nt < 8; nt++) {
          #pragma unroll
          for (int j = 0; j < 2; j++) {
            int col = cb + nt * 8 + j;
            if (col > rlo)     s8[nt][j]     = -1e30f;
            if (col > rlo + 8) s8[nt][j + 2] = -1e30f;
          }
        }
      }
      float tm0 = -1e30f, tm1 = -1e30f;
      #pragma unroll
      for (int nt = 0; nt < 8; nt++) {
        tm0 = fmaxf(tm0, fmaxf(s8[nt][0], s8[nt][1]));
        tm1 = fmaxf(tm1, fmaxf(s8[nt][2], s8[nt][3]));
      }
      tm0 = fmaxf(tm0, __shfl_xor_sync(0xffffffffu, tm0, 1));
      tm0 = fmaxf(tm0, __shfl_xor_sync(0xffffffffu, tm0, 2));
      tm1 = fmaxf(tm1, __shfl_xor_sync(0xffffffffu, tm1, 1));
      tm1 = fmaxf(tm1, __shfl_xor_sync(0xffffffffu, tm1, 2));
      const float mn0 = fmaxf(m0, tm0), mn1 = fmaxf(m1, tm1);
      const float aa0 = fexp2(m0 - mn0), aa1 = fexp2(m1 - mn1);
      m0 = mn0; m1 = mn1;
      float ts0 = 0.f, ts1 = 0.f;
      unsigned pH[4][4];
      #pragma unroll
      for (int kc = 0; kc < 4; kc++) {
        float e00 = fexp2(s8[2*kc][0]   - m0), e01 = fexp2(s8[2*kc][1]   - m0);
        float e02 = fexp2(s8[2*kc][2]   - m1), e03 = fexp2(s8[2*kc][3]   - m1);
        float e10 = fexp2(s8[2*kc+1][0] - m0), e11 = fexp2(s8[2*kc+1][1] - m0);
        float e12 = fexp2(s8[2*kc+1][2] - m1), e13 = fexp2(s8[2*kc+1][3] - m1);
        ts0 += e00 + e01 + e10 + e11;
        ts1 += e02 + e03 + e12 + e13;
        pH[kc][0] = pack_h2(e00, e01);
        pH[kc][1] = pack_h2(e02, e03);
        pH[kc][2] = pack_h2(e10, e11);
        pH[kc][3] = pack_h2(e12, e13);
      }
      ts0 += __shfl_xor_sync(0xffffffffu, ts0, 1);
      ts0 += __shfl_xor_sync(0xffffffffu, ts0, 2);
      ts1 += __shfl_xor_sync(0xffffffffu, ts1, 1);
      ts1 += __shfl_xor_sync(0xffffffffu, ts1, 2);
      l0 = l0 * aa0 + ts0;
      l1 = l1 * aa1 + ts1;
      #pragma unroll
      for (int nt = 0; nt < 16; nt++) {
        o[nt][0] *= aa0; o[nt][1] *= aa0;
        o[nt][2] *= aa1; o[nt][3] *= aa1;
      }
      #pragma unroll
      for (int kc = 0; kc < 4; kc++) {
        #pragma unroll
        for (int ntp = 0; ntp < 8; ntp++) {
          const unsigned voff = (unsigned)((kc * 16 + ar) * AT_RS + ntp * 32 + aco);
          unsigned vh[4];
          ldsm4t(vh, kvb + AT_TSZ + voff);
          #pragma unroll
          for (int hf = 0; hf < 2; hf++)
            mma16816(o[ntp * 2 + hf], pH[kc], vh[hf*2], vh[hf*2+1]);
        }
      }
    }
    __syncthreads();
  }

  const float inv0 = 1.f / l0, inv1 = 1.f / l1;
  #pragma unroll
  for (int nt = 0; nt < 16; nt++) {
    const int col = h * HD_ + nt * 8 + ((lane & 3) << 1);
    size_t b0 = (size_t)rlo * H_ + col;
    size_t b1 = (size_t)(rlo + 8) * H_ + col;
    *(unsigned*)(out + b0) = pack_h2(o[nt][0] * inv0, o[nt][1] * inv0);
    *(unsigned*)(out + b1) = pack_h2(o[nt][2] * inv1, o[nt][3] * inv1);
  }
}

// ---------------- gating + routing ----------------
__global__ void __launch_bounds__(256) gate_kernel(const float* __restrict__ gw) {
  const int t = blockIdx.x;
  __shared__ float part[256];
  const int tid = threadIdx.x;
  const int e = tid & 15, c = tid >> 4;
  const fp16* xh = g_h3n + (size_t)t*H_;
  float s = 0.f;
  for (int h = c*128; h < c*128+128; h++)
    s += __half2float(xh[h]) * gw[h*E_ + e];
  part[tid] = s;
  __syncthreads();
  if (tid == 0) {
    float lg[16];
    for (int ee=0; ee<16; ee++){ float v=0.f; for (int cc=0; cc<16; cc++) v += part[cc*16+ee]; lg[ee]=v; }
    int i1 = 0;
    for (int ee=1; ee<16; ee++) if (lg[ee] > lg[i1]) i1 = ee;
    int i2 = (i1==0) ? 1 : 0;
    for (int ee=0; ee<16; ee++) if (ee!=i1 && lg[ee] > lg[i2]) i2 = ee;
    float mx = lg[i1];
    float p1 = expf(lg[i1]-mx), p2 = expf(lg[i2]-mx);
    float d = p1 + p2;
    g_topi[t*2]=i1; g_topi[t*2+1]=i2;
    g_topw[t*2]=p1/d; g_topw[t*2+1]=p2/d;
  }
}

__global__ void moe_zero_kernel(){ if (threadIdx.x < E_){ g_cnt[threadIdx.x]=0; g_cur[threadIdx.x]=0; } }
__global__ void moe_count_kernel(){ int i = blockIdx.x*256+threadIdx.x; if (i < P_) atomicAdd(&g_cnt[g_topi[i]], 1); }
__global__ void moe_scan_kernel(){ if (threadIdx.x==0){ int o=0; for (int e=0;e<E_;e++){ g_off[e]=o; o+=g_cnt[e]; } } }
__global__ void moe_scatter_kernel(){
  int i = blockIdx.x*256+threadIdx.x;
  if (i < P_) {
    int e = g_topi[i];
    int pos = g_off[e] + atomicAdd(&g_cur[e], 1);
    g_ptok[pos] = i >> 1;
    g_pslot[i]  = pos;
    g_wslot[pos] = g_topw[i];
  }
}

// ---------------- final combine: out = resat + mlp + ymh[p0] + ymh[p1] ----------------
__global__ void final_kernel(float* __restrict__ out) {
  const int t = blockIdx.x;
  const int p0 = g_pslot[t*2], p1 = g_pslot[t*2+1];
  const float4* ra = (const float4*)(g_resat + (size_t)t*H_);
  const float4* ml = (const float4*)(g_mlp   + (size_t)t*H_);
  const __half2* y0 = (const __half2*)(g_ymh + (size_t)p0*H_);
  const __half2* y1 = (const __half2*)(g_ymh + (size_t)p1*H_);
  float4* op = (float4*)(out + (size_t)t*H_);
  for (int i = threadIdx.x; i < 512; i += 256) {
    float4 A = ra[i], B = ml[i];
    float2 c0 = __half22float2(y0[2*i]),   c1 = __half22float2(y0[2*i+1]);
    float2 d0 = __half22float2(y1[2*i]),   d1 = __half22float2(y1[2*i+1]);
    op[i] = make_float4(A.x+B.x+c0.x+d0.x, A.y+B.y+c0.y+d0.y,
                        A.z+B.z+c1.x+d1.x, A.w+B.w+c1.y+d1.y);
  }
}

// ---------------- host ----------------
extern "C" void kernel_launch(void* const* d_in, const int* in_sizes, int n_in,
                              void* d_out, int out_size) {
  (void)in_sizes; (void)n_in; (void)out_size;
  const float* x      = (const float*)d_in[0];
  const float* ln_in  = (const float*)d_in[1];
  const float* ln_post= (const float*)d_in[2];
  const float* ln_res = (const float*)d_in[3];
  const float* wqkv   = (const float*)d_in[4];
  const float* wo     = (const float*)d_in[5];
  const float* w13    = (const float*)d_in[6];
  const float* w2     = (const float*)d_in[7];
  const float* gw     = (const float*)d_in[8];
  const float* ws     = (const float*)d_in[9];
  const float* w2s    = (const float*)d_in[10];
  float* out = (float*)d_out;

  float *resat,*mlp;
  cudaGetSymbolAddress((void**)&resat,g_resat);
  cudaGetSymbolAddress((void**)&mlp,  g_mlp);

  fp16 *qkvh,*xn,*attn,*h2n,*hmid,*h3n,*hmm,*ymh;
  cudaGetSymbolAddress((void**)&qkvh, g_qkvh);
  cudaGetSymbolAddress((void**)&xn,   g_xn);
  cudaGetSymbolAddress((void**)&attn, g_attn);
  cudaGetSymbolAddress((void**)&h2n,  g_h2n);
  cudaGetSymbolAddress((void**)&hmid, g_hmid);
  cudaGetSymbolAddress((void**)&h3n,  g_h3n);
  cudaGetSymbolAddress((void**)&hmm,  g_hmm);
  cudaGetSymbolAddress((void**)&ymh,  g_ymh);

  fp16 *wq,*wo16,*w1316,*w216,*ws16,*w2s16;
  cudaGetSymbolAddress((void**)&wq,    g_wqkvT);
  cudaGetSymbolAddress((void**)&wo16,  g_woT);
  cudaGetSymbolAddress((void**)&w1316, g_w13T);
  cudaGetSymbolAddress((void**)&w216,  g_w2T);
  cudaGetSymbolAddress((void**)&ws16,  g_ws);
  cudaGetSymbolAddress((void**)&w2s16, g_w2s);

  cudaFuncSetAttribute(mma_gemm, cudaFuncAttributeMaxDynamicSharedMemorySize, MMA_SMEM);
  cudaFuncSetAttribute(attn_mma, cudaFuncAttributeMaxDynamicSharedMemorySize, AT_SMEM);

  // fork a side stream (host objects only; created once per host invocation).
  cudaStream_t s1;
  cudaStreamCreateWithFlags(&s1, cudaStreamNonBlocking);
  cudaEvent_t evFork, evWq, evW, evJoin;
  cudaEventCreateWithFlags(&evFork, cudaEventDisableTiming);
  cudaEventCreateWithFlags(&evWq,   cudaEventDisableTiming);
  cudaEventCreateWithFlags(&evW,    cudaEventDisableTiming);
  cudaEventCreateWithFlags(&evJoin, cudaEventDisableTiming);

  cudaEventRecord(evFork, 0);
  cudaStreamWaitEvent(s1, evFork, 0);

  // ---- side stream: wqkv transpose first (main waits on it), then the rest ----
  transpose_h<<<dim3(QKVW_/32, H_/32), 256, 0, s1>>>(wqkv, wq, H_, QKVW_, 0);
  cudaEventRecord(evWq, s1);
  transpose_h<<<dim3(H_/32,   H_/32), 256, 0, s1>>>(wo,  wo16,  H_, H_, 0);
  transpose_h<<<dim3(2*H_/32, H_/32), 256, 0, s1>>>(w13, w1316, H_, 2*H_, 1);
  transpose_h<<<dim3(H_/32,   H_/32), 256, 0, s1>>>(w2,  w216,  H_, H_, 0);
  cudaEventRecord(evW, s1);
  convert_ws_int<<<(E_*2*I_*H_)/2048, 256, 0, s1>>>(ws, ws16);
  convert_h8<<<(E_*H_*I_)/2048, 256, 0, s1>>>(w2s, w2s16);
  rmsnorm_h<<<T_, 256, 0, s1>>>(x, ln_post, h3n);
  gate_kernel<<<T_, 256, 0, s1>>>(gw);
  moe_zero_kernel<<<1, 32, 0, s1>>>();
  moe_count_kernel<<<P_/256, 256, 0, s1>>>();
  moe_scan_kernel<<<1, 32, 0, s1>>>();
  moe_scatter_kernel<<<P_/256, 256, 0, s1>>>();
  mma_gemm<<<dim3(2*I_/128, T_/128, E_), 256, MMA_SMEM, s1>>>(h3n, ws16, nullptr, hmm, nullptr, 2*I_, H_, 1, 1);
  mma_gemm<<<dim3(H_/128, T_/128, E_), 256, MMA_SMEM, s1>>>(hmm, w2s16, nullptr, ymh, nullptr, H_, I_, 2, 4);
  cudaEventRecord(evJoin, s1);

  // ---- main stream: attention chain + residual MLP ----
  rmsnorm_h<<<T_, 256>>>(x, ln_in, xn);
  cudaStreamWaitEvent(0, evWq, 0);
  mma_gemm<<<dim3(QKVW_/128, T_/128, 1), 256, MMA_SMEM>>>(xn, wq, nullptr, qkvh, nullptr, QKVW_, H_, 0, 3);
  rope_split_kernel<<<dim3(T_, NH_ + 2*NKV_), 64>>>(qkvh);
  attn_mma<<<dim3(NH_, T_/128), 256, AT_SMEM>>>(attn);
  cudaStreamWaitEvent(0, evW, 0);
  mma_gemm<<<dim3(H_/128, T_/128, 1), 256, MMA_SMEM>>>(attn, wo16, resat, nullptr, x, H_, H_, 0, 2);
  rmsnorm_h<<<T_, 256>>>(resat, ln_res, h2n);
  mma_gemm<<<dim3(2*H_/128, T_/128, 1), 256, MMA_SMEM>>>(h2n, w1316, nullptr, hmid, nullptr, 2*H_, H_, 0, 1);
  mma_gemm<<<dim3(H_/128, T_/128, 1), 256, MMA_SMEM>>>(hmid, w216, mlp, nullptr, nullptr, H_, H_, 0, 0);

  // ---- join + combine ----
  cudaStreamWaitEvent(0, evJoin, 0);
  final_kernel<<<T_, 256>>>(out);
}